// round 1
// baseline (speedup 1.0000x reference)
#include <cuda_runtime.h>
#include <math.h>

#define Bb 4
#define Ll 2048
#define DM 512
#define Hh 8
#define DK 64
#define DFF 2048
#define Uu 40
#define BH (Bb*Hh)
#define ROWS (Bb*Ll)

// ---------------- scratch (static device globals; allocation-free) ----------
__device__ float g_Q[ROWS*DM];
__device__ float g_K[ROWS*DM];
__device__ float g_V[ROWS*DM];
__device__ float g_M[BH*Ll];
__device__ int   g_top[BH*Uu];
__device__ float g_S[BH*Uu*Ll];     // scores / attn (in-place softmax)
__device__ float g_upd[BH*Uu*DK];
__device__ float g_vm[BH*DK];
__device__ float g_ctx[ROWS*DM];
__device__ float g_ao[ROWS*DM];
__device__ float g_x1[ROWS*DM];
__device__ float g_ff[ROWS*DFF];
__device__ float g_y2[ROWS*DM];

// ---------------- generic fp32 GEMM: C[M,N] = A[M,K] @ B ----------------
// TRANSB=0: B is [K,N] row-major.  TRANSB=1: B is [N,K] row-major (use B^T).
// Requires M%64==0, N%64==0, K%16==0 (true for all calls here).
template<int TRANSB>
__global__ void sgemm_kernel(const float* __restrict__ A,
                             const float* __restrict__ Bm,
                             float* __restrict__ C,
                             int M, int N, int K) {
    __shared__ float As[16][64];
    __shared__ float Bs[16][64];

    const int tx = threadIdx.x;      // 0..15
    const int ty = threadIdx.y;      // 0..15
    const int tid = ty * 16 + tx;
    const int m0 = blockIdx.y * 64;
    const int n0 = blockIdx.x * 64;

    float acc[4][4];
#pragma unroll
    for (int i = 0; i < 4; i++)
#pragma unroll
        for (int j = 0; j < 4; j++) acc[i][j] = 0.f;

    // A tile loader mapping
    const int aM = tid >> 2;          // 0..63
    const int aK = (tid & 3) * 4;     // 0,4,8,12
    // B tile loader mapping (non-trans)
    const int bK = tid >> 4;          // 0..15
    const int bN = (tid & 15) * 4;    // 0..60
    // B tile loader mapping (trans)
    const int tN = tid >> 2;          // 0..63
    const int tK = (tid & 3) * 4;     // 0,4,8,12

    for (int k0 = 0; k0 < K; k0 += 16) {
        float4 av = *(const float4*)&A[(size_t)(m0 + aM) * K + k0 + aK];
        As[aK + 0][aM] = av.x;
        As[aK + 1][aM] = av.y;
        As[aK + 2][aM] = av.z;
        As[aK + 3][aM] = av.w;
        if (TRANSB) {
            float4 bv = *(const float4*)&Bm[(size_t)(n0 + tN) * K + k0 + tK];
            Bs[tK + 0][tN] = bv.x;
            Bs[tK + 1][tN] = bv.y;
            Bs[tK + 2][tN] = bv.z;
            Bs[tK + 3][tN] = bv.w;
        } else {
            float4 bv = *(const float4*)&Bm[(size_t)(k0 + bK) * N + n0 + bN];
            *(float4*)&Bs[bK][bN] = bv;
        }
        __syncthreads();
#pragma unroll
        for (int k = 0; k < 16; k++) {
            float4 a = *(const float4*)&As[k][ty * 4];
            float4 b = *(const float4*)&Bs[k][tx * 4];
            acc[0][0] += a.x * b.x; acc[0][1] += a.x * b.y; acc[0][2] += a.x * b.z; acc[0][3] += a.x * b.w;
            acc[1][0] += a.y * b.x; acc[1][1] += a.y * b.y; acc[1][2] += a.y * b.z; acc[1][3] += a.y * b.w;
            acc[2][0] += a.z * b.x; acc[2][1] += a.z * b.y; acc[2][2] += a.z * b.z; acc[2][3] += a.z * b.w;
            acc[3][0] += a.w * b.x; acc[3][1] += a.w * b.y; acc[3][2] += a.w * b.z; acc[3][3] += a.w * b.w;
        }
        __syncthreads();
    }
#pragma unroll
    for (int i = 0; i < 4; i++) {
        float4 o;
        o.x = acc[i][0]; o.y = acc[i][1]; o.z = acc[i][2]; o.w = acc[i][3];
        *(float4*)&C[(size_t)(m0 + ty * 4 + i) * N + n0 + tx * 4] = o;
    }
}

// ---------------- sampled QK measure M = max_s(qk) - mean over L ------------
__global__ void measure_kernel(const float* __restrict__ Q,
                               const float* __restrict__ K,
                               const int* __restrict__ sidx,
                               float* __restrict__ Mout) {
    int gw = blockIdx.x * 4 + (threadIdx.x >> 5);
    int lane = threadIdx.x & 31;
    int l = gw % Ll;
    int bh = gw / Ll;
    int b = bh / Hh, h = bh % Hh;
    const float* q = Q + ((size_t)(b * Ll + l)) * DM + h * DK;
    float q0 = q[lane], q1 = q[lane + 32];
    float mx = -1e30f, sum = 0.f;
#pragma unroll 4
    for (int s = 0; s < Uu; s++) {
        int j = sidx[l * Uu + s];
        const float* kp = K + ((size_t)(b * Ll + j)) * DM + h * DK;
        float p = q0 * kp[lane] + q1 * kp[lane + 32];
#pragma unroll
        for (int o = 16; o; o >>= 1) p += __shfl_xor_sync(0xffffffffu, p, o);
        mx = fmaxf(mx, p);
        sum += p;
    }
    if (lane == 0) Mout[bh * Ll + l] = mx - sum / (float)Ll;
}

// ---------------- top-40 per (b,h), ties -> lowest index --------------------
__global__ void topk_kernel(const float* __restrict__ Mv, int* __restrict__ top) {
    int bh = blockIdx.x;
    int t = threadIdx.x;
    __shared__ float vals[Ll];
    __shared__ float rv[256];
    __shared__ int   ri[256];
    for (int i = t; i < Ll; i += 256) vals[i] = Mv[bh * Ll + i];
    __syncthreads();
    for (int k = 0; k < Uu; k++) {
        float bv = -1e30f; int bi = Ll;
        for (int i = t; i < Ll; i += 256) {
            float v = vals[i];
            if (v > bv) { bv = v; bi = i; }   // strided ascending -> first hit is lowest idx
        }
        rv[t] = bv; ri[t] = bi;
        __syncthreads();
        for (int s = 128; s; s >>= 1) {
            if (t < s) {
                if (rv[t + s] > rv[t] || (rv[t + s] == rv[t] && ri[t + s] < ri[t])) {
                    rv[t] = rv[t + s]; ri[t] = ri[t + s];
                }
            }
            __syncthreads();
        }
        if (t == 0) { top[bh * Uu + k] = ri[0]; vals[ri[0]] = -1e30f; }
        __syncthreads();
    }
}

// ---------------- V mean over L per (b,h,d) --------------------------------
__global__ void vmean_kernel(const float* __restrict__ V, float* __restrict__ vm) {
    int bh = blockIdx.x;
    int b = bh / Hh, h = bh % Hh;
    int t = threadIdx.x;           // 256
    int d = t & 63;
    int c = t >> 6;                // 4 chunks
    __shared__ float red[256];
    float s = 0.f;
    for (int l = c * (Ll / 4); l < (c + 1) * (Ll / 4); l++)
        s += V[((size_t)(b * Ll + l)) * DM + h * DK + d];
    red[t] = s;
    __syncthreads();
    if (c == 0) vm[bh * DK + d] = (red[d] + red[d + 64] + red[d + 128] + red[d + 192]) / (float)Ll;
}

// ---------------- scores = Q_red @ K^T / 8 ---------------------------------
__global__ void scores_kernel(const float* __restrict__ Q,
                              const float* __restrict__ K,
                              const int* __restrict__ top,
                              float* __restrict__ S) {
    int bh = blockIdx.y;
    int b = bh / Hh, h = bh % Hh;
    int l0 = blockIdx.x * 128;
    int t = threadIdx.x;           // 256
    __shared__ float Qs[Uu][DK];
    __shared__ float Ks[128][DK + 1];
    for (int idx = t; idx < Uu * DK; idx += 256) {
        int u = idx / DK, d = idx % DK;
        Qs[u][d] = Q[((size_t)(b * Ll + top[bh * Uu + u])) * DM + h * DK + d];
    }
    for (int idx = t; idx < 128 * DK; idx += 256) {
        int i = idx >> 6, d = idx & 63;
        Ks[i][d] = K[((size_t)(b * Ll + l0 + i)) * DM + h * DK + d];
    }
    __syncthreads();
    for (int idx = t; idx < Uu * 128; idx += 256) {
        int u = idx >> 7, i = idx & 127;
        float s = 0.f;
#pragma unroll
        for (int d = 0; d < DK; d++) s += Qs[u][d] * Ks[i][d];
        S[((size_t)(bh * Uu + u)) * Ll + l0 + i] = s * 0.125f;
    }
}

// ---------------- row softmax over L ---------------------------------------
__global__ void softmax_kernel(float* __restrict__ S) {
    int row = blockIdx.x;
    int t = threadIdx.x;           // 256
    float* p = S + (size_t)row * Ll;
    __shared__ float red[256];
    float mx = -1e30f;
    for (int i = t; i < Ll; i += 256) mx = fmaxf(mx, p[i]);
    red[t] = mx; __syncthreads();
    for (int s = 128; s; s >>= 1) { if (t < s) red[t] = fmaxf(red[t], red[t + s]); __syncthreads(); }
    mx = red[0]; __syncthreads();
    float sum = 0.f;
    for (int i = t; i < Ll; i += 256) { float e = expf(p[i] - mx); p[i] = e; sum += e; }
    red[t] = sum; __syncthreads();
    for (int s = 128; s; s >>= 1) { if (t < s) red[t] += red[t + s]; __syncthreads(); }
    float inv = 1.f / red[0];
    for (int i = t; i < Ll; i += 256) p[i] *= inv;
}

// ---------------- upd = attn @ V  (40 x L) @ (L x 64) ----------------------
__global__ void upd_kernel(const float* __restrict__ S,
                           const float* __restrict__ V,
                           float* __restrict__ upd) {
    int bh = blockIdx.x;
    int b = bh / Hh, h = bh % Hh;
    int t = threadIdx.x;           // 256
    __shared__ float Vs[64][DK + 1];
    __shared__ float As[Uu][64];
    int d = t & 63;
    int u0 = t >> 6;               // 0..3 ; outputs u = u0 + 4*o, o=0..9
    float acc[10];
#pragma unroll
    for (int o = 0; o < 10; o++) acc[o] = 0.f;

    for (int l0 = 0; l0 < Ll; l0 += 64) {
        for (int idx = t; idx < 64 * DK; idx += 256) {
            int i = idx >> 6, dd = idx & 63;
            Vs[i][dd] = V[((size_t)(b * Ll + l0 + i)) * DM + h * DK + dd];
        }
        for (int idx = t; idx < Uu * 64; idx += 256) {
            int u = idx >> 6, i = idx & 63;
            As[u][i] = S[((size_t)(bh * Uu + u)) * Ll + l0 + i];
        }
        __syncthreads();
#pragma unroll 8
        for (int i = 0; i < 64; i++) {
            float vv = Vs[i][d];
#pragma unroll
            for (int o = 0; o < 10; o++) acc[o] += As[u0 + 4 * o][i] * vv;
        }
        __syncthreads();
    }
#pragma unroll
    for (int o = 0; o < 10; o++) {
        int u = u0 + 4 * o;
        upd[((size_t)bh * Uu + u) * DK + d] = acc[o];
    }
}

// ---------------- ctx fill with mean, then scatter upd ---------------------
__global__ void ctxfill_kernel(const float* __restrict__ vm, float* __restrict__ ctx) {
    size_t i = (size_t)blockIdx.x * 256 + threadIdx.x;   // over ROWS*DM
    int col = (int)(i % DM);
    int b = (int)(i / ((size_t)Ll * DM));
    ctx[i] = vm[(b * Hh + (col >> 6)) * DK + (col & 63)];
}

__global__ void scatter_kernel(const float* __restrict__ upd,
                               const int* __restrict__ top,
                               float* __restrict__ ctx) {
    int i = blockIdx.x * 256 + threadIdx.x;              // BH*Uu*DK = 81920
    int d = i & 63;
    int u = (i >> 6) % Uu;
    int bh = i / (DK * Uu);
    int b = bh / Hh, h = bh % Hh;
    int l = top[bh * Uu + u];
    ctx[((size_t)(b * Ll + l)) * DM + h * DK + d] = upd[i];
}

// ---------------- residual (+bias) + LayerNorm -----------------------------
__global__ void addln_kernel(const float* __restrict__ A,
                             const float* __restrict__ R,
                             const float* __restrict__ bias,   // may be null
                             const float* __restrict__ gamma,
                             const float* __restrict__ beta,
                             float* __restrict__ out) {
    int row = blockIdx.x;
    int t = threadIdx.x;           // 256, DM=512 -> 2 per thread
    __shared__ float red[256];
    size_t base = (size_t)row * DM;
    float v0 = A[base + t] + R[base + t];
    float v1 = A[base + t + 256] + R[base + t + 256];
    if (bias) { v0 += bias[t]; v1 += bias[t + 256]; }
    red[t] = v0 + v1; __syncthreads();
    for (int s = 128; s; s >>= 1) { if (t < s) red[t] += red[t + s]; __syncthreads(); }
    float mean = red[0] / (float)DM; __syncthreads();
    float d0 = v0 - mean, d1 = v1 - mean;
    red[t] = d0 * d0 + d1 * d1; __syncthreads();
    for (int s = 128; s; s >>= 1) { if (t < s) red[t] += red[t + s]; __syncthreads(); }
    float inv = rsqrtf(red[0] / (float)DM + 1e-5f);
    out[base + t]       = d0 * inv * gamma[t]       + beta[t];
    out[base + t + 256] = d1 * inv * gamma[t + 256] + beta[t + 256];
}

// ---------------- bias + exact GELU ----------------------------------------
__global__ void biasgelu_kernel(float* __restrict__ Y, const float* __restrict__ bias) {
    size_t i = (size_t)blockIdx.x * 256 + threadIdx.x;   // ROWS*DFF
    int col = (int)(i % DFF);
    float v = Y[i] + bias[col];
    Y[i] = 0.5f * v * (1.f + erff(v * 0.70710678118654752f));
}

// ---------------- host orchestration ---------------------------------------
extern "C" void kernel_launch(void* const* d_in, const int* in_sizes, int n_in,
                              void* d_out, int out_size) {
    const float* x       = (const float*)d_in[0];
    const float* Wq      = (const float*)d_in[1];
    const float* Wk      = (const float*)d_in[2];
    const float* Wv      = (const float*)d_in[3];
    const float* Wo      = (const float*)d_in[4];
    const float* ln1g    = (const float*)d_in[5];
    const float* ln1b    = (const float*)d_in[6];
    const float* w1      = (const float*)d_in[7];   // [DFF, DM]
    const float* b1      = (const float*)d_in[8];
    const float* w2      = (const float*)d_in[9];   // [DM, DFF]
    const float* b2      = (const float*)d_in[10];
    const float* ln2g    = (const float*)d_in[11];
    const float* ln2b    = (const float*)d_in[12];
    const int*   sidx    = (const int*)d_in[13];
    float* out = (float*)d_out;

    float *pQ, *pK, *pV, *pM, *pS, *pUpd, *pVm, *pCtx, *pAo, *pX1, *pFF, *pY2;
    int *pTop;
    cudaGetSymbolAddress((void**)&pQ, g_Q);
    cudaGetSymbolAddress((void**)&pK, g_K);
    cudaGetSymbolAddress((void**)&pV, g_V);
    cudaGetSymbolAddress((void**)&pM, g_M);
    cudaGetSymbolAddress((void**)&pTop, g_top);
    cudaGetSymbolAddress((void**)&pS, g_S);
    cudaGetSymbolAddress((void**)&pUpd, g_upd);
    cudaGetSymbolAddress((void**)&pVm, g_vm);
    cudaGetSymbolAddress((void**)&pCtx, g_ctx);
    cudaGetSymbolAddress((void**)&pAo, g_ao);
    cudaGetSymbolAddress((void**)&pX1, g_x1);
    cudaGetSymbolAddress((void**)&pFF, g_ff);
    cudaGetSymbolAddress((void**)&pY2, g_y2);

    dim3 blk(16, 16);
    dim3 gProj(DM / 64, ROWS / 64);

    // QKV projections (stored [B, L, H*DK] row-major)
    sgemm_kernel<0><<<gProj, blk>>>(x, Wq, pQ, ROWS, DM, DM);
    sgemm_kernel<0><<<gProj, blk>>>(x, Wk, pK, ROWS, DM, DM);
    sgemm_kernel<0><<<gProj, blk>>>(x, Wv, pV, ROWS, DM, DM);

    // sparse measure + top-k
    measure_kernel<<<BH * Ll / 4, 128>>>(pQ, pK, sidx, pM);
    topk_kernel<<<BH, 256>>>(pM, pTop);

    // mean-V context
    vmean_kernel<<<BH, 256>>>(pV, pVm);

    // reduced attention
    scores_kernel<<<dim3(Ll / 128, BH), 256>>>(pQ, pK, pTop, pS);
    softmax_kernel<<<BH * Uu, 256>>>(pS);
    upd_kernel<<<BH, 256>>>(pS, pV, pUpd);

    // context assembly + output projection
    ctxfill_kernel<<<(ROWS * DM) / 256, 256>>>(pVm, pCtx);
    scatter_kernel<<<(BH * Uu * DK) / 256, 256>>>(pUpd, pTop, pCtx);
    sgemm_kernel<0><<<gProj, blk>>>(pCtx, Wo, pAo, ROWS, DM, DM);

    // residual + LN1
    addln_kernel<<<ROWS, 256>>>(x, pAo, nullptr, ln1g, ln1b, pX1);

    // FFN
    sgemm_kernel<1><<<dim3(DFF / 64, ROWS / 64), blk>>>(pX1, w1, pFF, ROWS, DFF, DM);
    biasgelu_kernel<<<(size_t)ROWS * DFF / 256, 256>>>(pFF, b1);
    sgemm_kernel<1><<<dim3(DM / 64, ROWS / 64), blk>>>(pFF, w2, pY2, ROWS, DM, DFF);

    // residual + bias + LN2 -> output
    addln_kernel<<<ROWS, 256>>>(pX1, pY2, b2, ln2g, ln2b, out);
}

// round 3
// speedup vs baseline: 2.1299x; 2.1299x over previous
#include <cuda_runtime.h>
#include <math.h>
#include <stdint.h>

#define Bb 4
#define Ll 2048
#define DM 512
#define Hh 8
#define DK 64
#define DFF 2048
#define Uu 40
#define BH (Bb*Hh)
#define ROWS (Bb*Ll)

// ---------------- scratch (static device globals; allocation-free) ----------
__device__ float g_Q[ROWS*DM];
__device__ float g_K[ROWS*DM];
__device__ float g_V[ROWS*DM];
__device__ float g_M[BH*Ll];
__device__ int   g_top[BH*Uu];
__device__ float g_S[BH*Uu*Ll];
__device__ float g_upd[BH*Uu*DK];
__device__ float g_vm[BH*DK];
__device__ float g_ctx[ROWS*DM];
__device__ float g_ao[ROWS*DM];
__device__ float g_x1[ROWS*DM];
__device__ float g_ff[ROWS*DFF];
__device__ float g_y2[ROWS*DM];
__device__ float g_WT[2*DM*DM];   // transposed Wv, Wo : [N,K]

#define SWZ(b) ((b) ^ (((b) >> 3) & 0x70))

__device__ __forceinline__ uint32_t smem_u32(const void* p) {
    uint32_t a;
    asm("{ .reg .u64 t; cvta.to.shared.u64 t, %1; cvt.u32.u64 %0, t; }" : "=r"(a) : "l"(p));
    return a;
}
__device__ __forceinline__ void cp_async16(uint32_t s, const void* g) {
    asm volatile("cp.async.cg.shared.global [%0], [%1], 16;" :: "r"(s), "l"(g) : "memory");
}
__device__ __forceinline__ void ldsm_x4(uint32_t* r, uint32_t a) {
    asm volatile("ldmatrix.sync.aligned.m8n8.x4.shared.b16 {%0,%1,%2,%3}, [%4];"
                 : "=r"(r[0]), "=r"(r[1]), "=r"(r[2]), "=r"(r[3]) : "r"(a));
}
__device__ __forceinline__ uint32_t tf32u(uint32_t x) {
    uint32_t r;
    asm("cvt.rna.tf32.f32 %0, %1;" : "=r"(r) : "f"(__uint_as_float(x)));
    return r;
}
__device__ __forceinline__ void mma_tf32(float* c, const uint32_t* a, uint32_t b0, uint32_t b1) {
    asm volatile("mma.sync.aligned.m16n8k8.row.col.f32.tf32.tf32.f32 "
                 "{%0,%1,%2,%3}, {%4,%5,%6,%7}, {%8,%9}, {%0,%1,%2,%3};"
                 : "+f"(c[0]), "+f"(c[1]), "+f"(c[2]), "+f"(c[3])
                 : "r"(a[0]), "r"(a[1]), "r"(a[2]), "r"(a[3]), "r"(b0), "r"(b1));
}
__device__ __forceinline__ float gelu_f(float v) {
    return 0.5f * v * (1.f + erff(v * 0.70710678118654752f));
}

// ============ tf32 mma.sync GEMM: C[M,N] = A[M,K] @ B^T, B stored [N,K] =====
// Block 128x128, BK=32, 256 threads (8 warps, warp tile 64x32), 3-stage cp.async.
// EPI: 0 plain store, 1 bias+GELU.
template<int EPI>
__global__ void __launch_bounds__(256, 2) mma_gemm(
    const float* __restrict__ A, const float* __restrict__ Bw,
    const float* __restrict__ bias, float* __restrict__ C,
    int M, int N, int K)
{
    extern __shared__ char smem[];
    const uint32_t sbase = smem_u32(smem);
    const int tid = threadIdx.x, wid = tid >> 5, lane = tid & 31;
    const int m0 = blockIdx.y * 128, n0 = blockIdx.x * 128;
    const int wm0 = (wid & 1) * 64, wn0 = (wid >> 1) * 32;
    const int STG = 32768;               // per-stage bytes: A 16KB + B 16KB
    const int KC = K >> 5;

    float acc[4][4][4];
#pragma unroll
    for (int i = 0; i < 4; i++)
#pragma unroll
        for (int j = 0; j < 4; j++)
#pragma unroll
            for (int r = 0; r < 4; r++) acc[i][j][r] = 0.f;

    const int lr = tid >> 3;             // 0..31 -> combined with pass
    const int lc = tid & 7;              // 16B chunk 0..7

    auto load_stage = [&](int kc, int s) {
        const float* Ap = A + (size_t)m0 * K + kc * 32;
        const float* Bp = Bw + (size_t)n0 * K + kc * 32;
        uint32_t sa = sbase + s * STG;
        uint32_t sbB = sa + 16384;
#pragma unroll
        for (int p = 0; p < 4; p++) {
            int rr = lr + p * 32;
            uint32_t so = SWZ((uint32_t)(rr * 128 + lc * 16));
            cp_async16(sa + so,  Ap + (size_t)rr * K + lc * 4);
            cp_async16(sbB + so, Bp + (size_t)rr * K + lc * 4);
        }
    };

    // prologue: stages 0,1
    load_stage(0, 0);
    asm volatile("cp.async.commit_group;");
    if (KC > 1) load_stage(1, 1);
    asm volatile("cp.async.commit_group;");

    // per-lane ldmatrix row mapping
    const int arow = lane & 15;              // A: rows 0..15 of m16 tile
    const int ae   = lane >> 4;              // A: k-chunk lo/hi
    const int brow = ((lane >> 4) << 3) + (lane & 7);  // B: n row within n16 pair
    const int be   = (lane >> 3) & 1;        // B: k-chunk lo/hi

    for (int i = 0; i < KC; i++) {
        asm volatile("cp.async.wait_group 1;" ::: "memory");
        __syncthreads();
        if (i + 2 < KC) load_stage(i + 2, (i + 2) % 3);
        asm volatile("cp.async.commit_group;");

        uint32_t sa = sbase + (i % 3) * STG;
        uint32_t sbB = sa + 16384;
#pragma unroll
        for (int s8 = 0; s8 < 4; s8++) {
            uint32_t Af[4][4], Bf[2][4];
#pragma unroll
            for (int mt = 0; mt < 4; mt++) {
                uint32_t addr = sa + SWZ((uint32_t)((wm0 + mt * 16 + arow) * 128 + (s8 * 2 + ae) * 16));
                ldsm_x4(Af[mt], addr);
            }
#pragma unroll
            for (int p = 0; p < 2; p++) {
                uint32_t addr = sbB + SWZ((uint32_t)((wn0 + p * 16 + brow) * 128 + (s8 * 2 + be) * 16));
                ldsm_x4(Bf[p], addr);
            }
#pragma unroll
            for (int mt = 0; mt < 4; mt++)
#pragma unroll
                for (int r = 0; r < 4; r++) Af[mt][r] = tf32u(Af[mt][r]);
#pragma unroll
            for (int p = 0; p < 2; p++)
#pragma unroll
                for (int r = 0; r < 4; r++) Bf[p][r] = tf32u(Bf[p][r]);
#pragma unroll
            for (int mt = 0; mt < 4; mt++)
#pragma unroll
                for (int nt = 0; nt < 4; nt++)
                    mma_tf32(acc[mt][nt], Af[mt],
                             Bf[nt >> 1][(nt & 1) * 2], Bf[nt >> 1][(nt & 1) * 2 + 1]);
        }
        __syncthreads();
    }
    asm volatile("cp.async.wait_group 0;" ::: "memory");

    // epilogue
    const int rbase = m0 + wm0 + (lane >> 2);
    const int cbase = n0 + wn0 + (lane & 3) * 2;
#pragma unroll
    for (int mt = 0; mt < 4; mt++) {
#pragma unroll
        for (int nt = 0; nt < 4; nt++) {
            int col = cbase + nt * 8;
            float v0 = acc[mt][nt][0], v1 = acc[mt][nt][1];
            float v2 = acc[mt][nt][2], v3 = acc[mt][nt][3];
            if (EPI == 1) {
                float b0 = bias[col], b1 = bias[col + 1];
                v0 = gelu_f(v0 + b0); v1 = gelu_f(v1 + b1);
                v2 = gelu_f(v2 + b0); v3 = gelu_f(v3 + b1);
            }
            float2 p0; p0.x = v0; p0.y = v1;
            float2 p1; p1.x = v2; p1.y = v3;
            *(float2*)&C[(size_t)(rbase + mt * 16) * N + col] = p0;
            *(float2*)&C[(size_t)(rbase + mt * 16 + 8) * N + col] = p1;
        }
    }
}

// ---------------- fp32 SIMT GEMM (proven; used for Q,K) --------------------
// C[M,N] = A[M,K] @ B, B is [K,N] row-major.
__global__ void sgemm_kernel(const float* __restrict__ A,
                             const float* __restrict__ Bm,
                             float* __restrict__ C,
                             int M, int N, int K) {
    __shared__ float As[16][64];
    __shared__ float Bs[16][64];

    const int tx = threadIdx.x;
    const int ty = threadIdx.y;
    const int tid = ty * 16 + tx;
    const int m0 = blockIdx.y * 64;
    const int n0 = blockIdx.x * 64;

    float acc[4][4];
#pragma unroll
    for (int i = 0; i < 4; i++)
#pragma unroll
        for (int j = 0; j < 4; j++) acc[i][j] = 0.f;

    const int aM = tid >> 2;
    const int aK = (tid & 3) * 4;
    const int bK = tid >> 4;
    const int bN = (tid & 15) * 4;

    for (int k0 = 0; k0 < K; k0 += 16) {
        float4 av = *(const float4*)&A[(size_t)(m0 + aM) * K + k0 + aK];
        As[aK + 0][aM] = av.x;
        As[aK + 1][aM] = av.y;
        As[aK + 2][aM] = av.z;
        As[aK + 3][aM] = av.w;
        float4 bv = *(const float4*)&Bm[(size_t)(k0 + bK) * N + n0 + bN];
        *(float4*)&Bs[bK][bN] = bv;
        __syncthreads();
#pragma unroll
        for (int k = 0; k < 16; k++) {
            float4 a = *(const float4*)&As[k][ty * 4];
            float4 b = *(const float4*)&Bs[k][tx * 4];
            acc[0][0] += a.x * b.x; acc[0][1] += a.x * b.y; acc[0][2] += a.x * b.z; acc[0][3] += a.x * b.w;
            acc[1][0] += a.y * b.x; acc[1][1] += a.y * b.y; acc[1][2] += a.y * b.z; acc[1][3] += a.y * b.w;
            acc[2][0] += a.z * b.x; acc[2][1] += a.z * b.y; acc[2][2] += a.z * b.z; acc[2][3] += a.z * b.w;
            acc[3][0] += a.w * b.x; acc[3][1] += a.w * b.y; acc[3][2] += a.w * b.z; acc[3][3] += a.w * b.w;
        }
        __syncthreads();
    }
#pragma unroll
    for (int i = 0; i < 4; i++) {
        float4 o;
        o.x = acc[i][0]; o.y = acc[i][1]; o.z = acc[i][2]; o.w = acc[i][3];
        *(float4*)&C[(size_t)(m0 + ty * 4 + i) * N + n0 + tx * 4] = o;
    }
}

// ---------------- 512x512 transpose ----------------------------------------
__global__ void transpose_kernel(const float* __restrict__ W, float* __restrict__ Wt) {
    __shared__ float t[32][33];
    int bx = blockIdx.x * 32, by = blockIdx.y * 32;
    int x = bx + threadIdx.x;
    for (int i = threadIdx.y; i < 32; i += 8)
        t[i][threadIdx.x] = W[(size_t)(by + i) * DM + x];
    __syncthreads();
    int x2 = by + threadIdx.x;
    for (int i = threadIdx.y; i < 32; i += 8)
        Wt[(size_t)(bx + i) * DM + x2] = t[threadIdx.x][i];
}

// ---------------- sampled QK measure ---------------------------------------
__global__ void measure_kernel(const float* __restrict__ Q,
                               const float* __restrict__ K,
                               const int* __restrict__ sidx,
                               float* __restrict__ Mout) {
    int gw = blockIdx.x * 4 + (threadIdx.x >> 5);
    int lane = threadIdx.x & 31;
    int l = gw % Ll;
    int bh = gw / Ll;
    int b = bh / Hh, h = bh % Hh;
    const float* q = Q + ((size_t)(b * Ll + l)) * DM + h * DK;
    float q0 = q[lane], q1 = q[lane + 32];
    float mx = -1e30f, sum = 0.f;
#pragma unroll 4
    for (int s = 0; s < Uu; s++) {
        int j = sidx[l * Uu + s];
        const float* kp = K + ((size_t)(b * Ll + j)) * DM + h * DK;
        float p = q0 * kp[lane] + q1 * kp[lane + 32];
#pragma unroll
        for (int o = 16; o; o >>= 1) p += __shfl_xor_sync(0xffffffffu, p, o);
        mx = fmaxf(mx, p);
        sum += p;
    }
    if (lane == 0) Mout[bh * Ll + l] = mx - sum / (float)Ll;
}

// ---------------- top-40 per (b,h) -----------------------------------------
__global__ void topk_kernel(const float* __restrict__ Mv, int* __restrict__ top) {
    int bh = blockIdx.x;
    int t = threadIdx.x;
    __shared__ float vals[Ll];
    __shared__ float rv[256];
    __shared__ int   ri[256];
    for (int i = t; i < Ll; i += 256) vals[i] = Mv[bh * Ll + i];
    __syncthreads();
    for (int k = 0; k < Uu; k++) {
        float bv = -1e30f; int bi = Ll;
        for (int i = t; i < Ll; i += 256) {
            float v = vals[i];
            if (v > bv) { bv = v; bi = i; }
        }
        rv[t] = bv; ri[t] = bi;
        __syncthreads();
        for (int s = 128; s; s >>= 1) {
            if (t < s) {
                if (rv[t + s] > rv[t] || (rv[t + s] == rv[t] && ri[t + s] < ri[t])) {
                    rv[t] = rv[t + s]; ri[t] = ri[t + s];
                }
            }
            __syncthreads();
        }
        if (t == 0) { top[bh * Uu + k] = ri[0]; vals[ri[0]] = -1e30f; }
        __syncthreads();
    }
}

// ---------------- V mean ----------------------------------------------------
__global__ void vmean_kernel(const float* __restrict__ V, float* __restrict__ vm) {
    int bh = blockIdx.x;
    int b = bh / Hh, h = bh % Hh;
    int t = threadIdx.x;
    int d = t & 63;
    int c = t >> 6;
    __shared__ float red[256];
    float s = 0.f;
    for (int l = c * (Ll / 4); l < (c + 1) * (Ll / 4); l++)
        s += V[((size_t)(b * Ll + l)) * DM + h * DK + d];
    red[t] = s;
    __syncthreads();
    if (c == 0) vm[bh * DK + d] = (red[d] + red[d + 64] + red[d + 128] + red[d + 192]) / (float)Ll;
}

// ---------------- scores = Q_red @ K^T / 8 ---------------------------------
__global__ void scores_kernel(const float* __restrict__ Q,
                              const float* __restrict__ K,
                              const int* __restrict__ top,
                              float* __restrict__ S) {
    int bh = blockIdx.y;
    int b = bh / Hh, h = bh % Hh;
    int l0 = blockIdx.x * 128;
    int t = threadIdx.x;
    __shared__ float Qs[Uu][DK];
    __shared__ float Ks[128][DK + 1];
    for (int idx = t; idx < Uu * DK; idx += 256) {
        int u = idx / DK, d = idx % DK;
        Qs[u][d] = Q[((size_t)(b * Ll + top[bh * Uu + u])) * DM + h * DK + d];
    }
    for (int idx = t; idx < 128 * DK; idx += 256) {
        int i = idx >> 6, d = idx & 63;
        Ks[i][d] = K[((size_t)(b * Ll + l0 + i)) * DM + h * DK + d];
    }
    __syncthreads();
    for (int idx = t; idx < Uu * 128; idx += 256) {
        int u = idx >> 7, i = idx & 127;
        float s = 0.f;
#pragma unroll
        for (int d = 0; d < DK; d++) s += Qs[u][d] * Ks[i][d];
        S[((size_t)(bh * Uu + u)) * Ll + l0 + i] = s * 0.125f;
    }
}

// ---------------- row softmax ----------------------------------------------
__global__ void softmax_kernel(float* __restrict__ S) {
    int row = blockIdx.x;
    int t = threadIdx.x;
    float* p = S + (size_t)row * Ll;
    __shared__ float red[256];
    float mx = -1e30f;
    for (int i = t; i < Ll; i += 256) mx = fmaxf(mx, p[i]);
    red[t] = mx; __syncthreads();
    for (int s = 128; s; s >>= 1) { if (t < s) red[t] = fmaxf(red[t], red[t + s]); __syncthreads(); }
    mx = red[0]; __syncthreads();
    float sum = 0.f;
    for (int i = t; i < Ll; i += 256) { float e = expf(p[i] - mx); p[i] = e; sum += e; }
    red[t] = sum; __syncthreads();
    for (int s = 128; s; s >>= 1) { if (t < s) red[t] += red[t + s]; __syncthreads(); }
    float inv = 1.f / red[0];
    for (int i = t; i < Ll; i += 256) p[i] *= inv;
}

// ---------------- upd = attn @ V -------------------------------------------
__global__ void upd_kernel(const float* __restrict__ S,
                           const float* __restrict__ V,
                           float* __restrict__ upd) {
    int bh = blockIdx.x;
    int b = bh / Hh, h = bh % Hh;
    int t = threadIdx.x;
    __shared__ float Vs[64][DK + 1];
    __shared__ float As[Uu][64];
    int d = t & 63;
    int u0 = t >> 6;
    float acc[10];
#pragma unroll
    for (int o = 0; o < 10; o++) acc[o] = 0.f;

    for (int l0 = 0; l0 < Ll; l0 += 64) {
        for (int idx = t; idx < 64 * DK; idx += 256) {
            int i = idx >> 6, dd = idx & 63;
            Vs[i][dd] = V[((size_t)(b * Ll + l0 + i)) * DM + h * DK + dd];
        }
        for (int idx = t; idx < Uu * 64; idx += 256) {
            int u = idx >> 6, i = idx & 63;
            As[u][i] = S[((size_t)(bh * Uu + u)) * Ll + l0 + i];
        }
        __syncthreads();
#pragma unroll 8
        for (int i = 0; i < 64; i++) {
            float vv = Vs[i][d];
#pragma unroll
            for (int o = 0; o < 10; o++) acc[o] += As[u0 + 4 * o][i] * vv;
        }
        __syncthreads();
    }
#pragma unroll
    for (int o = 0; o < 10; o++) {
        int u = u0 + 4 * o;
        upd[((size_t)bh * Uu + u) * DK + d] = acc[o];
    }
}

// ---------------- ctx fill + scatter ---------------------------------------
__global__ void ctxfill_kernel(const float* __restrict__ vm, float* __restrict__ ctx) {
    size_t i = (size_t)blockIdx.x * 256 + threadIdx.x;
    int col = (int)(i % DM);
    int b = (int)(i / ((size_t)Ll * DM));
    ctx[i] = vm[(b * Hh + (col >> 6)) * DK + (col & 63)];
}

__global__ void scatter_kernel(const float* __restrict__ upd,
                               const int* __restrict__ top,
                               float* __restrict__ ctx) {
    int i = blockIdx.x * 256 + threadIdx.x;
    int d = i & 63;
    int u = (i >> 6) % Uu;
    int bh = i / (DK * Uu);
    int b = bh / Hh, h = bh % Hh;
    int l = top[bh * Uu + u];
    ctx[((size_t)(b * Ll + l)) * DM + h * DK + d] = upd[i];
}

// ---------------- residual (+bias) + LayerNorm -----------------------------
__global__ void addln_kernel(const float* __restrict__ A,
                             const float* __restrict__ R,
                             const float* __restrict__ bias,
                             const float* __restrict__ gamma,
                             const float* __restrict__ beta,
                             float* __restrict__ out) {
    int row = blockIdx.x;
    int t = threadIdx.x;
    __shared__ float red[256];
    size_t base = (size_t)row * DM;
    float v0 = A[base + t] + R[base + t];
    float v1 = A[base + t + 256] + R[base + t + 256];
    if (bias) { v0 += bias[t]; v1 += bias[t + 256]; }
    red[t] = v0 + v1; __syncthreads();
    for (int s = 128; s; s >>= 1) { if (t < s) red[t] += red[t + s]; __syncthreads(); }
    float mean = red[0] / (float)DM; __syncthreads();
    float d0 = v0 - mean, d1 = v1 - mean;
    red[t] = d0 * d0 + d1 * d1; __syncthreads();
    for (int s = 128; s; s >>= 1) { if (t < s) red[t] += red[t + s]; __syncthreads(); }
    float inv = rsqrtf(red[0] / (float)DM + 1e-5f);
    out[base + t]       = d0 * inv * gamma[t]       + beta[t];
    out[base + t + 256] = d1 * inv * gamma[t + 256] + beta[t + 256];
}

// ---------------- host orchestration ---------------------------------------
extern "C" void kernel_launch(void* const* d_in, const int* in_sizes, int n_in,
                              void* d_out, int out_size) {
    const float* x    = (const float*)d_in[0];
    const float* Wq   = (const float*)d_in[1];
    const float* Wk   = (const float*)d_in[2];
    const float* Wv   = (const float*)d_in[3];
    const float* Wo   = (const float*)d_in[4];
    const float* ln1g = (const float*)d_in[5];
    const float* ln1b = (const float*)d_in[6];
    const float* w1   = (const float*)d_in[7];   // [DFF, DM] = [N,K]
    const float* b1   = (const float*)d_in[8];
    const float* w2   = (const float*)d_in[9];   // [DM, DFF] = [N,K]
    const float* b2   = (const float*)d_in[10];
    const float* ln2g = (const float*)d_in[11];
    const float* ln2b = (const float*)d_in[12];
    const int*   sidx = (const int*)d_in[13];
    float* out = (float*)d_out;

    float *pQ, *pK, *pV, *pM, *pS, *pUpd, *pVm, *pCtx, *pAo, *pX1, *pFF, *pY2, *pWT;
    int *pTop;
    cudaGetSymbolAddress((void**)&pQ, g_Q);
    cudaGetSymbolAddress((void**)&pK, g_K);
    cudaGetSymbolAddress((void**)&pV, g_V);
    cudaGetSymbolAddress((void**)&pM, g_M);
    cudaGetSymbolAddress((void**)&pTop, g_top);
    cudaGetSymbolAddress((void**)&pS, g_S);
    cudaGetSymbolAddress((void**)&pUpd, g_upd);
    cudaGetSymbolAddress((void**)&pVm, g_vm);
    cudaGetSymbolAddress((void**)&pCtx, g_ctx);
    cudaGetSymbolAddress((void**)&pAo, g_ao);
    cudaGetSymbolAddress((void**)&pX1, g_x1);
    cudaGetSymbolAddress((void**)&pFF, g_ff);
    cudaGetSymbolAddress((void**)&pY2, g_y2);
    cudaGetSymbolAddress((void**)&pWT, g_WT);

    const int smemT = 3 * 32768;   // 98304
    cudaFuncSetAttribute(mma_gemm<0>, cudaFuncAttributeMaxDynamicSharedMemorySize, smemT);
    cudaFuncSetAttribute(mma_gemm<1>, cudaFuncAttributeMaxDynamicSharedMemorySize, smemT);

    float* WvT = pWT;
    float* WoT = pWT + DM * DM;
    dim3 tblk(32, 8), tgrid(DM / 32, DM / 32);
    transpose_kernel<<<tgrid, tblk>>>(Wv, WvT);
    transpose_kernel<<<tgrid, tblk>>>(Wo, WoT);

    dim3 blk(16, 16);
    dim3 gProj(DM / 64, ROWS / 64);
    dim3 gT512(DM / 128, ROWS / 128);    // (4, 64)
    dim3 gTff(DFF / 128, ROWS / 128);    // (16, 64)

    // Q,K in exact fp32 (top-k stability); V via tf32 tensor path
    sgemm_kernel<<<gProj, blk>>>(x, Wq, pQ, ROWS, DM, DM);
    sgemm_kernel<<<gProj, blk>>>(x, Wk, pK, ROWS, DM, DM);
    mma_gemm<0><<<gT512, 256, smemT>>>(x, WvT, nullptr, pV, ROWS, DM, DM);

    // sparse measure + top-k
    measure_kernel<<<BH * Ll / 4, 128>>>(pQ, pK, sidx, pM);
    topk_kernel<<<BH, 256>>>(pM, pTop);

    // mean-V context
    vmean_kernel<<<BH, 256>>>(pV, pVm);

    // reduced attention
    scores_kernel<<<dim3(Ll / 128, BH), 256>>>(pQ, pK, pTop, pS);
    softmax_kernel<<<BH * Uu, 256>>>(pS);
    upd_kernel<<<BH, 256>>>(pS, pV, pUpd);

    // context assembly + output projection (tf32)
    ctxfill_kernel<<<(ROWS * DM) / 256, 256>>>(pVm, pCtx);
    scatter_kernel<<<(BH * Uu * DK) / 256, 256>>>(pUpd, pTop, pCtx);
    mma_gemm<0><<<gT512, 256, smemT>>>(pCtx, WoT, nullptr, pAo, ROWS, DM, DM);

    // residual + LN1
    addln_kernel<<<ROWS, 256>>>(x, pAo, nullptr, ln1g, ln1b, pX1);

    // FFN (tf32; bias+GELU fused in GEMM1 epilogue)
    mma_gemm<1><<<gTff, 256, smemT>>>(pX1, w1, b1, pFF, ROWS, DFF, DM);
    mma_gemm<0><<<gT512, 256, smemT>>>(pFF, w2, nullptr, pY2, ROWS, DM, DFF);

    // residual + bias + LN2 -> output
    addln_kernel<<<ROWS, 256>>>(pX1, pY2, b2, ln2g, ln2b, out);
}

// round 4
// speedup vs baseline: 2.4650x; 1.1574x over previous
#include <cuda_runtime.h>
#include <math.h>
#include <stdint.h>

#define Bb 4
#define Ll 2048
#define DM 512
#define Hh 8
#define DK 64
#define DFF 2048
#define Uu 40
#define BH (Bb*Hh)
#define ROWS (Bb*Ll)

// ---------------- scratch (static device globals; allocation-free) ----------
__device__ float g_Q[ROWS*DM];
__device__ float g_K[ROWS*DM];
__device__ float g_V[ROWS*DM];
__device__ float g_M[BH*Ll];
__device__ int   g_top[BH*Uu];
__device__ float g_S[BH*Uu*Ll];
__device__ float g_upd[BH*Uu*DK];
__device__ float g_vm[BH*DK];
__device__ float g_ctx[ROWS*DM];
__device__ float g_ao[ROWS*DM];
__device__ float g_x1[ROWS*DM];
__device__ float g_ff[ROWS*DFF];
__device__ float g_y2[ROWS*DM];
__device__ float g_WT[4*DM*DM];   // transposed Wq, Wk, Wv, Wo : [N,K]

#define SWZ(b) ((b) ^ (((b) >> 3) & 0x70))

__device__ __forceinline__ uint32_t smem_u32(const void* p) {
    uint32_t a;
    asm("{ .reg .u64 t; cvta.to.shared.u64 t, %1; cvt.u32.u64 %0, t; }" : "=r"(a) : "l"(p));
    return a;
}
__device__ __forceinline__ void cp_async16(uint32_t s, const void* g) {
    asm volatile("cp.async.cg.shared.global [%0], [%1], 16;" :: "r"(s), "l"(g) : "memory");
}
__device__ __forceinline__ void ldsm_x4(uint32_t* r, uint32_t a) {
    asm volatile("ldmatrix.sync.aligned.m8n8.x4.shared.b16 {%0,%1,%2,%3}, [%4];"
                 : "=r"(r[0]), "=r"(r[1]), "=r"(r[2]), "=r"(r[3]) : "r"(a));
}
__device__ __forceinline__ void split_tf32(uint32_t x, uint32_t& hi, uint32_t& lo) {
    float f = __uint_as_float(x);
    asm("cvt.rna.tf32.f32 %0, %1;" : "=r"(hi) : "f"(f));
    float r = f - __uint_as_float(hi);
    asm("cvt.rna.tf32.f32 %0, %1;" : "=r"(lo) : "f"(r));
}
__device__ __forceinline__ void mma_tf32(float* c, const uint32_t* a, uint32_t b0, uint32_t b1) {
    asm volatile("mma.sync.aligned.m16n8k8.row.col.f32.tf32.tf32.f32 "
                 "{%0,%1,%2,%3}, {%4,%5,%6,%7}, {%8,%9}, {%0,%1,%2,%3};"
                 : "+f"(c[0]), "+f"(c[1]), "+f"(c[2]), "+f"(c[3])
                 : "r"(a[0]), "r"(a[1]), "r"(a[2]), "r"(a[3]), "r"(b0), "r"(b1));
}
__device__ __forceinline__ float gelu_f(float v) {
    return 0.5f * v * (1.f + erff(v * 0.70710678118654752f));
}

// ============ tf32 mma.sync GEMM (1-pass, raw-bit truncation) ==============
// C[M,N] = A[M,K] @ B^T, B stored [N,K]. Block 128x128, BK=32, 256 threads,
// 8 warps (warp tile 64x32), 3-stage cp.async. EPI: 0 plain, 1 bias+GELU.
template<int EPI>
__global__ void __launch_bounds__(256, 2) mma_gemm(
    const float* __restrict__ A, const float* __restrict__ Bw,
    const float* __restrict__ bias, float* __restrict__ C,
    int M, int N, int K)
{
    extern __shared__ char smem[];
    const uint32_t sbase = smem_u32(smem);
    const int tid = threadIdx.x, wid = tid >> 5, lane = tid & 31;
    const int m0 = blockIdx.y * 128, n0 = blockIdx.x * 128;
    const int wm0 = (wid & 1) * 64, wn0 = (wid >> 1) * 32;
    const int STG = 32768;
    const int KC = K >> 5;

    float acc[4][4][4];
#pragma unroll
    for (int i = 0; i < 4; i++)
#pragma unroll
        for (int j = 0; j < 4; j++)
#pragma unroll
            for (int r = 0; r < 4; r++) acc[i][j][r] = 0.f;

    const int lr = tid >> 3;
    const int lc = tid & 7;

    auto load_stage = [&](int kc, int s) {
        const float* Ap = A + (size_t)m0 * K + kc * 32;
        const float* Bp = Bw + (size_t)n0 * K + kc * 32;
        uint32_t sa = sbase + s * STG;
        uint32_t sbB = sa + 16384;
#pragma unroll
        for (int p = 0; p < 4; p++) {
            int rr = lr + p * 32;
            uint32_t so = SWZ((uint32_t)(rr * 128 + lc * 16));
            cp_async16(sa + so,  Ap + (size_t)rr * K + lc * 4);
            cp_async16(sbB + so, Bp + (size_t)rr * K + lc * 4);
        }
    };

    load_stage(0, 0);
    asm volatile("cp.async.commit_group;");
    if (KC > 1) load_stage(1, 1);
    asm volatile("cp.async.commit_group;");

    const int arow = lane & 15;
    const int ae   = lane >> 4;
    const int brow = ((lane >> 4) << 3) + (lane & 7);
    const int be   = (lane >> 3) & 1;

    for (int i = 0; i < KC; i++) {
        asm volatile("cp.async.wait_group 1;" ::: "memory");
        __syncthreads();
        if (i + 2 < KC) load_stage(i + 2, (i + 2) % 3);
        asm volatile("cp.async.commit_group;");

        uint32_t sa = sbase + (i % 3) * STG;
        uint32_t sbB = sa + 16384;
#pragma unroll
        for (int s8 = 0; s8 < 4; s8++) {
            uint32_t Af[4][4], Bf[2][4];
#pragma unroll
            for (int mt = 0; mt < 4; mt++) {
                uint32_t addr = sa + SWZ((uint32_t)((wm0 + mt * 16 + arow) * 128 + (s8 * 2 + ae) * 16));
                ldsm_x4(Af[mt], addr);
            }
#pragma unroll
            for (int p = 0; p < 2; p++) {
                uint32_t addr = sbB + SWZ((uint32_t)((wn0 + p * 16 + brow) * 128 + (s8 * 2 + be) * 16));
                ldsm_x4(Bf[p], addr);
            }
            // raw fp32 bits fed to tf32 mma: HW truncates low mantissa.
#pragma unroll
            for (int mt = 0; mt < 4; mt++)
#pragma unroll
                for (int nt = 0; nt < 4; nt++)
                    mma_tf32(acc[mt][nt], Af[mt],
                             Bf[nt >> 1][(nt & 1) * 2], Bf[nt >> 1][(nt & 1) * 2 + 1]);
        }
        __syncthreads();
    }
    asm volatile("cp.async.wait_group 0;" ::: "memory");

    const int rbase = m0 + wm0 + (lane >> 2);
    const int cbase = n0 + wn0 + (lane & 3) * 2;
#pragma unroll
    for (int mt = 0; mt < 4; mt++) {
#pragma unroll
        for (int nt = 0; nt < 4; nt++) {
            int col = cbase + nt * 8;
            float v0 = acc[mt][nt][0], v1 = acc[mt][nt][1];
            float v2 = acc[mt][nt][2], v3 = acc[mt][nt][3];
            if (EPI == 1) {
                float b0 = bias[col], b1 = bias[col + 1];
                v0 = gelu_f(v0 + b0); v1 = gelu_f(v1 + b1);
                v2 = gelu_f(v2 + b0); v3 = gelu_f(v3 + b1);
            }
            float2 p0; p0.x = v0; p0.y = v1;
            float2 p1; p1.x = v2; p1.y = v3;
            *(float2*)&C[(size_t)(rbase + mt * 16) * N + col] = p0;
            *(float2*)&C[(size_t)(rbase + mt * 16 + 8) * N + col] = p1;
        }
    }
}

// ============ tf32x3 mma.sync GEMM (3-pass, near-fp32; for Q,K) ============
__global__ void __launch_bounds__(256) mma_gemm3(
    const float* __restrict__ A, const float* __restrict__ Bw,
    float* __restrict__ C, int M, int N, int K)
{
    extern __shared__ char smem[];
    const uint32_t sbase = smem_u32(smem);
    const int tid = threadIdx.x, wid = tid >> 5, lane = tid & 31;
    const int m0 = blockIdx.y * 128, n0 = blockIdx.x * 128;
    const int wm0 = (wid & 1) * 64, wn0 = (wid >> 1) * 32;
    const int STG = 32768;
    const int KC = K >> 5;

    float acc[4][4][4];
#pragma unroll
    for (int i = 0; i < 4; i++)
#pragma unroll
        for (int j = 0; j < 4; j++)
#pragma unroll
            for (int r = 0; r < 4; r++) acc[i][j][r] = 0.f;

    const int lr = tid >> 3;
    const int lc = tid & 7;

    auto load_stage = [&](int kc, int s) {
        const float* Ap = A + (size_t)m0 * K + kc * 32;
        const float* Bp = Bw + (size_t)n0 * K + kc * 32;
        uint32_t sa = sbase + s * STG;
        uint32_t sbB = sa + 16384;
#pragma unroll
        for (int p = 0; p < 4; p++) {
            int rr = lr + p * 32;
            uint32_t so = SWZ((uint32_t)(rr * 128 + lc * 16));
            cp_async16(sa + so,  Ap + (size_t)rr * K + lc * 4);
            cp_async16(sbB + so, Bp + (size_t)rr * K + lc * 4);
        }
    };

    load_stage(0, 0);
    asm volatile("cp.async.commit_group;");
    if (KC > 1) load_stage(1, 1);
    asm volatile("cp.async.commit_group;");

    const int arow = lane & 15;
    const int ae   = lane >> 4;
    const int brow = ((lane >> 4) << 3) + (lane & 7);
    const int be   = (lane >> 3) & 1;

    for (int i = 0; i < KC; i++) {
        asm volatile("cp.async.wait_group 1;" ::: "memory");
        __syncthreads();
        if (i + 2 < KC) load_stage(i + 2, (i + 2) % 3);
        asm volatile("cp.async.commit_group;");

        uint32_t sa = sbase + (i % 3) * STG;
        uint32_t sbB = sa + 16384;
#pragma unroll
        for (int s8 = 0; s8 < 4; s8++) {
            uint32_t Af[4][4], Bh[2][4], Bl[2][4];
#pragma unroll
            for (int mt = 0; mt < 4; mt++) {
                uint32_t addr = sa + SWZ((uint32_t)((wm0 + mt * 16 + arow) * 128 + (s8 * 2 + ae) * 16));
                ldsm_x4(Af[mt], addr);
            }
#pragma unroll
            for (int p = 0; p < 2; p++) {
                uint32_t Br[4];
                uint32_t addr = sbB + SWZ((uint32_t)((wn0 + p * 16 + brow) * 128 + (s8 * 2 + be) * 16));
                ldsm_x4(Br, addr);
#pragma unroll
                for (int r = 0; r < 4; r++) split_tf32(Br[r], Bh[p][r], Bl[p][r]);
            }
#pragma unroll
            for (int mt = 0; mt < 4; mt++) {
                uint32_t Ah[4], Al[4];
#pragma unroll
                for (int r = 0; r < 4; r++) split_tf32(Af[mt][r], Ah[r], Al[r]);
#pragma unroll
                for (int nt = 0; nt < 4; nt++) {
                    uint32_t bh0 = Bh[nt >> 1][(nt & 1) * 2], bh1 = Bh[nt >> 1][(nt & 1) * 2 + 1];
                    uint32_t bl0 = Bl[nt >> 1][(nt & 1) * 2], bl1 = Bl[nt >> 1][(nt & 1) * 2 + 1];
                    mma_tf32(acc[mt][nt], Al, bh0, bh1);
                    mma_tf32(acc[mt][nt], Ah, bl0, bl1);
                    mma_tf32(acc[mt][nt], Ah, bh0, bh1);
                }
            }
        }
        __syncthreads();
    }
    asm volatile("cp.async.wait_group 0;" ::: "memory");

    const int rbase = m0 + wm0 + (lane >> 2);
    const int cbase = n0 + wn0 + (lane & 3) * 2;
#pragma unroll
    for (int mt = 0; mt < 4; mt++) {
#pragma unroll
        for (int nt = 0; nt < 4; nt++) {
            int col = cbase + nt * 8;
            float2 p0; p0.x = acc[mt][nt][0]; p0.y = acc[mt][nt][1];
            float2 p1; p1.x = acc[mt][nt][2]; p1.y = acc[mt][nt][3];
            *(float2*)&C[(size_t)(rbase + mt * 16) * N + col] = p0;
            *(float2*)&C[(size_t)(rbase + mt * 16 + 8) * N + col] = p1;
        }
    }
}

// ---------------- 512x512 transpose ----------------------------------------
__global__ void transpose_kernel(const float* __restrict__ W, float* __restrict__ Wt) {
    __shared__ float t[32][33];
    int bx = blockIdx.x * 32, by = blockIdx.y * 32;
    int x = bx + threadIdx.x;
    for (int i = threadIdx.y; i < 32; i += 8)
        t[i][threadIdx.x] = W[(size_t)(by + i) * DM + x];
    __syncthreads();
    int x2 = by + threadIdx.x;
    for (int i = threadIdx.y; i < 32; i += 8)
        Wt[(size_t)(bx + i) * DM + x2] = t[threadIdx.x][i];
}

// ---------------- sampled QK measure (ILP-2) --------------------------------
__global__ void measure_kernel(const float* __restrict__ Q,
                               const float* __restrict__ K,
                               const int* __restrict__ sidx,
                               float* __restrict__ Mout) {
    int gw = blockIdx.x * 4 + (threadIdx.x >> 5);
    int lane = threadIdx.x & 31;
    int l = gw % Ll;
    int bh = gw / Ll;
    int b = bh / Hh, h = bh % Hh;
    const float* q = Q + ((size_t)(b * Ll + l)) * DM + h * DK;
    float q0 = q[lane], q1 = q[lane + 32];
    const float* Kb = K + (size_t)b * Ll * DM + h * DK;
    float mx = -1e30f, sum = 0.f;
#pragma unroll 4
    for (int s = 0; s < Uu; s += 2) {
        int2 jj = *(const int2*)&sidx[l * Uu + s];
        const float* k0 = Kb + (size_t)jj.x * DM;
        const float* k1 = Kb + (size_t)jj.y * DM;
        float p0 = q0 * __ldg(k0 + lane) + q1 * __ldg(k0 + lane + 32);
        float p1 = q0 * __ldg(k1 + lane) + q1 * __ldg(k1 + lane + 32);
#pragma unroll
        for (int o = 16; o; o >>= 1) {
            p0 += __shfl_xor_sync(0xffffffffu, p0, o);
            p1 += __shfl_xor_sync(0xffffffffu, p1, o);
        }
        mx = fmaxf(mx, fmaxf(p0, p1));
        sum += p0 + p1;
    }
    if (lane == 0) Mout[bh * Ll + l] = mx - sum / (float)Ll;
}

// ---------------- top-40 per (b,h) -----------------------------------------
__global__ void topk_kernel(const float* __restrict__ Mv, int* __restrict__ top) {
    int bh = blockIdx.x;
    int t = threadIdx.x;
    __shared__ float vals[Ll];
    __shared__ float rv[256];
    __shared__ int   ri[256];
    for (int i = t; i < Ll; i += 256) vals[i] = Mv[bh * Ll + i];
    __syncthreads();
    for (int k = 0; k < Uu; k++) {
        float bv = -1e30f; int bi = Ll;
        for (int i = t; i < Ll; i += 256) {
            float v = vals[i];
            if (v > bv) { bv = v; bi = i; }
        }
        rv[t] = bv; ri[t] = bi;
        __syncthreads();
        for (int s = 128; s; s >>= 1) {
            if (t < s) {
                if (rv[t + s] > rv[t] || (rv[t + s] == rv[t] && ri[t + s] < ri[t])) {
                    rv[t] = rv[t + s]; ri[t] = ri[t + s];
                }
            }
            __syncthreads();
        }
        if (t == 0) { top[bh * Uu + k] = ri[0]; vals[ri[0]] = -1e30f; }
        __syncthreads();
    }
}

// ---------------- V mean ----------------------------------------------------
__global__ void vmean_kernel(const float* __restrict__ V, float* __restrict__ vm) {
    int bh = blockIdx.x;
    int b = bh / Hh, h = bh % Hh;
    int t = threadIdx.x;
    int d = t & 63;
    int c = t >> 6;
    __shared__ float red[256];
    float s = 0.f;
    for (int l = c * (Ll / 4); l < (c + 1) * (Ll / 4); l++)
        s += V[((size_t)(b * Ll + l)) * DM + h * DK + d];
    red[t] = s;
    __syncthreads();
    if (c == 0) vm[bh * DK + d] = (red[d] + red[d + 64] + red[d + 128] + red[d + 192]) / (float)Ll;
}

// ---------------- scores = Q_red @ K^T / 8 ---------------------------------
__global__ void scores_kernel(const float* __restrict__ Q,
                              const float* __restrict__ K,
                              const int* __restrict__ top,
                              float* __restrict__ S) {
    int bh = blockIdx.y;
    int b = bh / Hh, h = bh % Hh;
    int l0 = blockIdx.x * 128;
    int t = threadIdx.x;
    __shared__ float Qs[Uu][DK];
    __shared__ float Ks[128][DK + 1];
    for (int idx = t; idx < Uu * DK; idx += 256) {
        int u = idx / DK, d = idx % DK;
        Qs[u][d] = Q[((size_t)(b * Ll + top[bh * Uu + u])) * DM + h * DK + d];
    }
    for (int idx = t; idx < 128 * DK; idx += 256) {
        int i = idx >> 6, d = idx & 63;
        Ks[i][d] = K[((size_t)(b * Ll + l0 + i)) * DM + h * DK + d];
    }
    __syncthreads();
    for (int idx = t; idx < Uu * 128; idx += 256) {
        int u = idx >> 7, i = idx & 127;
        float s = 0.f;
#pragma unroll
        for (int d = 0; d < DK; d++) s += Qs[u][d] * Ks[i][d];
        S[((size_t)(bh * Uu + u)) * Ll + l0 + i] = s * 0.125f;
    }
}

// ---------------- row softmax ----------------------------------------------
__global__ void softmax_kernel(float* __restrict__ S) {
    int row = blockIdx.x;
    int t = threadIdx.x;
    float* p = S + (size_t)row * Ll;
    __shared__ float red[256];
    float mx = -1e30f;
    for (int i = t; i < Ll; i += 256) mx = fmaxf(mx, p[i]);
    red[t] = mx; __syncthreads();
    for (int s = 128; s; s >>= 1) { if (t < s) red[t] = fmaxf(red[t], red[t + s]); __syncthreads(); }
    mx = red[0]; __syncthreads();
    float sum = 0.f;
    for (int i = t; i < Ll; i += 256) { float e = expf(p[i] - mx); p[i] = e; sum += e; }
    red[t] = sum; __syncthreads();
    for (int s = 128; s; s >>= 1) { if (t < s) red[t] += red[t + s]; __syncthreads(); }
    float inv = 1.f / red[0];
    for (int i = t; i < Ll; i += 256) p[i] *= inv;
}

// ---------------- upd = attn @ V -------------------------------------------
__global__ void upd_kernel(const float* __restrict__ S,
                           const float* __restrict__ V,
                           float* __restrict__ upd) {
    int bh = blockIdx.x;
    int b = bh / Hh, h = bh % Hh;
    int t = threadIdx.x;
    __shared__ float Vs[64][DK + 1];
    __shared__ float As[Uu][64];
    int d = t & 63;
    int u0 = t >> 6;
    float acc[10];
#pragma unroll
    for (int o = 0; o < 10; o++) acc[o] = 0.f;

    for (int l0 = 0; l0 < Ll; l0 += 64) {
        for (int idx = t; idx < 64 * DK; idx += 256) {
            int i = idx >> 6, dd = idx & 63;
            Vs[i][dd] = V[((size_t)(b * Ll + l0 + i)) * DM + h * DK + dd];
        }
        for (int idx = t; idx < Uu * 64; idx += 256) {
            int u = idx >> 6, i = idx & 63;
            As[u][i] = S[((size_t)(bh * Uu + u)) * Ll + l0 + i];
        }
        __syncthreads();
#pragma unroll 8
        for (int i = 0; i < 64; i++) {
            float vv = Vs[i][d];
#pragma unroll
            for (int o = 0; o < 10; o++) acc[o] += As[u0 + 4 * o][i] * vv;
        }
        __syncthreads();
    }
#pragma unroll
    for (int o = 0; o < 10; o++) {
        int u = u0 + 4 * o;
        upd[((size_t)bh * Uu + u) * DK + d] = acc[o];
    }
}

// ---------------- ctx fill + scatter ---------------------------------------
__global__ void ctxfill_kernel(const float* __restrict__ vm, float* __restrict__ ctx) {
    size_t i = (size_t)blockIdx.x * 256 + threadIdx.x;
    int col = (int)(i % DM);
    int b = (int)(i / ((size_t)Ll * DM));
    ctx[i] = vm[(b * Hh + (col >> 6)) * DK + (col & 63)];
}

__global__ void scatter_kernel(const float* __restrict__ upd,
                               const int* __restrict__ top,
                               float* __restrict__ ctx) {
    int i = blockIdx.x * 256 + threadIdx.x;
    int d = i & 63;
    int u = (i >> 6) % Uu;
    int bh = i / (DK * Uu);
    int b = bh / Hh, h = bh % Hh;
    int l = top[bh * Uu + u];
    ctx[((size_t)(b * Ll + l)) * DM + h * DK + d] = upd[i];
}

// ---------------- residual (+bias) + LayerNorm -----------------------------
__global__ void addln_kernel(const float* __restrict__ A,
                             const float* __restrict__ R,
                             const float* __restrict__ bias,
                             const float* __restrict__ gamma,
                             const float* __restrict__ beta,
                             float* __restrict__ out) {
    int row = blockIdx.x;
    int t = threadIdx.x;
    __shared__ float red[256];
    size_t base = (size_t)row * DM;
    float v0 = A[base + t] + R[base + t];
    float v1 = A[base + t + 256] + R[base + t + 256];
    if (bias) { v0 += bias[t]; v1 += bias[t + 256]; }
    red[t] = v0 + v1; __syncthreads();
    for (int s = 128; s; s >>= 1) { if (t < s) red[t] += red[t + s]; __syncthreads(); }
    float mean = red[0] / (float)DM; __syncthreads();
    float d0 = v0 - mean, d1 = v1 - mean;
    red[t] = d0 * d0 + d1 * d1; __syncthreads();
    for (int s = 128; s; s >>= 1) { if (t < s) red[t] += red[t + s]; __syncthreads(); }
    float inv = rsqrtf(red[0] / (float)DM + 1e-5f);
    out[base + t]       = d0 * inv * gamma[t]       + beta[t];
    out[base + t + 256] = d1 * inv * gamma[t + 256] + beta[t + 256];
}

// ---------------- host orchestration ---------------------------------------
extern "C" void kernel_launch(void* const* d_in, const int* in_sizes, int n_in,
                              void* d_out, int out_size) {
    const float* x    = (const float*)d_in[0];
    const float* Wq   = (const float*)d_in[1];
    const float* Wk   = (const float*)d_in[2];
    const float* Wv   = (const float*)d_in[3];
    const float* Wo   = (const float*)d_in[4];
    const float* ln1g = (const float*)d_in[5];
    const float* ln1b = (const float*)d_in[6];
    const float* w1   = (const float*)d_in[7];   // [DFF, DM] = [N,K]
    const float* b1   = (const float*)d_in[8];
    const float* w2   = (const float*)d_in[9];   // [DM, DFF] = [N,K]
    const float* b2   = (const float*)d_in[10];
    const float* ln2g = (const float*)d_in[11];
    const float* ln2b = (const float*)d_in[12];
    const int*   sidx = (const int*)d_in[13];
    float* out = (float*)d_out;

    float *pQ, *pK, *pV, *pM, *pS, *pUpd, *pVm, *pCtx, *pAo, *pX1, *pFF, *pY2, *pWT;
    int *pTop;
    cudaGetSymbolAddress((void**)&pQ, g_Q);
    cudaGetSymbolAddress((void**)&pK, g_K);
    cudaGetSymbolAddress((void**)&pV, g_V);
    cudaGetSymbolAddress((void**)&pM, g_M);
    cudaGetSymbolAddress((void**)&pTop, g_top);
    cudaGetSymbolAddress((void**)&pS, g_S);
    cudaGetSymbolAddress((void**)&pUpd, g_upd);
    cudaGetSymbolAddress((void**)&pVm, g_vm);
    cudaGetSymbolAddress((void**)&pCtx, g_ctx);
    cudaGetSymbolAddress((void**)&pAo, g_ao);
    cudaGetSymbolAddress((void**)&pX1, g_x1);
    cudaGetSymbolAddress((void**)&pFF, g_ff);
    cudaGetSymbolAddress((void**)&pY2, g_y2);
    cudaGetSymbolAddress((void**)&pWT, g_WT);

    const int smemT = 3 * 32768;   // 98304
    cudaFuncSetAttribute(mma_gemm<0>, cudaFuncAttributeMaxDynamicSharedMemorySize, smemT);
    cudaFuncSetAttribute(mma_gemm<1>, cudaFuncAttributeMaxDynamicSharedMemorySize, smemT);
    cudaFuncSetAttribute(mma_gemm3,  cudaFuncAttributeMaxDynamicSharedMemorySize, smemT);

    float* WqT = pWT;
    float* WkT = pWT + DM * DM;
    float* WvT = pWT + 2 * DM * DM;
    float* WoT = pWT + 3 * DM * DM;
    dim3 tblk(32, 8), tgrid(DM / 32, DM / 32);
    transpose_kernel<<<tgrid, tblk>>>(Wq, WqT);
    transpose_kernel<<<tgrid, tblk>>>(Wk, WkT);
    transpose_kernel<<<tgrid, tblk>>>(Wv, WvT);
    transpose_kernel<<<tgrid, tblk>>>(Wo, WoT);

    dim3 gT512(DM / 128, ROWS / 128);    // (4, 64)
    dim3 gTff(DFF / 128, ROWS / 128);    // (16, 64)

    // Q,K via tf32x3 (near-fp32, top-k safe); V via 1-pass tf32
    mma_gemm3<<<gT512, 256, smemT>>>(x, WqT, pQ, ROWS, DM, DM);
    mma_gemm3<<<gT512, 256, smemT>>>(x, WkT, pK, ROWS, DM, DM);
    mma_gemm<0><<<gT512, 256, smemT>>>(x, WvT, nullptr, pV, ROWS, DM, DM);

    // sparse measure + top-k
    measure_kernel<<<BH * Ll / 4, 128>>>(pQ, pK, sidx, pM);
    topk_kernel<<<BH, 256>>>(pM, pTop);

    // mean-V context
    vmean_kernel<<<BH, 256>>>(pV, pVm);

    // reduced attention
    scores_kernel<<<dim3(Ll / 128, BH), 256>>>(pQ, pK, pTop, pS);
    softmax_kernel<<<BH * Uu, 256>>>(pS);
    upd_kernel<<<BH, 256>>>(pS, pV, pUpd);

    // context assembly + output projection (tf32)
    ctxfill_kernel<<<(ROWS * DM) / 256, 256>>>(pVm, pCtx);
    scatter_kernel<<<(BH * Uu * DK) / 256, 256>>>(pUpd, pTop, pCtx);
    mma_gemm<0><<<gT512, 256, smemT>>>(pCtx, WoT, nullptr, pAo, ROWS, DM, DM);

    // residual + LN1
    addln_kernel<<<ROWS, 256>>>(x, pAo, nullptr, ln1g, ln1b, pX1);

    // FFN (tf32; bias+GELU fused in GEMM1 epilogue)
    mma_gemm<1><<<gTff, 256, smemT>>>(pX1, w1, b1, pFF, ROWS, DFF, DM);
    mma_gemm<0><<<gT512, 256, smemT>>>(pFF, w2, nullptr, pY2, ROWS, DM, DFF);

    // residual + bias + LN2 -> output
    addln_kernel<<<ROWS, 256>>>(pX1, pY2, b2, ln2g, ln2b, out);
}

// round 5
// speedup vs baseline: 3.0018x; 1.2177x over previous
#include <cuda_runtime.h>
#include <cuda_fp16.h>
#include <math.h>
#include <stdint.h>

#define Bb 4
#define Ll 2048
#define DM 512
#define Hh 8
#define DK 64
#define DFF 2048
#define Uu 40
#define BH (Bb*Hh)
#define ROWS (Bb*Ll)

// ---------------- scratch (static device globals; allocation-free) ----------
__device__ float g_Q[ROWS*DM];
__device__ float g_K[ROWS*DM];
__device__ float g_V[ROWS*DM];
__device__ float g_M[BH*Ll];
__device__ int   g_top[BH*Uu];
__device__ float g_S[BH*Uu*Ll];
__device__ float g_upd[BH*Uu*DK];
__device__ float g_vm[BH*DK];
__device__ float g_ao[ROWS*DM];
__device__ float g_x1[ROWS*DM];
__device__ float g_y2[ROWS*DM];
__device__ __half g_xs[ROWS*DM*2];    // x split: [M][K/32][hi32|lo32]
__device__ __half g_xh[ROWS*DM];      // x fp16
__device__ __half g_x1h[ROWS*DM];     // x1 fp16
__device__ __half g_ctxh[ROWS*DM];    // ctx fp16
__device__ __half g_ffh[ROWS*DFF];    // FFN mid fp16
__device__ __half g_wqs[DM*DM*2];     // Wq^T split
__device__ __half g_wks[DM*DM*2];     // Wk^T split
__device__ __half g_wvh[DM*DM];       // Wv^T fp16
__device__ __half g_woh[DM*DM];       // Wo^T fp16
__device__ __half g_w1h[DFF*DM];
__device__ __half g_w2h[DM*DFF];

#define SWZ(b) ((b) ^ (((b) >> 3) & 0x70))

__device__ __forceinline__ uint32_t smem_u32(const void* p) {
    uint32_t a;
    asm("{ .reg .u64 t; cvta.to.shared.u64 t, %1; cvt.u32.u64 %0, t; }" : "=r"(a) : "l"(p));
    return a;
}
__device__ __forceinline__ void cp_async16(uint32_t s, const void* g) {
    asm volatile("cp.async.cg.shared.global [%0], [%1], 16;" :: "r"(s), "l"(g) : "memory");
}
__device__ __forceinline__ void ldsm_x4(uint32_t* r, uint32_t a) {
    asm volatile("ldmatrix.sync.aligned.m8n8.x4.shared.b16 {%0,%1,%2,%3}, [%4];"
                 : "=r"(r[0]), "=r"(r[1]), "=r"(r[2]), "=r"(r[3]) : "r"(a));
}
__device__ __forceinline__ void mma_f16(float* c, const uint32_t* a, uint32_t b0, uint32_t b1) {
    asm volatile("mma.sync.aligned.m16n8k16.row.col.f32.f16.f16.f32 "
                 "{%0,%1,%2,%3}, {%4,%5,%6,%7}, {%8,%9}, {%0,%1,%2,%3};"
                 : "+f"(c[0]), "+f"(c[1]), "+f"(c[2]), "+f"(c[3])
                 : "r"(a[0]), "r"(a[1]), "r"(a[2]), "r"(a[3]), "r"(b0), "r"(b1));
}
__device__ __forceinline__ float gelu_f(float v) {
    return 0.5f * v * (1.f + erff(v * 0.70710678118654752f));
}

// ============ fp16 mma GEMM (1-pass): C[M,N] = A[M,K] @ B^T, B [N,K] =======
// Block 128x128, BK=64, 256 threads (8 warps, warp 64x32), 3-stage cp.async.
// EPI: 0 plain, 1 bias+GELU.  OUTH: 0 fp32 C, 1 fp16 C.
template<int EPI, int OUTH>
__global__ void __launch_bounds__(256, 2) hgemm(
    const __half* __restrict__ A, const __half* __restrict__ Bw,
    const float* __restrict__ bias, void* __restrict__ Cv,
    int M, int N, int K)
{
    extern __shared__ char smem[];
    const uint32_t sbase = smem_u32(smem);
    const int tid = threadIdx.x, wid = tid >> 5, lane = tid & 31;
    const int m0 = blockIdx.y * 128, n0 = blockIdx.x * 128;
    const int wm0 = (wid & 1) * 64, wn0 = (wid >> 1) * 32;
    const int STG = 32768;
    const int KC = K >> 6;

    float acc[4][4][4];
#pragma unroll
    for (int i = 0; i < 4; i++)
#pragma unroll
        for (int j = 0; j < 4; j++)
#pragma unroll
            for (int r = 0; r < 4; r++) acc[i][j][r] = 0.f;

    auto load_stage = [&](int kc, int s) {
        const __half* Ap = A + (size_t)m0 * K + kc * 64;
        const __half* Bp = Bw + (size_t)n0 * K + kc * 64;
        uint32_t sa = sbase + s * STG;
        uint32_t sb = sa + 16384;
#pragma unroll
        for (int p = 0; p < 4; p++) {
            int idx = tid + p * 256;
            int r = idx >> 3, c = idx & 7;
            uint32_t so = SWZ((uint32_t)(r * 128 + c * 16));
            cp_async16(sa + so, Ap + (size_t)r * K + c * 8);
            cp_async16(sb + so, Bp + (size_t)r * K + c * 8);
        }
    };

    load_stage(0, 0);
    asm volatile("cp.async.commit_group;");
    if (KC > 1) load_stage(1, 1);
    asm volatile("cp.async.commit_group;");

    const int frow = lane & 15;
    const int fchk = (lane >> 4) * 16;

    for (int i = 0; i < KC; i++) {
        asm volatile("cp.async.wait_group 1;" ::: "memory");
        __syncthreads();
        if (i + 2 < KC) load_stage(i + 2, (i + 2) % 3);
        asm volatile("cp.async.commit_group;");

        uint32_t sa = sbase + (i % 3) * STG;
        uint32_t sb = sa + 16384;
#pragma unroll
        for (int s = 0; s < 4; s++) {             // k16-steps within BK=64
            uint32_t Bf[2][4];
#pragma unroll
            for (int p = 0; p < 2; p++)
                ldsm_x4(Bf[p], sb + SWZ((uint32_t)((wn0 + p * 16 + frow) * 128 + s * 32 + fchk)));
#pragma unroll
            for (int mt = 0; mt < 4; mt++) {
                uint32_t Af[4];
                ldsm_x4(Af, sa + SWZ((uint32_t)((wm0 + mt * 16 + frow) * 128 + s * 32 + fchk)));
#pragma unroll
                for (int nt = 0; nt < 4; nt++)
                    mma_f16(acc[mt][nt], Af, Bf[nt >> 1][nt & 1], Bf[nt >> 1][(nt & 1) + 2]);
            }
        }
        __syncthreads();
    }
    asm volatile("cp.async.wait_group 0;" ::: "memory");

    const int rbase = m0 + wm0 + (lane >> 2);
    const int cbase = n0 + wn0 + (lane & 3) * 2;
    float* Cf = (float*)Cv;
    __half* Ch = (__half*)Cv;
#pragma unroll
    for (int mt = 0; mt < 4; mt++) {
#pragma unroll
        for (int nt = 0; nt < 4; nt++) {
            int col = cbase + nt * 8;
            float v0 = acc[mt][nt][0], v1 = acc[mt][nt][1];
            float v2 = acc[mt][nt][2], v3 = acc[mt][nt][3];
            if (EPI == 1) {
                float b0 = bias[col], b1 = bias[col + 1];
                v0 = gelu_f(v0 + b0); v1 = gelu_f(v1 + b1);
                v2 = gelu_f(v2 + b0); v3 = gelu_f(v3 + b1);
            }
            size_t r0 = (size_t)(rbase + mt * 16) * N + col;
            size_t r1 = (size_t)(rbase + mt * 16 + 8) * N + col;
            if (OUTH) {
                *(__half2*)&Ch[r0] = __floats2half2_rn(v0, v1);
                *(__half2*)&Ch[r1] = __floats2half2_rn(v2, v3);
            } else {
                float2 p0; p0.x = v0; p0.y = v1;
                float2 p1; p1.x = v2; p1.y = v3;
                *(float2*)&Cf[r0] = p0;
                *(float2*)&Cf[r1] = p1;
            }
        }
    }
}

// ============ fp16x3 split GEMM (near-fp32; for Q,K) =======================
// A: [M][K/32][hi32|lo32] halves; B: [N][K/32][hi32|lo32] halves. C fp32.
__global__ void __launch_bounds__(256, 2) hgemm3(
    const __half* __restrict__ As, const __half* __restrict__ Bs,
    float* __restrict__ C, int M, int N, int K)
{
    extern __shared__ char smem[];
    const uint32_t sbase = smem_u32(smem);
    const int tid = threadIdx.x, wid = tid >> 5, lane = tid & 31;
    const int m0 = blockIdx.y * 128, n0 = blockIdx.x * 128;
    const int wm0 = (wid & 1) * 64, wn0 = (wid >> 1) * 32;
    const int STG = 32768;
    const int KC = K >> 5;            // stages of 32-k
    const int RS = K * 2;             // halves per row in split layout

    float acc[4][4][4];
#pragma unroll
    for (int i = 0; i < 4; i++)
#pragma unroll
        for (int j = 0; j < 4; j++)
#pragma unroll
            for (int r = 0; r < 4; r++) acc[i][j][r] = 0.f;

    auto load_stage = [&](int kc, int s) {
        const __half* Ap = As + (size_t)m0 * RS + kc * 64;
        const __half* Bp = Bs + (size_t)n0 * RS + kc * 64;
        uint32_t sa = sbase + s * STG;
        uint32_t sb = sa + 16384;
#pragma unroll
        for (int p = 0; p < 4; p++) {
            int idx = tid + p * 256;
            int r = idx >> 3, c = idx & 7;
            uint32_t so = SWZ((uint32_t)(r * 128 + c * 16));
            cp_async16(sa + so, Ap + (size_t)r * RS + c * 8);
            cp_async16(sb + so, Bp + (size_t)r * RS + c * 8);
        }
    };

    load_stage(0, 0);
    asm volatile("cp.async.commit_group;");
    if (KC > 1) load_stage(1, 1);
    asm volatile("cp.async.commit_group;");

    const int frow = lane & 15;
    const int fchk = (lane >> 4) * 16;

    for (int i = 0; i < KC; i++) {
        asm volatile("cp.async.wait_group 1;" ::: "memory");
        __syncthreads();
        if (i + 2 < KC) load_stage(i + 2, (i + 2) % 3);
        asm volatile("cp.async.commit_group;");

        uint32_t sa = sbase + (i % 3) * STG;
        uint32_t sb = sa + 16384;
#pragma unroll
        for (int s = 0; s < 2; s++) {          // k16-steps within 32-k chunk
            uint32_t Bh[2][4], Bl[2][4];
#pragma unroll
            for (int p = 0; p < 2; p++) {
                uint32_t rowoff = (uint32_t)((wn0 + p * 16 + frow) * 128 + s * 32 + fchk);
                ldsm_x4(Bh[p], sb + SWZ(rowoff));
                ldsm_x4(Bl[p], sb + SWZ(rowoff + 64));
            }
#pragma unroll
            for (int mt = 0; mt < 4; mt++) {
                uint32_t Ah[4], Al[4];
                uint32_t rowoff = (uint32_t)((wm0 + mt * 16 + frow) * 128 + s * 32 + fchk);
                ldsm_x4(Ah, sa + SWZ(rowoff));
                ldsm_x4(Al, sa + SWZ(rowoff + 64));
#pragma unroll
                for (int nt = 0; nt < 4; nt++) {
                    uint32_t bh0 = Bh[nt >> 1][nt & 1], bh1 = Bh[nt >> 1][(nt & 1) + 2];
                    uint32_t bl0 = Bl[nt >> 1][nt & 1], bl1 = Bl[nt >> 1][(nt & 1) + 2];
                    mma_f16(acc[mt][nt], Al, bh0, bh1);
                    mma_f16(acc[mt][nt], Ah, bl0, bl1);
                    mma_f16(acc[mt][nt], Ah, bh0, bh1);
                }
            }
        }
        __syncthreads();
    }
    asm volatile("cp.async.wait_group 0;" ::: "memory");

    const int rbase = m0 + wm0 + (lane >> 2);
    const int cbase = n0 + wn0 + (lane & 3) * 2;
#pragma unroll
    for (int mt = 0; mt < 4; mt++) {
#pragma unroll
        for (int nt = 0; nt < 4; nt++) {
            int col = cbase + nt * 8;
            float2 p0; p0.x = acc[mt][nt][0]; p0.y = acc[mt][nt][1];
            float2 p1; p1.x = acc[mt][nt][2]; p1.y = acc[mt][nt][3];
            *(float2*)&C[(size_t)(rbase + mt * 16) * N + col] = p0;
            *(float2*)&C[(size_t)(rbase + mt * 16 + 8) * N + col] = p1;
        }
    }
}

// ---------------- prep: x -> split + plain fp16 ----------------------------
__global__ void prep_x(const float* __restrict__ x, __half* __restrict__ xs,
                       __half* __restrict__ xh) {
    size_t i = ((size_t)blockIdx.x * 256 + threadIdx.x) * 4;
    int m = (int)(i / DM), k = (int)(i % DM);
    float4 v = *(const float4*)&x[i];
    __half h0 = __float2half_rn(v.x), h1 = __float2half_rn(v.y);
    __half h2 = __float2half_rn(v.z), h3 = __float2half_rn(v.w);
    __half l0 = __float2half_rn(v.x - __half2float(h0));
    __half l1 = __float2half_rn(v.y - __half2float(h1));
    __half l2 = __float2half_rn(v.z - __half2float(h2));
    __half l3 = __float2half_rn(v.w - __half2float(h3));
    xh[i] = h0; xh[i + 1] = h1; xh[i + 2] = h2; xh[i + 3] = h3;
    size_t o = (size_t)m * (DM * 2) + (k >> 5) * 64 + (k & 31);
    xs[o] = h0; xs[o + 1] = h1; xs[o + 2] = h2; xs[o + 3] = h3;
    xs[o + 32] = l0; xs[o + 33] = l1; xs[o + 34] = l2; xs[o + 35] = l3;
}

// ---------------- prep: W [K,N] -> split-transposed [N][K/32][hi|lo] --------
__global__ void prep_wsplit(const float* __restrict__ W, __half* __restrict__ o) {
    __shared__ float t[32][33];
    int bx = blockIdx.x * 32, by = blockIdx.y * 32;   // bx: n0, by: k0
    int tx = threadIdx.x;
    for (int i = threadIdx.y; i < 32; i += 8)
        t[i][tx] = W[(size_t)(by + i) * DM + bx + tx];
    __syncthreads();
    for (int i = threadIdx.y; i < 32; i += 8) {
        int n = bx + i;
        float v = t[tx][i];               // = W[by+tx][n]
        __half h = __float2half_rn(v);
        __half l = __float2half_rn(v - __half2float(h));
        size_t off = (size_t)n * (DM * 2) + (by >> 5) * 64 + tx;
        o[off] = h; o[off + 32] = l;
    }
}

// ---------------- prep: W [K,N] -> fp16 transposed [N,K] --------------------
__global__ void prep_wT(const float* __restrict__ W, __half* __restrict__ o) {
    __shared__ float t[32][33];
    int bx = blockIdx.x * 32, by = blockIdx.y * 32;
    int tx = threadIdx.x;
    for (int i = threadIdx.y; i < 32; i += 8)
        t[i][tx] = W[(size_t)(by + i) * DM + bx + tx];
    __syncthreads();
    for (int i = threadIdx.y; i < 32; i += 8)
        o[(size_t)(bx + i) * DM + by + tx] = __float2half_rn(t[tx][i]);
}

// ---------------- prep: flat fp32 -> fp16 ----------------------------------
__global__ void prep_cvt(const float* __restrict__ w, __half* __restrict__ o) {
    size_t i = ((size_t)blockIdx.x * 256 + threadIdx.x) * 4;
    float4 v = *(const float4*)&w[i];
    __half2 a = __floats2half2_rn(v.x, v.y);
    __half2 b = __floats2half2_rn(v.z, v.w);
    *(__half2*)&o[i] = a;
    *(__half2*)&o[i + 2] = b;
}

// ---------------- sampled QK measure (ILP-2) --------------------------------
__global__ void measure_kernel(const float* __restrict__ Q,
                               const float* __restrict__ K,
                               const int* __restrict__ sidx,
                               float* __restrict__ Mout) {
    int gw = blockIdx.x * 4 + (threadIdx.x >> 5);
    int lane = threadIdx.x & 31;
    int l = gw % Ll;
    int bh = gw / Ll;
    int b = bh / Hh, h = bh % Hh;
    const float* q = Q + ((size_t)(b * Ll + l)) * DM + h * DK;
    float q0 = q[lane], q1 = q[lane + 32];
    const float* Kb = K + (size_t)b * Ll * DM + h * DK;
    float mx = -1e30f, sum = 0.f;
#pragma unroll 4
    for (int s = 0; s < Uu; s += 2) {
        int2 jj = *(const int2*)&sidx[l * Uu + s];
        const float* k0 = Kb + (size_t)jj.x * DM;
        const float* k1 = Kb + (size_t)jj.y * DM;
        float p0 = q0 * __ldg(k0 + lane) + q1 * __ldg(k0 + lane + 32);
        float p1 = q0 * __ldg(k1 + lane) + q1 * __ldg(k1 + lane + 32);
#pragma unroll
        for (int o = 16; o; o >>= 1) {
            p0 += __shfl_xor_sync(0xffffffffu, p0, o);
            p1 += __shfl_xor_sync(0xffffffffu, p1, o);
        }
        mx = fmaxf(mx, fmaxf(p0, p1));
        sum += p0 + p1;
    }
    if (lane == 0) Mout[bh * Ll + l] = mx - sum / (float)Ll;
}

// ---------------- top-40 per (b,h) -----------------------------------------
__global__ void topk_kernel(const float* __restrict__ Mv, int* __restrict__ top) {
    int bh = blockIdx.x;
    int t = threadIdx.x;
    __shared__ float vals[Ll];
    __shared__ float rv[256];
    __shared__ int   ri[256];
    for (int i = t; i < Ll; i += 256) vals[i] = Mv[bh * Ll + i];
    __syncthreads();
    for (int k = 0; k < Uu; k++) {
        float bv = -1e30f; int bi = Ll;
        for (int i = t; i < Ll; i += 256) {
            float v = vals[i];
            if (v > bv) { bv = v; bi = i; }
        }
        rv[t] = bv; ri[t] = bi;
        __syncthreads();
        for (int s = 128; s; s >>= 1) {
            if (t < s) {
                if (rv[t + s] > rv[t] || (rv[t + s] == rv[t] && ri[t + s] < ri[t])) {
                    rv[t] = rv[t + s]; ri[t] = ri[t + s];
                }
            }
            __syncthreads();
        }
        if (t == 0) { top[bh * Uu + k] = ri[0]; vals[ri[0]] = -1e30f; }
        __syncthreads();
    }
}

// ---------------- V mean ----------------------------------------------------
__global__ void vmean_kernel(const float* __restrict__ V, float* __restrict__ vm) {
    int bh = blockIdx.x;
    int b = bh / Hh, h = bh % Hh;
    int t = threadIdx.x;
    int d = t & 63;
    int c = t >> 6;
    __shared__ float red[256];
    float s = 0.f;
    for (int l = c * (Ll / 4); l < (c + 1) * (Ll / 4); l++)
        s += V[((size_t)(b * Ll + l)) * DM + h * DK + d];
    red[t] = s;
    __syncthreads();
    if (c == 0) vm[bh * DK + d] = (red[d] + red[d + 64] + red[d + 128] + red[d + 192]) / (float)Ll;
}

// ---------------- scores = Q_red @ K^T / 8 ---------------------------------
__global__ void scores_kernel(const float* __restrict__ Q,
                              const float* __restrict__ K,
                              const int* __restrict__ top,
                              float* __restrict__ S) {
    int bh = blockIdx.y;
    int b = bh / Hh, h = bh % Hh;
    int l0 = blockIdx.x * 128;
    int t = threadIdx.x;
    __shared__ float Qs[Uu][DK];
    __shared__ float Ks[128][DK + 1];
    for (int idx = t; idx < Uu * DK; idx += 256) {
        int u = idx / DK, d = idx % DK;
        Qs[u][d] = Q[((size_t)(b * Ll + top[bh * Uu + u])) * DM + h * DK + d];
    }
    for (int idx = t; idx < 128 * DK; idx += 256) {
        int i = idx >> 6, d = idx & 63;
        Ks[i][d] = K[((size_t)(b * Ll + l0 + i)) * DM + h * DK + d];
    }
    __syncthreads();
    for (int idx = t; idx < Uu * 128; idx += 256) {
        int u = idx >> 7, i = idx & 127;
        float s = 0.f;
#pragma unroll
        for (int d = 0; d < DK; d++) s += Qs[u][d] * Ks[i][d];
        S[((size_t)(bh * Uu + u)) * Ll + l0 + i] = s * 0.125f;
    }
}

// ---------------- row softmax ----------------------------------------------
__global__ void softmax_kernel(float* __restrict__ S) {
    int row = blockIdx.x;
    int t = threadIdx.x;
    float* p = S + (size_t)row * Ll;
    __shared__ float red[256];
    float mx = -1e30f;
    for (int i = t; i < Ll; i += 256) mx = fmaxf(mx, p[i]);
    red[t] = mx; __syncthreads();
    for (int s = 128; s; s >>= 1) { if (t < s) red[t] = fmaxf(red[t], red[t + s]); __syncthreads(); }
    mx = red[0]; __syncthreads();
    float sum = 0.f;
    for (int i = t; i < Ll; i += 256) { float e = expf(p[i] - mx); p[i] = e; sum += e; }
    red[t] = sum; __syncthreads();
    for (int s = 128; s; s >>= 1) { if (t < s) red[t] += red[t + s]; __syncthreads(); }
    float inv = 1.f / red[0];
    for (int i = t; i < Ll; i += 256) p[i] *= inv;
}

// ---------------- upd = attn @ V -------------------------------------------
__global__ void upd_kernel(const float* __restrict__ S,
                           const float* __restrict__ V,
                           float* __restrict__ upd) {
    int bh = blockIdx.x;
    int b = bh / Hh, h = bh % Hh;
    int t = threadIdx.x;
    __shared__ float Vs[64][DK + 1];
    __shared__ float As[Uu][64];
    int d = t & 63;
    int u0 = t >> 6;
    float acc[10];
#pragma unroll
    for (int o = 0; o < 10; o++) acc[o] = 0.f;

    for (int l0 = 0; l0 < Ll; l0 += 64) {
        for (int idx = t; idx < 64 * DK; idx += 256) {
            int i = idx >> 6, dd = idx & 63;
            Vs[i][dd] = V[((size_t)(b * Ll + l0 + i)) * DM + h * DK + dd];
        }
        for (int idx = t; idx < Uu * 64; idx += 256) {
            int u = idx >> 6, i = idx & 63;
            As[u][i] = S[((size_t)(bh * Uu + u)) * Ll + l0 + i];
        }
        __syncthreads();
#pragma unroll 8
        for (int i = 0; i < 64; i++) {
            float vv = Vs[i][d];
#pragma unroll
            for (int o = 0; o < 10; o++) acc[o] += As[u0 + 4 * o][i] * vv;
        }
        __syncthreads();
    }
#pragma unroll
    for (int o = 0; o < 10; o++) {
        int u = u0 + 4 * o;
        upd[((size_t)bh * Uu + u) * DK + d] = acc[o];
    }
}

// ---------------- ctx fill + scatter (fp16 ctx) ----------------------------
__global__ void ctxfill_kernel(const float* __restrict__ vm, __half* __restrict__ ctx) {
    size_t i = (size_t)blockIdx.x * 256 + threadIdx.x;
    int col = (int)(i % DM);
    int b = (int)(i / ((size_t)Ll * DM));
    ctx[i] = __float2half_rn(vm[(b * Hh + (col >> 6)) * DK + (col & 63)]);
}

__global__ void scatter_kernel(const float* __restrict__ upd,
                               const int* __restrict__ top,
                               __half* __restrict__ ctx) {
    int i = blockIdx.x * 256 + threadIdx.x;
    int d = i & 63;
    int u = (i >> 6) % Uu;
    int bh = i / (DK * Uu);
    int b = bh / Hh, h = bh % Hh;
    int l = top[bh * Uu + u];
    ctx[((size_t)(b * Ll + l)) * DM + h * DK + d] = __float2half_rn(upd[i]);
}

// ---------------- residual (+bias) + LayerNorm (optional fp16 copy) --------
__global__ void addln_kernel(const float* __restrict__ A,
                             const float* __restrict__ R,
                             const float* __restrict__ bias,
                             const float* __restrict__ gamma,
                             const float* __restrict__ beta,
                             float* __restrict__ out,
                             __half* __restrict__ outh) {
    int row = blockIdx.x;
    int t = threadIdx.x;
    __shared__ float red[256];
    size_t base = (size_t)row * DM;
    float v0 = A[base + t] + R[base + t];
    float v1 = A[base + t + 256] + R[base + t + 256];
    if (bias) { v0 += bias[t]; v1 += bias[t + 256]; }
    red[t] = v0 + v1; __syncthreads();
    for (int s = 128; s; s >>= 1) { if (t < s) red[t] += red[t + s]; __syncthreads(); }
    float mean = red[0] / (float)DM; __syncthreads();
    float d0 = v0 - mean, d1 = v1 - mean;
    red[t] = d0 * d0 + d1 * d1; __syncthreads();
    for (int s = 128; s; s >>= 1) { if (t < s) red[t] += red[t + s]; __syncthreads(); }
    float inv = rsqrtf(red[0] / (float)DM + 1e-5f);
    float o0 = d0 * inv * gamma[t] + beta[t];
    float o1 = d1 * inv * gamma[t + 256] + beta[t + 256];
    out[base + t] = o0;
    out[base + t + 256] = o1;
    if (outh) {
        outh[base + t] = __float2half_rn(o0);
        outh[base + t + 256] = __float2half_rn(o1);
    }
}

// ---------------- host orchestration ---------------------------------------
extern "C" void kernel_launch(void* const* d_in, const int* in_sizes, int n_in,
                              void* d_out, int out_size) {
    const float* x    = (const float*)d_in[0];
    const float* Wq   = (const float*)d_in[1];
    const float* Wk   = (const float*)d_in[2];
    const float* Wv   = (const float*)d_in[3];
    const float* Wo   = (const float*)d_in[4];
    const float* ln1g = (const float*)d_in[5];
    const float* ln1b = (const float*)d_in[6];
    const float* w1   = (const float*)d_in[7];   // [DFF, DM] = [N,K]
    const float* b1   = (const float*)d_in[8];
    const float* w2   = (const float*)d_in[9];   // [DM, DFF] = [N,K]
    const float* b2   = (const float*)d_in[10];
    const float* ln2g = (const float*)d_in[11];
    const float* ln2b = (const float*)d_in[12];
    const int*   sidx = (const int*)d_in[13];
    float* out = (float*)d_out;

    float *pQ, *pK, *pV, *pM, *pS, *pUpd, *pVm, *pAo, *pX1, *pY2;
    __half *pXs, *pXh, *pX1h, *pCtxh, *pFFh, *pWqs, *pWks, *pWvh, *pWoh, *pW1h, *pW2h;
    int *pTop;
    cudaGetSymbolAddress((void**)&pQ, g_Q);
    cudaGetSymbolAddress((void**)&pK, g_K);
    cudaGetSymbolAddress((void**)&pV, g_V);
    cudaGetSymbolAddress((void**)&pM, g_M);
    cudaGetSymbolAddress((void**)&pTop, g_top);
    cudaGetSymbolAddress((void**)&pS, g_S);
    cudaGetSymbolAddress((void**)&pUpd, g_upd);
    cudaGetSymbolAddress((void**)&pVm, g_vm);
    cudaGetSymbolAddress((void**)&pAo, g_ao);
    cudaGetSymbolAddress((void**)&pX1, g_x1);
    cudaGetSymbolAddress((void**)&pY2, g_y2);
    cudaGetSymbolAddress((void**)&pXs, g_xs);
    cudaGetSymbolAddress((void**)&pXh, g_xh);
    cudaGetSymbolAddress((void**)&pX1h, g_x1h);
    cudaGetSymbolAddress((void**)&pCtxh, g_ctxh);
    cudaGetSymbolAddress((void**)&pFFh, g_ffh);
    cudaGetSymbolAddress((void**)&pWqs, g_wqs);
    cudaGetSymbolAddress((void**)&pWks, g_wks);
    cudaGetSymbolAddress((void**)&pWvh, g_wvh);
    cudaGetSymbolAddress((void**)&pWoh, g_woh);
    cudaGetSymbolAddress((void**)&pW1h, g_w1h);
    cudaGetSymbolAddress((void**)&pW2h, g_w2h);

    const int smemT = 3 * 32768;   // 98304
    cudaFuncSetAttribute(hgemm<0,0>, cudaFuncAttributeMaxDynamicSharedMemorySize, smemT);
    cudaFuncSetAttribute(hgemm<1,1>, cudaFuncAttributeMaxDynamicSharedMemorySize, smemT);
    cudaFuncSetAttribute(hgemm3,     cudaFuncAttributeMaxDynamicSharedMemorySize, smemT);

    // ---- prep (convert / transpose / split) ----
    dim3 tblk(32, 8), tgrid(DM / 32, DM / 32);
    prep_x<<<ROWS * DM / 4 / 256, 256>>>(x, pXs, pXh);
    prep_wsplit<<<tgrid, tblk>>>(Wq, pWqs);
    prep_wsplit<<<tgrid, tblk>>>(Wk, pWks);
    prep_wT<<<tgrid, tblk>>>(Wv, pWvh);
    prep_wT<<<tgrid, tblk>>>(Wo, pWoh);
    prep_cvt<<<DFF * DM / 4 / 256, 256>>>(w1, pW1h);
    prep_cvt<<<DM * DFF / 4 / 256, 256>>>(w2, pW2h);

    dim3 gT512(DM / 128, ROWS / 128);    // (4, 64)
    dim3 gTff(DFF / 128, ROWS / 128);    // (16, 64)

    // Q,K via fp16x3 split (near-fp32, top-k safe); V via 1-pass fp16
    hgemm3<<<gT512, 256, smemT>>>(pXs, pWqs, pQ, ROWS, DM, DM);
    hgemm3<<<gT512, 256, smemT>>>(pXs, pWks, pK, ROWS, DM, DM);
    hgemm<0,0><<<gT512, 256, smemT>>>(pXh, pWvh, nullptr, pV, ROWS, DM, DM);

    // sparse measure + top-k
    measure_kernel<<<BH * Ll / 4, 128>>>(pQ, pK, sidx, pM);
    topk_kernel<<<BH, 256>>>(pM, pTop);

    // mean-V context
    vmean_kernel<<<BH, 256>>>(pV, pVm);

    // reduced attention
    scores_kernel<<<dim3(Ll / 128, BH), 256>>>(pQ, pK, pTop, pS);
    softmax_kernel<<<BH * Uu, 256>>>(pS);
    upd_kernel<<<BH, 256>>>(pS, pV, pUpd);

    // context assembly (fp16) + output projection
    ctxfill_kernel<<<(ROWS * DM) / 256, 256>>>(pVm, pCtxh);
    scatter_kernel<<<(BH * Uu * DK) / 256, 256>>>(pUpd, pTop, pCtxh);
    hgemm<0,0><<<gT512, 256, smemT>>>(pCtxh, pWoh, nullptr, pAo, ROWS, DM, DM);

    // residual + LN1 (fp32 + fp16 copy for FFN)
    addln_kernel<<<ROWS, 256>>>(x, pAo, nullptr, ln1g, ln1b, pX1, pX1h);

    // FFN (fp16; bias+GELU fused, fp16 intermediate)
    hgemm<1,1><<<gTff, 256, smemT>>>(pX1h, pW1h, b1, pFFh, ROWS, DFF, DM);
    hgemm<0,0><<<gT512, 256, smemT>>>(pFFh, pW2h, nullptr, pY2, ROWS, DM, DFF);

    // residual + bias + LN2 -> output
    addln_kernel<<<ROWS, 256>>>(pX1, pY2, b2, ln2g, ln2b, out, nullptr);
}

// round 6
// speedup vs baseline: 3.8533x; 1.2837x over previous
#include <cuda_runtime.h>
#include <cuda_fp16.h>
#include <math.h>
#include <stdint.h>

#define Bb 4
#define Ll 2048
#define DM 512
#define Hh 8
#define DK 64
#define DFF 2048
#define Uu 40
#define BH (Bb*Hh)
#define ROWS (Bb*Ll)
#define UPDN (BH*Uu*DK)

// ---------------- scratch (static device globals; allocation-free) ----------
__device__ float g_QK[ROWS*1024];     // Q (cols 0-511) | K (cols 512-1023)
__device__ float g_V[ROWS*DM];
__device__ float g_M[BH*Ll];
__device__ int   g_top[BH*Uu];
__device__ int   g_map[BH*Ll];
__device__ float g_S[BH*Uu*Ll];
__device__ float g_upd[UPDN];
__device__ float g_upart[8*UPDN];
__device__ float g_vm[BH*DK];
__device__ float g_vpart[8*BH*DK];
__device__ float g_ao[ROWS*DM];
__device__ float g_x1[ROWS*DM];
__device__ float g_y2[ROWS*DM];
__device__ __half g_xs[ROWS*DM*2];    // x split: [M][K/32][hi32|lo32]
__device__ __half g_xh[ROWS*DM];      // x fp16
__device__ __half g_x1h[ROWS*DM];     // x1 fp16
__device__ __half g_ctxh[ROWS*DM];    // ctx fp16
__device__ __half g_ffh[ROWS*DFF];    // FFN mid fp16
__device__ __half g_wqks[1024*DM*2];  // [Wq^T;Wk^T] split
__device__ __half g_wvh[DM*DM];       // Wv^T fp16
__device__ __half g_woh[DM*DM];       // Wo^T fp16
__device__ __half g_w1h[DFF*DM];
__device__ __half g_w2h[DM*DFF];

#define SWZ(b) ((b) ^ (((b) >> 3) & 0x70))

__device__ __forceinline__ uint32_t smem_u32(const void* p) {
    uint32_t a;
    asm("{ .reg .u64 t; cvta.to.shared.u64 t, %1; cvt.u32.u64 %0, t; }" : "=r"(a) : "l"(p));
    return a;
}
__device__ __forceinline__ void cp_async16(uint32_t s, const void* g) {
    asm volatile("cp.async.cg.shared.global [%0], [%1], 16;" :: "r"(s), "l"(g) : "memory");
}
__device__ __forceinline__ void ldsm_x4(uint32_t* r, uint32_t a) {
    asm volatile("ldmatrix.sync.aligned.m8n8.x4.shared.b16 {%0,%1,%2,%3}, [%4];"
                 : "=r"(r[0]), "=r"(r[1]), "=r"(r[2]), "=r"(r[3]) : "r"(a));
}
__device__ __forceinline__ void mma_f16(float* c, const uint32_t* a, uint32_t b0, uint32_t b1) {
    asm volatile("mma.sync.aligned.m16n8k16.row.col.f32.f16.f16.f32 "
                 "{%0,%1,%2,%3}, {%4,%5,%6,%7}, {%8,%9}, {%0,%1,%2,%3};"
                 : "+f"(c[0]), "+f"(c[1]), "+f"(c[2]), "+f"(c[3])
                 : "r"(a[0]), "r"(a[1]), "r"(a[2]), "r"(a[3]), "r"(b0), "r"(b1));
}
__device__ __forceinline__ float gelu_f(float v) {
    return 0.5f * v * (1.f + erff(v * 0.70710678118654752f));
}

// ============ fp16 mma GEMM (1-pass): C[M,N] = A[M,K] @ B^T, B [N,K] =======
template<int EPI, int OUTH>
__global__ void __launch_bounds__(256, 2) hgemm(
    const __half* __restrict__ A, const __half* __restrict__ Bw,
    const float* __restrict__ bias, void* __restrict__ Cv,
    int M, int N, int K)
{
    extern __shared__ char smem[];
    const uint32_t sbase = smem_u32(smem);
    const int tid = threadIdx.x, wid = tid >> 5, lane = tid & 31;
    const int m0 = blockIdx.y * 128, n0 = blockIdx.x * 128;
    const int wm0 = (wid & 1) * 64, wn0 = (wid >> 1) * 32;
    const int STG = 32768;
    const int KC = K >> 6;

    float acc[4][4][4];
#pragma unroll
    for (int i = 0; i < 4; i++)
#pragma unroll
        for (int j = 0; j < 4; j++)
#pragma unroll
            for (int r = 0; r < 4; r++) acc[i][j][r] = 0.f;

    auto load_stage = [&](int kc, int s) {
        const __half* Ap = A + (size_t)m0 * K + kc * 64;
        const __half* Bp = Bw + (size_t)n0 * K + kc * 64;
        uint32_t sa = sbase + s * STG;
        uint32_t sb = sa + 16384;
#pragma unroll
        for (int p = 0; p < 4; p++) {
            int idx = tid + p * 256;
            int r = idx >> 3, c = idx & 7;
            uint32_t so = SWZ((uint32_t)(r * 128 + c * 16));
            cp_async16(sa + so, Ap + (size_t)r * K + c * 8);
            cp_async16(sb + so, Bp + (size_t)r * K + c * 8);
        }
    };

    load_stage(0, 0);
    asm volatile("cp.async.commit_group;");
    if (KC > 1) load_stage(1, 1);
    asm volatile("cp.async.commit_group;");

    const int frow = lane & 15;
    const int fchk = (lane >> 4) * 16;

    for (int i = 0; i < KC; i++) {
        asm volatile("cp.async.wait_group 1;" ::: "memory");
        __syncthreads();
        if (i + 2 < KC) load_stage(i + 2, (i + 2) % 3);
        asm volatile("cp.async.commit_group;");

        uint32_t sa = sbase + (i % 3) * STG;
        uint32_t sb = sa + 16384;
#pragma unroll
        for (int s = 0; s < 4; s++) {
            uint32_t Bf[2][4];
#pragma unroll
            for (int p = 0; p < 2; p++)
                ldsm_x4(Bf[p], sb + SWZ((uint32_t)((wn0 + p * 16 + frow) * 128 + s * 32 + fchk)));
#pragma unroll
            for (int mt = 0; mt < 4; mt++) {
                uint32_t Af[4];
                ldsm_x4(Af, sa + SWZ((uint32_t)((wm0 + mt * 16 + frow) * 128 + s * 32 + fchk)));
#pragma unroll
                for (int nt = 0; nt < 4; nt++)
                    mma_f16(acc[mt][nt], Af, Bf[nt >> 1][nt & 1], Bf[nt >> 1][(nt & 1) + 2]);
            }
        }
        __syncthreads();
    }
    asm volatile("cp.async.wait_group 0;" ::: "memory");

    const int rbase = m0 + wm0 + (lane >> 2);
    const int cbase = n0 + wn0 + (lane & 3) * 2;
    float* Cf = (float*)Cv;
    __half* Ch = (__half*)Cv;
#pragma unroll
    for (int mt = 0; mt < 4; mt++) {
#pragma unroll
        for (int nt = 0; nt < 4; nt++) {
            int col = cbase + nt * 8;
            float v0 = acc[mt][nt][0], v1 = acc[mt][nt][1];
            float v2 = acc[mt][nt][2], v3 = acc[mt][nt][3];
            if (EPI == 1) {
                float b0 = bias[col], b1 = bias[col + 1];
                v0 = gelu_f(v0 + b0); v1 = gelu_f(v1 + b1);
                v2 = gelu_f(v2 + b0); v3 = gelu_f(v3 + b1);
            }
            size_t r0 = (size_t)(rbase + mt * 16) * N + col;
            size_t r1 = (size_t)(rbase + mt * 16 + 8) * N + col;
            if (OUTH) {
                *(__half2*)&Ch[r0] = __floats2half2_rn(v0, v1);
                *(__half2*)&Ch[r1] = __floats2half2_rn(v2, v3);
            } else {
                float2 p0; p0.x = v0; p0.y = v1;
                float2 p1; p1.x = v2; p1.y = v3;
                *(float2*)&Cf[r0] = p0;
                *(float2*)&Cf[r1] = p1;
            }
        }
    }
}

// ============ fp16x3 split GEMM (near-fp32; for Q|K merged) ================
__global__ void __launch_bounds__(256, 2) hgemm3(
    const __half* __restrict__ As, const __half* __restrict__ Bs,
    float* __restrict__ C, int M, int N, int K)
{
    extern __shared__ char smem[];
    const uint32_t sbase = smem_u32(smem);
    const int tid = threadIdx.x, wid = tid >> 5, lane = tid & 31;
    const int m0 = blockIdx.y * 128, n0 = blockIdx.x * 128;
    const int wm0 = (wid & 1) * 64, wn0 = (wid >> 1) * 32;
    const int STG = 32768;
    const int KC = K >> 5;
    const int RS = K * 2;

    float acc[4][4][4];
#pragma unroll
    for (int i = 0; i < 4; i++)
#pragma unroll
        for (int j = 0; j < 4; j++)
#pragma unroll
            for (int r = 0; r < 4; r++) acc[i][j][r] = 0.f;

    auto load_stage = [&](int kc, int s) {
        const __half* Ap = As + (size_t)m0 * RS + kc * 64;
        const __half* Bp = Bs + (size_t)n0 * RS + kc * 64;
        uint32_t sa = sbase + s * STG;
        uint32_t sb = sa + 16384;
#pragma unroll
        for (int p = 0; p < 4; p++) {
            int idx = tid + p * 256;
            int r = idx >> 3, c = idx & 7;
            uint32_t so = SWZ((uint32_t)(r * 128 + c * 16));
            cp_async16(sa + so, Ap + (size_t)r * RS + c * 8);
            cp_async16(sb + so, Bp + (size_t)r * RS + c * 8);
        }
    };

    load_stage(0, 0);
    asm volatile("cp.async.commit_group;");
    if (KC > 1) load_stage(1, 1);
    asm volatile("cp.async.commit_group;");

    const int frow = lane & 15;
    const int fchk = (lane >> 4) * 16;

    for (int i = 0; i < KC; i++) {
        asm volatile("cp.async.wait_group 1;" ::: "memory");
        __syncthreads();
        if (i + 2 < KC) load_stage(i + 2, (i + 2) % 3);
        asm volatile("cp.async.commit_group;");

        uint32_t sa = sbase + (i % 3) * STG;
        uint32_t sb = sa + 16384;
#pragma unroll
        for (int s = 0; s < 2; s++) {
            uint32_t Bh[2][4], Bl[2][4];
#pragma unroll
            for (int p = 0; p < 2; p++) {
                uint32_t rowoff = (uint32_t)((wn0 + p * 16 + frow) * 128 + s * 32 + fchk);
                ldsm_x4(Bh[p], sb + SWZ(rowoff));
                ldsm_x4(Bl[p], sb + SWZ(rowoff + 64));
            }
#pragma unroll
            for (int mt = 0; mt < 4; mt++) {
                uint32_t Ah[4], Al[4];
                uint32_t rowoff = (uint32_t)((wm0 + mt * 16 + frow) * 128 + s * 32 + fchk);
                ldsm_x4(Ah, sa + SWZ(rowoff));
                ldsm_x4(Al, sa + SWZ(rowoff + 64));
#pragma unroll
                for (int nt = 0; nt < 4; nt++) {
                    uint32_t bh0 = Bh[nt >> 1][nt & 1], bh1 = Bh[nt >> 1][(nt & 1) + 2];
                    uint32_t bl0 = Bl[nt >> 1][nt & 1], bl1 = Bl[nt >> 1][(nt & 1) + 2];
                    mma_f16(acc[mt][nt], Al, bh0, bh1);
                    mma_f16(acc[mt][nt], Ah, bl0, bl1);
                    mma_f16(acc[mt][nt], Ah, bh0, bh1);
                }
            }
        }
        __syncthreads();
    }
    asm volatile("cp.async.wait_group 0;" ::: "memory");

    const int rbase = m0 + wm0 + (lane >> 2);
    const int cbase = n0 + wn0 + (lane & 3) * 2;
#pragma unroll
    for (int mt = 0; mt < 4; mt++) {
#pragma unroll
        for (int nt = 0; nt < 4; nt++) {
            int col = cbase + nt * 8;
            float2 p0; p0.x = acc[mt][nt][0]; p0.y = acc[mt][nt][1];
            float2 p1; p1.x = acc[mt][nt][2]; p1.y = acc[mt][nt][3];
            *(float2*)&C[(size_t)(rbase + mt * 16) * N + col] = p0;
            *(float2*)&C[(size_t)(rbase + mt * 16 + 8) * N + col] = p1;
        }
    }
}

// ---------------- prep: x -> split + plain fp16 ----------------------------
__global__ void prep_x(const float* __restrict__ x, __half* __restrict__ xs,
                       __half* __restrict__ xh) {
    size_t i = ((size_t)blockIdx.x * 256 + threadIdx.x) * 4;
    int m = (int)(i / DM), k = (int)(i % DM);
    float4 v = *(const float4*)&x[i];
    __half h0 = __float2half_rn(v.x), h1 = __float2half_rn(v.y);
    __half h2 = __float2half_rn(v.z), h3 = __float2half_rn(v.w);
    __half l0 = __float2half_rn(v.x - __half2float(h0));
    __half l1 = __float2half_rn(v.y - __half2float(h1));
    __half l2 = __float2half_rn(v.z - __half2float(h2));
    __half l3 = __float2half_rn(v.w - __half2float(h3));
    xh[i] = h0; xh[i + 1] = h1; xh[i + 2] = h2; xh[i + 3] = h3;
    size_t o = (size_t)m * (DM * 2) + (k >> 5) * 64 + (k & 31);
    xs[o] = h0; xs[o + 1] = h1; xs[o + 2] = h2; xs[o + 3] = h3;
    xs[o + 32] = l0; xs[o + 33] = l1; xs[o + 34] = l2; xs[o + 35] = l3;
}

// ---------------- mega weight prep -----------------------------------------
// blocks [0,256) Wq split | [256,512) Wk split | [512,768) Wv T | [768,1024) Wo T
// [1024,2048) w1 cvt | [2048,3072) w2 cvt
__global__ void prep_w(const float* __restrict__ Wq, const float* __restrict__ Wk,
                       const float* __restrict__ Wv, const float* __restrict__ Wo,
                       const float* __restrict__ w1, const float* __restrict__ w2,
                       __half* __restrict__ wqks, __half* __restrict__ wvh,
                       __half* __restrict__ woh, __half* __restrict__ w1h,
                       __half* __restrict__ w2h) {
    int blk = blockIdx.x;
    int tx = threadIdx.x, ty = threadIdx.y;
    if (blk < 1024) {
        int region = blk >> 8;
        int tile = blk & 255;
        int bx = (tile & 15) * 32, by = (tile >> 4) * 32;
        const float* W = region == 0 ? Wq : region == 1 ? Wk : region == 2 ? Wv : Wo;
        __shared__ float tbuf[32][33];
        for (int i = ty; i < 32; i += 8)
            tbuf[i][tx] = W[(size_t)(by + i) * DM + bx + tx];
        __syncthreads();
        if (region < 2) {
            int roff = region * 512;
            for (int i = ty; i < 32; i += 8) {
                int n = bx + i;
                float v = tbuf[tx][i];
                __half hh = __float2half_rn(v);
                __half lo = __float2half_rn(v - __half2float(hh));
                size_t off = (size_t)(roff + n) * (DM * 2) + (by >> 5) * 64 + tx;
                wqks[off] = hh; wqks[off + 32] = lo;
            }
        } else {
            __half* o = (region == 2) ? wvh : woh;
            for (int i = ty; i < 32; i += 8)
                o[(size_t)(bx + i) * DM + by + tx] = __float2half_rn(tbuf[tx][i]);
        }
    } else {
        int t = ty * 32 + tx;
        const float* src = (blk < 2048) ? w1 : w2;
        __half* dst = (blk < 2048) ? w1h : w2h;
        size_t i = ((size_t)((blk - 1024) & 1023)) * 1024 + t * 4;
        float4 v = *(const float4*)&src[i];
        *(__half2*)&dst[i] = __floats2half2_rn(v.x, v.y);
        *(__half2*)&dst[i + 2] = __floats2half2_rn(v.z, v.w);
    }
}

// ---------------- sampled QK measure (ILP-2, merged QK buffer) -------------
__global__ void measure_kernel(const float* __restrict__ QK,
                               const int* __restrict__ sidx,
                               float* __restrict__ Mout) {
    int gw = blockIdx.x * 4 + (threadIdx.x >> 5);
    int lane = threadIdx.x & 31;
    int l = gw % Ll;
    int bh = gw / Ll;
    int b = bh >> 3, h = bh & 7;
    const float* q = QK + ((size_t)(b * Ll + l)) * 1024 + h * DK;
    float q0 = q[lane], q1 = q[lane + 32];
    const float* Kb = QK + (size_t)b * Ll * 1024 + 512 + h * DK;
    float mx = -1e30f, sum = 0.f;
#pragma unroll 4
    for (int s = 0; s < Uu; s += 2) {
        int2 jj = *(const int2*)&sidx[l * Uu + s];
        const float* k0 = Kb + (size_t)jj.x * 1024;
        const float* k1 = Kb + (size_t)jj.y * 1024;
        float p0 = q0 * __ldg(k0 + lane) + q1 * __ldg(k0 + lane + 32);
        float p1 = q0 * __ldg(k1 + lane) + q1 * __ldg(k1 + lane + 32);
#pragma unroll
        for (int o = 16; o; o >>= 1) {
            p0 += __shfl_xor_sync(0xffffffffu, p0, o);
            p1 += __shfl_xor_sync(0xffffffffu, p1, o);
        }
        mx = fmaxf(mx, fmaxf(p0, p1));
        sum += p0 + p1;
    }
    if (lane == 0) Mout[bh * Ll + l] = mx - sum / (float)Ll;
}

// ---------------- top-40 per (b,h) + membership map ------------------------
__global__ void topk_kernel(const float* __restrict__ Mv, int* __restrict__ top,
                            int* __restrict__ map) {
    int bh = blockIdx.x;
    int t = threadIdx.x;
    __shared__ float vals[Ll];
    __shared__ float rv[256];
    __shared__ int   ri[256];
    for (int i = t; i < Ll; i += 256) {
        vals[i] = Mv[bh * Ll + i];
        map[bh * Ll + i] = -1;
    }
    __syncthreads();
    for (int k = 0; k < Uu; k++) {
        float bv = -1e30f; int bi = Ll;
        for (int i = t; i < Ll; i += 256) {
            float v = vals[i];
            if (v > bv) { bv = v; bi = i; }
        }
        rv[t] = bv; ri[t] = bi;
        __syncthreads();
        for (int s = 128; s; s >>= 1) {
            if (t < s) {
                if (rv[t + s] > rv[t] || (rv[t + s] == rv[t] && ri[t + s] < ri[t])) {
                    rv[t] = rv[t + s]; ri[t] = ri[t + s];
                }
            }
            __syncthreads();
        }
        if (t == 0) {
            top[bh * Uu + k] = ri[0];
            map[bh * Ll + ri[0]] = k;
            vals[ri[0]] = -1e30f;
        }
        __syncthreads();
    }
}

// ---------------- V mean partials ------------------------------------------
__global__ void vmean_kernel(const float* __restrict__ V, float* __restrict__ vpart) {
    int bh = blockIdx.x, c8 = blockIdx.y;
    int b = bh >> 3, h = bh & 7;
    int t = threadIdx.x;
    int d = t & 63, sub = t >> 6;
    __shared__ float red[256];
    float s = 0.f;
    int l0 = c8 * 256 + sub * 64;
#pragma unroll 8
    for (int r = 0; r < 64; r++)
        s += V[((size_t)(b * Ll + l0 + r)) * DM + h * DK + d];
    red[t] = s;
    __syncthreads();
    if (t < 64)
        vpart[c8 * (BH * DK) + bh * DK + t] = red[t] + red[t + 64] + red[t + 128] + red[t + 192];
}

// ---------------- scores = Q_red @ K^T / 8 (register-tiled) ----------------
__global__ void __launch_bounds__(256) scores_kernel(
    const float* __restrict__ QK, const int* __restrict__ top, float* __restrict__ S) {
    int bh = blockIdx.x;
    int l0 = blockIdx.y * 256;
    int b = bh >> 3, h = bh & 7;
    int t = threadIdx.x;
    extern __shared__ float sm[];
    float* Qs = sm;               // 40*64
    float* Ks = sm + Uu * 64;     // 256*65
    const float* Qbase = QK + (size_t)b * Ll * 1024 + h * DK;
    const float* Kbase = Qbase + 512;
    for (int idx = t; idx < Uu * 64; idx += 256) {
        int u = idx >> 6, d = idx & 63;
        Qs[idx] = Qbase[(size_t)top[bh * Uu + u] * 1024 + d];
    }
    for (int idx = t; idx < 256 * 64; idx += 256) {
        int i = idx >> 6, d = idx & 63;
        Ks[i * 65 + d] = Kbase[(size_t)(l0 + i) * 1024 + d];
    }
    __syncthreads();
    int ig = t & 63, ug = t >> 6;
    float acc[4][10];
#pragma unroll
    for (int c = 0; c < 4; c++)
#pragma unroll
        for (int o = 0; o < 10; o++) acc[c][o] = 0.f;
#pragma unroll 4
    for (int d = 0; d < 64; d++) {
        float k0 = Ks[ig * 65 + d];
        float k1 = Ks[(ig + 64) * 65 + d];
        float k2 = Ks[(ig + 128) * 65 + d];
        float k3 = Ks[(ig + 192) * 65 + d];
#pragma unroll
        for (int o = 0; o < 10; o++) {
            float q = Qs[(ug + 4 * o) * 64 + d];
            acc[0][o] += q * k0; acc[1][o] += q * k1;
            acc[2][o] += q * k2; acc[3][o] += q * k3;
        }
    }
#pragma unroll
    for (int o = 0; o < 10; o++) {
        size_t row = ((size_t)bh * Uu + ug + 4 * o) * Ll + l0 + ig;
#pragma unroll
        for (int c = 0; c < 4; c++)
            S[row + 64 * c] = acc[c][o] * 0.125f;
    }
}

// ---------------- row softmax ----------------------------------------------
__global__ void softmax_kernel(float* __restrict__ S) {
    int row = blockIdx.x;
    int t = threadIdx.x;
    float* p = S + (size_t)row * Ll;
    __shared__ float red[256];
    float mx = -1e30f;
    for (int i = t; i < Ll; i += 256) mx = fmaxf(mx, p[i]);
    red[t] = mx; __syncthreads();
    for (int s = 128; s; s >>= 1) { if (t < s) red[t] = fmaxf(red[t], red[t + s]); __syncthreads(); }
    mx = red[0]; __syncthreads();
    float sum = 0.f;
    for (int i = t; i < Ll; i += 256) { float e = expf(p[i] - mx); p[i] = e; sum += e; }
    red[t] = sum; __syncthreads();
    for (int s = 128; s; s >>= 1) { if (t < s) red[t] += red[t + s]; __syncthreads(); }
    float inv = 1.f / red[0];
    for (int i = t; i < Ll; i += 256) p[i] *= inv;
}

// ---------------- upd partials: attn @ V over L-chunk ----------------------
__global__ void __launch_bounds__(256) upd_kernel(
    const float* __restrict__ S, const float* __restrict__ V,
    float* __restrict__ upart) {
    int bh = blockIdx.x, lc = blockIdx.y;     // lc: 8 L-chunks of 256
    int b = bh >> 3, h = bh & 7;
    int t = threadIdx.x;
    __shared__ float Vs[64][65];
    __shared__ float As[Uu][64];
    int d = t & 63, ug = t >> 6;
    float acc[10];
#pragma unroll
    for (int o = 0; o < 10; o++) acc[o] = 0.f;
    for (int lt = 0; lt < 4; lt++) {
        int l0 = lc * 256 + lt * 64;
        for (int idx = t; idx < 64 * 64; idx += 256) {
            int i = idx >> 6, dd = idx & 63;
            Vs[i][dd] = V[((size_t)(b * Ll + l0 + i)) * DM + h * DK + dd];
        }
        for (int idx = t; idx < Uu * 64; idx += 256) {
            int u = idx >> 6, i = idx & 63;
            As[u][i] = S[((size_t)bh * Uu + u) * Ll + l0 + i];
        }
        __syncthreads();
#pragma unroll 8
        for (int i = 0; i < 64; i++) {
            float vv = Vs[i][d];
#pragma unroll
            for (int o = 0; o < 10; o++) acc[o] += As[ug + 4 * o][i] * vv;
        }
        __syncthreads();
    }
#pragma unroll
    for (int o = 0; o < 10; o++)
        upart[(size_t)lc * UPDN + ((size_t)bh * Uu + ug + 4 * o) * DK + d] = acc[o];
}

// ---------------- reduce partials (upd + vmean) ----------------------------
__global__ void reduce_kernel(const float* __restrict__ upart,
                              const float* __restrict__ vpart,
                              float* __restrict__ upd, float* __restrict__ vm) {
    int i = blockIdx.x * 256 + threadIdx.x;   // < UPDN + BH*DK
    if (i < UPDN) {
        float s = 0.f;
#pragma unroll
        for (int c = 0; c < 8; c++) s += upart[(size_t)c * UPDN + i];
        upd[i] = s;
    } else {
        int j = i - UPDN;
        float s = 0.f;
#pragma unroll
        for (int c = 0; c < 8; c++) s += vpart[c * (BH * DK) + j];
        vm[j] = s * (1.f / (float)Ll);
    }
}

// ---------------- ctx build: mean fill + top-row scatter, fp16 -------------
__global__ void ctxbuild_kernel(const int* __restrict__ map,
                                const float* __restrict__ vm,
                                const float* __restrict__ upd,
                                __half* __restrict__ ctx) {
    size_t i4 = ((size_t)blockIdx.x * 256 + threadIdx.x) * 4;
    int col = (int)(i4 % DM);
    size_t row = i4 / DM;
    int b = (int)(row >> 11);
    int l = (int)(row & 2047);
    int h = col >> 6, d = col & 63;
    int bh = b * Hh + h;
    int u = map[bh * Ll + l];
    const float* src = (u >= 0) ? upd + ((size_t)bh * Uu + u) * DK + d
                                : vm + bh * DK + d;
    float4 v = *(const float4*)src;
    *(__half2*)&ctx[i4]     = __floats2half2_rn(v.x, v.y);
    *(__half2*)&ctx[i4 + 2] = __floats2half2_rn(v.z, v.w);
}

// ---------------- residual (+bias) + LayerNorm (optional fp16 copy) --------
__global__ void addln_kernel(const float* __restrict__ A,
                             const float* __restrict__ R,
                             const float* __restrict__ bias,
                             const float* __restrict__ gamma,
                             const float* __restrict__ beta,
                             float* __restrict__ out,
                             __half* __restrict__ outh) {
    int row = blockIdx.x;
    int t = threadIdx.x;
    __shared__ float red[256];
    size_t base = (size_t)row * DM;
    float v0 = A[base + t] + R[base + t];
    float v1 = A[base + t + 256] + R[base + t + 256];
    if (bias) { v0 += bias[t]; v1 += bias[t + 256]; }
    red[t] = v0 + v1; __syncthreads();
    for (int s = 128; s; s >>= 1) { if (t < s) red[t] += red[t + s]; __syncthreads(); }
    float mean = red[0] / (float)DM; __syncthreads();
    float d0 = v0 - mean, d1 = v1 - mean;
    red[t] = d0 * d0 + d1 * d1; __syncthreads();
    for (int s = 128; s; s >>= 1) { if (t < s) red[t] += red[t + s]; __syncthreads(); }
    float inv = rsqrtf(red[0] / (float)DM + 1e-5f);
    float o0 = d0 * inv * gamma[t] + beta[t];
    float o1 = d1 * inv * gamma[t + 256] + beta[t + 256];
    out[base + t] = o0;
    out[base + t + 256] = o1;
    if (outh) {
        outh[base + t] = __float2half_rn(o0);
        outh[base + t + 256] = __float2half_rn(o1);
    }
}

// ---------------- host orchestration ---------------------------------------
extern "C" void kernel_launch(void* const* d_in, const int* in_sizes, int n_in,
                              void* d_out, int out_size) {
    const float* x    = (const float*)d_in[0];
    const float* Wq   = (const float*)d_in[1];
    const float* Wk   = (const float*)d_in[2];
    const float* Wv   = (const float*)d_in[3];
    const float* Wo   = (const float*)d_in[4];
    const float* ln1g = (const float*)d_in[5];
    const float* ln1b = (const float*)d_in[6];
    const float* w1   = (const float*)d_in[7];
    const float* b1   = (const float*)d_in[8];
    const float* w2   = (const float*)d_in[9];
    const float* b2   = (const float*)d_in[10];
    const float* ln2g = (const float*)d_in[11];
    const float* ln2b = (const float*)d_in[12];
    const int*   sidx = (const int*)d_in[13];
    float* out = (float*)d_out;

    float *pQK, *pV, *pM, *pS, *pUpd, *pUpart, *pVm, *pVpart, *pAo, *pX1, *pY2;
    __half *pXs, *pXh, *pX1h, *pCtxh, *pFFh, *pWqks, *pWvh, *pWoh, *pW1h, *pW2h;
    int *pTop, *pMap;
    cudaGetSymbolAddress((void**)&pQK, g_QK);
    cudaGetSymbolAddress((void**)&pV, g_V);
    cudaGetSymbolAddress((void**)&pM, g_M);
    cudaGetSymbolAddress((void**)&pTop, g_top);
    cudaGetSymbolAddress((void**)&pMap, g_map);
    cudaGetSymbolAddress((void**)&pS, g_S);
    cudaGetSymbolAddress((void**)&pUpd, g_upd);
    cudaGetSymbolAddress((void**)&pUpart, g_upart);
    cudaGetSymbolAddress((void**)&pVm, g_vm);
    cudaGetSymbolAddress((void**)&pVpart, g_vpart);
    cudaGetSymbolAddress((void**)&pAo, g_ao);
    cudaGetSymbolAddress((void**)&pX1, g_x1);
    cudaGetSymbolAddress((void**)&pY2, g_y2);
    cudaGetSymbolAddress((void**)&pXs, g_xs);
    cudaGetSymbolAddress((void**)&pXh, g_xh);
    cudaGetSymbolAddress((void**)&pX1h, g_x1h);
    cudaGetSymbolAddress((void**)&pCtxh, g_ctxh);
    cudaGetSymbolAddress((void**)&pFFh, g_ffh);
    cudaGetSymbolAddress((void**)&pWqks, g_wqks);
    cudaGetSymbolAddress((void**)&pWvh, g_wvh);
    cudaGetSymbolAddress((void**)&pWoh, g_woh);
    cudaGetSymbolAddress((void**)&pW1h, g_w1h);
    cudaGetSymbolAddress((void**)&pW2h, g_w2h);

    const int smemT = 3 * 32768;
    const int smemS = (Uu * 64 + 256 * 65) * 4;   // 76800
    cudaFuncSetAttribute(hgemm<0,0>, cudaFuncAttributeMaxDynamicSharedMemorySize, smemT);
    cudaFuncSetAttribute(hgemm<1,1>, cudaFuncAttributeMaxDynamicSharedMemorySize, smemT);
    cudaFuncSetAttribute(hgemm3,     cudaFuncAttributeMaxDynamicSharedMemorySize, smemT);
    cudaFuncSetAttribute(scores_kernel, cudaFuncAttributeMaxDynamicSharedMemorySize, smemS);

    // prep
    prep_x<<<ROWS * DM / 4 / 256, 256>>>(x, pXs, pXh);
    prep_w<<<3072, dim3(32, 8)>>>(Wq, Wk, Wv, Wo, w1, w2, pWqks, pWvh, pWoh, pW1h, pW2h);

    // merged Q|K (fp16x3, near-fp32) and V (1-pass fp16)
    hgemm3<<<dim3(8, ROWS / 128), 256, smemT>>>(pXs, pWqks, pQK, ROWS, 1024, DM);
    hgemm<0,0><<<dim3(4, ROWS / 128), 256, smemT>>>(pXh, pWvh, nullptr, pV, ROWS, DM, DM);

    // sparse measure + top-k (+ membership map)
    measure_kernel<<<BH * Ll / 4, 128>>>(pQK, sidx, pM);
    topk_kernel<<<BH, 256>>>(pM, pTop, pMap);

    // V mean partials
    vmean_kernel<<<dim3(BH, 8), 256>>>(pV, pVpart);

    // reduced attention
    scores_kernel<<<dim3(BH, Ll / 256), 256, smemS>>>(pQK, pTop, pS);
    softmax_kernel<<<BH * Uu, 256>>>(pS);
    upd_kernel<<<dim3(BH, 8), 256>>>(pS, pV, pUpart);
    reduce_kernel<<<(UPDN + BH * DK) / 256, 256>>>(pUpart, pVpart, pUpd, pVm);

    // context (fp16) + output projection
    ctxbuild_kernel<<<ROWS * DM / 4 / 256, 256>>>(pMap, pVm, pUpd, pCtxh);
    hgemm<0,0><<<dim3(4, ROWS / 128), 256, smemT>>>(pCtxh, pWoh, nullptr, pAo, ROWS, DM, DM);

    // residual + LN1
    addln_kernel<<<ROWS, 256>>>(x, pAo, nullptr, ln1g, ln1b, pX1, pX1h);

    // FFN
    hgemm<1,1><<<dim3(16, ROWS / 128), 256, smemT>>>(pX1h, pW1h, b1, pFFh, ROWS, DFF, DM);
    hgemm<0,0><<<dim3(4, ROWS / 128), 256, smemT>>>(pFFh, pW2h, nullptr, pY2, ROWS, DM, DFF);

    // residual + bias + LN2 -> output
    addln_kernel<<<ROWS, 256>>>(pX1, pY2, b2, ln2g, ln2b, out, nullptr);
}

// round 7
// speedup vs baseline: 3.8724x; 1.0050x over previous
#include <cuda_runtime.h>
#include <cuda_fp16.h>
#include <math.h>
#include <stdint.h>

#define Bb 4
#define Ll 2048
#define DM 512
#define Hh 8
#define DK 64
#define DFF 2048
#define Uu 40
#define BH (Bb*Hh)
#define ROWS (Bb*Ll)
#define UPDN (BH*Uu*DK)

// ---------------- scratch (static device globals; allocation-free) ----------
__device__ float g_QK[ROWS*1024];     // Q (cols 0-511) | K (cols 512-1023)
__device__ float g_V[ROWS*DM];
__device__ float g_M[BH*Ll];
__device__ int   g_top[BH*Uu];
__device__ int   g_map[BH*Ll];
__device__ float g_S[BH*Uu*Ll];
__device__ float g_upd[UPDN];
__device__ float g_upart[8*UPDN];
__device__ float g_vm[BH*DK];
__device__ float g_vpart[8*BH*DK];
__device__ float g_ao[ROWS*DM];
__device__ float g_x1[ROWS*DM];
__device__ float g_y2[ROWS*DM];
__device__ __half g_xs[ROWS*DM*2];    // x split: [M][K/32][hi32|lo32]
__device__ __half g_xh[ROWS*DM];      // x fp16
__device__ __half g_x1h[ROWS*DM];     // x1 fp16
__device__ __half g_ctxh[ROWS*DM];    // ctx fp16
__device__ __half g_ffh[ROWS*DFF];    // FFN mid fp16
__device__ __half g_wqks[1024*DM*2];  // [Wq^T;Wk^T] split
__device__ __half g_wvh[DM*DM];       // Wv^T fp16
__device__ __half g_woh[DM*DM];       // Wo^T fp16
__device__ __half g_w1h[DFF*DM];
__device__ __half g_w2h[DM*DFF];

#define SWZ(b) ((b) ^ (((b) >> 3) & 0x70))

__device__ __forceinline__ uint32_t smem_u32(const void* p) {
    uint32_t a;
    asm("{ .reg .u64 t; cvta.to.shared.u64 t, %1; cvt.u32.u64 %0, t; }" : "=r"(a) : "l"(p));
    return a;
}
__device__ __forceinline__ void cp_async16(uint32_t s, const void* g) {
    asm volatile("cp.async.cg.shared.global [%0], [%1], 16;" :: "r"(s), "l"(g) : "memory");
}
__device__ __forceinline__ void ldsm_x4(uint32_t* r, uint32_t a) {
    asm volatile("ldmatrix.sync.aligned.m8n8.x4.shared.b16 {%0,%1,%2,%3}, [%4];"
                 : "=r"(r[0]), "=r"(r[1]), "=r"(r[2]), "=r"(r[3]) : "r"(a));
}
__device__ __forceinline__ void mma_f16(float* c, const uint32_t* a, uint32_t b0, uint32_t b1) {
    asm volatile("mma.sync.aligned.m16n8k16.row.col.f32.f16.f16.f32 "
                 "{%0,%1,%2,%3}, {%4,%5,%6,%7}, {%8,%9}, {%0,%1,%2,%3};"
                 : "+f"(c[0]), "+f"(c[1]), "+f"(c[2]), "+f"(c[3])
                 : "r"(a[0]), "r"(a[1]), "r"(a[2]), "r"(a[3]), "r"(b0), "r"(b1));
}
__device__ __forceinline__ float gelu_f(float v) {
    return 0.5f * v * (1.f + erff(v * 0.70710678118654752f));
}

// ============ fp16 mma GEMM (1-pass): C[M,N] = A[M,K] @ B^T, B [N,K] =======
// Tile 128x64, BK=64, 256 threads (8 warps, warp 32x32), 3 CTA/SM, 3-stage.
template<int EPI, int OUTH>
__global__ void __launch_bounds__(256, 3) hgemm(
    const __half* __restrict__ A, const __half* __restrict__ Bw,
    const float* __restrict__ bias, void* __restrict__ Cv,
    int M, int N, int K)
{
    extern __shared__ char smem[];
    const uint32_t sbase = smem_u32(smem);
    const int tid = threadIdx.x, wid = tid >> 5, lane = tid & 31;
    const int m0 = blockIdx.y * 128, n0 = blockIdx.x * 64;
    const int wm0 = (wid & 3) * 32, wn0 = (wid >> 2) * 32;
    const int STG = 24576;            // A 16KB + B 8KB
    const int KC = K >> 6;

    float acc[2][4][4];
#pragma unroll
    for (int i = 0; i < 2; i++)
#pragma unroll
        for (int j = 0; j < 4; j++)
#pragma unroll
            for (int r = 0; r < 4; r++) acc[i][j][r] = 0.f;

    auto load_stage = [&](int kc, int s) {
        const __half* Ap = A + (size_t)m0 * K + kc * 64;
        const __half* Bp = Bw + (size_t)n0 * K + kc * 64;
        uint32_t sa = sbase + s * STG;
        uint32_t sb = sa + 16384;
#pragma unroll
        for (int p = 0; p < 4; p++) {
            int idx = tid + p * 256;
            int r = idx >> 3, c = idx & 7;
            uint32_t so = SWZ((uint32_t)(r * 128 + c * 16));
            cp_async16(sa + so, Ap + (size_t)r * K + c * 8);
            if (p < 2) cp_async16(sb + so, Bp + (size_t)r * K + c * 8);
        }
    };

    load_stage(0, 0);
    asm volatile("cp.async.commit_group;");
    if (KC > 1) load_stage(1, 1);
    asm volatile("cp.async.commit_group;");

    const int frow = lane & 15;
    const int fchk = (lane >> 4) * 16;

    for (int i = 0; i < KC; i++) {
        asm volatile("cp.async.wait_group 1;" ::: "memory");
        __syncthreads();
        if (i + 2 < KC) load_stage(i + 2, (i + 2) % 3);
        asm volatile("cp.async.commit_group;");

        uint32_t sa = sbase + (i % 3) * STG;
        uint32_t sb = sa + 16384;
#pragma unroll
        for (int s = 0; s < 4; s++) {
            uint32_t Bf[2][4];
#pragma unroll
            for (int p = 0; p < 2; p++)
                ldsm_x4(Bf[p], sb + SWZ((uint32_t)((wn0 + p * 16 + frow) * 128 + s * 32 + fchk)));
#pragma unroll
            for (int mt = 0; mt < 2; mt++) {
                uint32_t Af[4];
                ldsm_x4(Af, sa + SWZ((uint32_t)((wm0 + mt * 16 + frow) * 128 + s * 32 + fchk)));
#pragma unroll
                for (int nt = 0; nt < 4; nt++)
                    mma_f16(acc[mt][nt], Af, Bf[nt >> 1][nt & 1], Bf[nt >> 1][(nt & 1) + 2]);
            }
        }
        __syncthreads();
    }
    asm volatile("cp.async.wait_group 0;" ::: "memory");

    const int rbase = m0 + wm0 + (lane >> 2);
    const int cbase = n0 + wn0 + (lane & 3) * 2;
    float* Cf = (float*)Cv;
    __half* Ch = (__half*)Cv;
#pragma unroll
    for (int mt = 0; mt < 2; mt++) {
#pragma unroll
        for (int nt = 0; nt < 4; nt++) {
            int col = cbase + nt * 8;
            float v0 = acc[mt][nt][0], v1 = acc[mt][nt][1];
            float v2 = acc[mt][nt][2], v3 = acc[mt][nt][3];
            if (EPI == 1) {
                float b0 = bias[col], b1 = bias[col + 1];
                v0 = gelu_f(v0 + b0); v1 = gelu_f(v1 + b1);
                v2 = gelu_f(v2 + b0); v3 = gelu_f(v3 + b1);
            }
            size_t r0 = (size_t)(rbase + mt * 16) * N + col;
            size_t r1 = (size_t)(rbase + mt * 16 + 8) * N + col;
            if (OUTH) {
                *(__half2*)&Ch[r0] = __floats2half2_rn(v0, v1);
                *(__half2*)&Ch[r1] = __floats2half2_rn(v2, v3);
            } else {
                float2 p0; p0.x = v0; p0.y = v1;
                float2 p1; p1.x = v2; p1.y = v3;
                *(float2*)&Cf[r0] = p0;
                *(float2*)&Cf[r1] = p1;
            }
        }
    }
}

// ============ fp16x3 split GEMM (near-fp32; for Q|K merged) ================
// Tile 128x64, split layout rows of 2K halves.
__global__ void __launch_bounds__(256, 3) hgemm3(
    const __half* __restrict__ As, const __half* __restrict__ Bs,
    float* __restrict__ C, int M, int N, int K)
{
    extern __shared__ char smem[];
    const uint32_t sbase = smem_u32(smem);
    const int tid = threadIdx.x, wid = tid >> 5, lane = tid & 31;
    const int m0 = blockIdx.y * 128, n0 = blockIdx.x * 64;
    const int wm0 = (wid & 3) * 32, wn0 = (wid >> 2) * 32;
    const int STG = 24576;
    const int KC = K >> 5;
    const int RS = K * 2;

    float acc[2][4][4];
#pragma unroll
    for (int i = 0; i < 2; i++)
#pragma unroll
        for (int j = 0; j < 4; j++)
#pragma unroll
            for (int r = 0; r < 4; r++) acc[i][j][r] = 0.f;

    auto load_stage = [&](int kc, int s) {
        const __half* Ap = As + (size_t)m0 * RS + kc * 64;
        const __half* Bp = Bs + (size_t)n0 * RS + kc * 64;
        uint32_t sa = sbase + s * STG;
        uint32_t sb = sa + 16384;
#pragma unroll
        for (int p = 0; p < 4; p++) {
            int idx = tid + p * 256;
            int r = idx >> 3, c = idx & 7;
            uint32_t so = SWZ((uint32_t)(r * 128 + c * 16));
            cp_async16(sa + so, Ap + (size_t)r * RS + c * 8);
            if (p < 2) cp_async16(sb + so, Bp + (size_t)r * RS + c * 8);
        }
    };

    load_stage(0, 0);
    asm volatile("cp.async.commit_group;");
    if (KC > 1) load_stage(1, 1);
    asm volatile("cp.async.commit_group;");

    const int frow = lane & 15;
    const int fchk = (lane >> 4) * 16;

    for (int i = 0; i < KC; i++) {
        asm volatile("cp.async.wait_group 1;" ::: "memory");
        __syncthreads();
        if (i + 2 < KC) load_stage(i + 2, (i + 2) % 3);
        asm volatile("cp.async.commit_group;");

        uint32_t sa = sbase + (i % 3) * STG;
        uint32_t sb = sa + 16384;
#pragma unroll
        for (int s = 0; s < 2; s++) {
            uint32_t Bh[2][4], Bl[2][4];
#pragma unroll
            for (int p = 0; p < 2; p++) {
                uint32_t rowoff = (uint32_t)((wn0 + p * 16 + frow) * 128 + s * 32 + fchk);
                ldsm_x4(Bh[p], sb + SWZ(rowoff));
                ldsm_x4(Bl[p], sb + SWZ(rowoff + 64));
            }
#pragma unroll
            for (int mt = 0; mt < 2; mt++) {
                uint32_t Ah[4], Al[4];
                uint32_t rowoff = (uint32_t)((wm0 + mt * 16 + frow) * 128 + s * 32 + fchk);
                ldsm_x4(Ah, sa + SWZ(rowoff));
                ldsm_x4(Al, sa + SWZ(rowoff + 64));
#pragma unroll
                for (int nt = 0; nt < 4; nt++) {
                    uint32_t bh0 = Bh[nt >> 1][nt & 1], bh1 = Bh[nt >> 1][(nt & 1) + 2];
                    uint32_t bl0 = Bl[nt >> 1][nt & 1], bl1 = Bl[nt >> 1][(nt & 1) + 2];
                    mma_f16(acc[mt][nt], Al, bh0, bh1);
                    mma_f16(acc[mt][nt], Ah, bl0, bl1);
                    mma_f16(acc[mt][nt], Ah, bh0, bh1);
                }
            }
        }
        __syncthreads();
    }
    asm volatile("cp.async.wait_group 0;" ::: "memory");

    const int rbase = m0 + wm0 + (lane >> 2);
    const int cbase = n0 + wn0 + (lane & 3) * 2;
#pragma unroll
    for (int mt = 0; mt < 2; mt++) {
#pragma unroll
        for (int nt = 0; nt < 4; nt++) {
            int col = cbase + nt * 8;
            float2 p0; p0.x = acc[mt][nt][0]; p0.y = acc[mt][nt][1];
            float2 p1; p1.x = acc[mt][nt][2]; p1.y = acc[mt][nt][3];
            *(float2*)&C[(size_t)(rbase + mt * 16) * N + col] = p0;
            *(float2*)&C[(size_t)(rbase + mt * 16 + 8) * N + col] = p1;
        }
    }
}

// ---------------- prep: x -> split + plain fp16 ----------------------------
__global__ void prep_x(const float* __restrict__ x, __half* __restrict__ xs,
                       __half* __restrict__ xh) {
    size_t i = ((size_t)blockIdx.x * 256 + threadIdx.x) * 4;
    int m = (int)(i / DM), k = (int)(i % DM);
    float4 v = *(const float4*)&x[i];
    __half h0 = __float2half_rn(v.x), h1 = __float2half_rn(v.y);
    __half h2 = __float2half_rn(v.z), h3 = __float2half_rn(v.w);
    __half l0 = __float2half_rn(v.x - __half2float(h0));
    __half l1 = __float2half_rn(v.y - __half2float(h1));
    __half l2 = __float2half_rn(v.z - __half2float(h2));
    __half l3 = __float2half_rn(v.w - __half2float(h3));
    xh[i] = h0; xh[i + 1] = h1; xh[i + 2] = h2; xh[i + 3] = h3;
    size_t o = (size_t)m * (DM * 2) + (k >> 5) * 64 + (k & 31);
    xs[o] = h0; xs[o + 1] = h1; xs[o + 2] = h2; xs[o + 3] = h3;
    xs[o + 32] = l0; xs[o + 33] = l1; xs[o + 34] = l2; xs[o + 35] = l3;
}

// ---------------- mega weight prep -----------------------------------------
__global__ void prep_w(const float* __restrict__ Wq, const float* __restrict__ Wk,
                       const float* __restrict__ Wv, const float* __restrict__ Wo,
                       const float* __restrict__ w1, const float* __restrict__ w2,
                       __half* __restrict__ wqks, __half* __restrict__ wvh,
                       __half* __restrict__ woh, __half* __restrict__ w1h,
                       __half* __restrict__ w2h) {
    int blk = blockIdx.x;
    int tx = threadIdx.x, ty = threadIdx.y;
    if (blk < 1024) {
        int region = blk >> 8;
        int tile = blk & 255;
        int bx = (tile & 15) * 32, by = (tile >> 4) * 32;
        const float* W = region == 0 ? Wq : region == 1 ? Wk : region == 2 ? Wv : Wo;
        __shared__ float tbuf[32][33];
        for (int i = ty; i < 32; i += 8)
            tbuf[i][tx] = W[(size_t)(by + i) * DM + bx + tx];
        __syncthreads();
        if (region < 2) {
            int roff = region * 512;
            for (int i = ty; i < 32; i += 8) {
                int n = bx + i;
                float v = tbuf[tx][i];
                __half hh = __float2half_rn(v);
                __half lo = __float2half_rn(v - __half2float(hh));
                size_t off = (size_t)(roff + n) * (DM * 2) + (by >> 5) * 64 + tx;
                wqks[off] = hh; wqks[off + 32] = lo;
            }
        } else {
            __half* o = (region == 2) ? wvh : woh;
            for (int i = ty; i < 32; i += 8)
                o[(size_t)(bx + i) * DM + by + tx] = __float2half_rn(tbuf[tx][i]);
        }
    } else {
        int t = ty * 32 + tx;
        const float* src = (blk < 2048) ? w1 : w2;
        __half* dst = (blk < 2048) ? w1h : w2h;
        size_t i = ((size_t)((blk - 1024) & 1023)) * 1024 + t * 4;
        float4 v = *(const float4*)&src[i];
        *(__half2*)&dst[i] = __floats2half2_rn(v.x, v.y);
        *(__half2*)&dst[i + 2] = __floats2half2_rn(v.z, v.w);
    }
}

// ---------------- sampled QK measure (ILP-2, float2 loads) ------------------
__global__ void measure_kernel(const float* __restrict__ QK,
                               const int* __restrict__ sidx,
                               float* __restrict__ Mout) {
    int gw = blockIdx.x * 4 + (threadIdx.x >> 5);
    int lane = threadIdx.x & 31;
    int l = gw % Ll;
    int bh = gw / Ll;
    int b = bh >> 3, h = bh & 7;
    const float2* q2 = (const float2*)(QK + ((size_t)(b * Ll + l)) * 1024 + h * DK);
    float2 qa = q2[lane];
    const float* Kb = QK + (size_t)b * Ll * 1024 + 512 + h * DK;
    float mx = -1e30f, sum = 0.f;
#pragma unroll 4
    for (int s = 0; s < Uu; s += 2) {
        int2 jj = *(const int2*)&sidx[l * Uu + s];
        float2 ka = __ldg((const float2*)(Kb + (size_t)jj.x * 1024) + lane);
        float2 kb = __ldg((const float2*)(Kb + (size_t)jj.y * 1024) + lane);
        float p0 = qa.x * ka.x + qa.y * ka.y;
        float p1 = qa.x * kb.x + qa.y * kb.y;
#pragma unroll
        for (int o = 16; o; o >>= 1) {
            p0 += __shfl_xor_sync(0xffffffffu, p0, o);
            p1 += __shfl_xor_sync(0xffffffffu, p1, o);
        }
        mx = fmaxf(mx, fmaxf(p0, p1));
        sum += p0 + p1;
    }
    if (lane == 0) Mout[bh * Ll + l] = mx - sum / (float)Ll;
}

// ---------------- top-40 per (b,h) + membership map ------------------------
__global__ void topk_kernel(const float* __restrict__ Mv, int* __restrict__ top,
                            int* __restrict__ map) {
    int bh = blockIdx.x;
    int t = threadIdx.x;
    __shared__ float vals[Ll];
    __shared__ float rv[256];
    __shared__ int   ri[256];
    for (int i = t; i < Ll; i += 256) {
        vals[i] = Mv[bh * Ll + i];
        map[bh * Ll + i] = -1;
    }
    __syncthreads();
    for (int k = 0; k < Uu; k++) {
        float bv = -1e30f; int bi = Ll;
        for (int i = t; i < Ll; i += 256) {
            float v = vals[i];
            if (v > bv) { bv = v; bi = i; }
        }
        rv[t] = bv; ri[t] = bi;
        __syncthreads();
        for (int s = 128; s; s >>= 1) {
            if (t < s) {
                if (rv[t + s] > rv[t] || (rv[t + s] == rv[t] && ri[t + s] < ri[t])) {
                    rv[t] = rv[t + s]; ri[t] = ri[t + s];
                }
            }
            __syncthreads();
        }
        if (t == 0) {
            top[bh * Uu + k] = ri[0];
            map[bh * Ll + ri[0]] = k;
            vals[ri[0]] = -1e30f;
        }
        __syncthreads();
    }
}

// ---------------- V mean partials ------------------------------------------
__global__ void vmean_kernel(const float* __restrict__ V, float* __restrict__ vpart) {
    int bh = blockIdx.x, c8 = blockIdx.y;
    int b = bh >> 3, h = bh & 7;
    int t = threadIdx.x;
    int d = t & 63, sub = t >> 6;
    __shared__ float red[256];
    float s = 0.f;
    int l0 = c8 * 256 + sub * 64;
#pragma unroll 8
    for (int r = 0; r < 64; r++)
        s += V[((size_t)(b * Ll + l0 + r)) * DM + h * DK + d];
    red[t] = s;
    __syncthreads();
    if (t < 64)
        vpart[c8 * (BH * DK) + bh * DK + t] = red[t] + red[t + 64] + red[t + 128] + red[t + 192];
}

// ---------------- scores = Q_red @ K^T / 8 (register-tiled) ----------------
__global__ void __launch_bounds__(256) scores_kernel(
    const float* __restrict__ QK, const int* __restrict__ top, float* __restrict__ S) {
    int bh = blockIdx.x;
    int l0 = blockIdx.y * 256;
    int b = bh >> 3, h = bh & 7;
    int t = threadIdx.x;
    extern __shared__ float sm[];
    float* Qs = sm;               // 40*64
    float* Ks = sm + Uu * 64;     // 256*65
    const float* Qbase = QK + (size_t)b * Ll * 1024 + h * DK;
    const float* Kbase = Qbase + 512;
    for (int idx = t; idx < Uu * 64; idx += 256) {
        int u = idx >> 6, d = idx & 63;
        Qs[idx] = Qbase[(size_t)top[bh * Uu + u] * 1024 + d];
    }
    for (int idx = t; idx < 256 * 64; idx += 256) {
        int i = idx >> 6, d = idx & 63;
        Ks[i * 65 + d] = Kbase[(size_t)(l0 + i) * 1024 + d];
    }
    __syncthreads();
    int ig = t & 63, ug = t >> 6;
    float acc[4][10];
#pragma unroll
    for (int c = 0; c < 4; c++)
#pragma unroll
        for (int o = 0; o < 10; o++) acc[c][o] = 0.f;
#pragma unroll 4
    for (int d = 0; d < 64; d++) {
        float k0 = Ks[ig * 65 + d];
        float k1 = Ks[(ig + 64) * 65 + d];
        float k2 = Ks[(ig + 128) * 65 + d];
        float k3 = Ks[(ig + 192) * 65 + d];
#pragma unroll
        for (int o = 0; o < 10; o++) {
            float q = Qs[(ug + 4 * o) * 64 + d];
            acc[0][o] += q * k0; acc[1][o] += q * k1;
            acc[2][o] += q * k2; acc[3][o] += q * k3;
        }
    }
#pragma unroll
    for (int o = 0; o < 10; o++) {
        size_t row = ((size_t)bh * Uu + ug + 4 * o) * Ll + l0 + ig;
#pragma unroll
        for (int c = 0; c < 4; c++)
            S[row + 64 * c] = acc[c][o] * 0.125f;
    }
}

// ---------------- row softmax ----------------------------------------------
__global__ void softmax_kernel(float* __restrict__ S) {
    int row = blockIdx.x;
    int t = threadIdx.x;
    float* p = S + (size_t)row * Ll;
    __shared__ float red[256];
    float mx = -1e30f;
    for (int i = t; i < Ll; i += 256) mx = fmaxf(mx, p[i]);
    red[t] = mx; __syncthreads();
    for (int s = 128; s; s >>= 1) { if (t < s) red[t] = fmaxf(red[t], red[t + s]); __syncthreads(); }
    mx = red[0]; __syncthreads();
    float sum = 0.f;
    for (int i = t; i < Ll; i += 256) { float e = expf(p[i] - mx); p[i] = e; sum += e; }
    red[t] = sum; __syncthreads();
    for (int s = 128; s; s >>= 1) { if (t < s) red[t] += red[t + s]; __syncthreads(); }
    float inv = 1.f / red[0];
    for (int i = t; i < Ll; i += 256) p[i] *= inv;
}

// ---------------- upd partials: attn @ V over L-chunk ----------------------
__global__ void __launch_bounds__(256) upd_kernel(
    const float* __restrict__ S, const float* __restrict__ V,
    float* __restrict__ upart) {
    int bh = blockIdx.x, lc = blockIdx.y;
    int b = bh >> 3, h = bh & 7;
    int t = threadIdx.x;
    __shared__ float Vs[64][65];
    __shared__ float As[Uu][64];
    int d = t & 63, ug = t >> 6;
    float acc[10];
#pragma unroll
    for (int o = 0; o < 10; o++) acc[o] = 0.f;
    for (int lt = 0; lt < 4; lt++) {
        int l0 = lc * 256 + lt * 64;
        for (int idx = t; idx < 64 * 64; idx += 256) {
            int i = idx >> 6, dd = idx & 63;
            Vs[i][dd] = V[((size_t)(b * Ll + l0 + i)) * DM + h * DK + dd];
        }
        for (int idx = t; idx < Uu * 64; idx += 256) {
            int u = idx >> 6, i = idx & 63;
            As[u][i] = S[((size_t)bh * Uu + u) * Ll + l0 + i];
        }
        __syncthreads();
#pragma unroll 8
        for (int i = 0; i < 64; i++) {
            float vv = Vs[i][d];
#pragma unroll
            for (int o = 0; o < 10; o++) acc[o] += As[ug + 4 * o][i] * vv;
        }
        __syncthreads();
    }
#pragma unroll
    for (int o = 0; o < 10; o++)
        upart[(size_t)lc * UPDN + ((size_t)bh * Uu + ug + 4 * o) * DK + d] = acc[o];
}

// ---------------- reduce partials (upd + vmean) ----------------------------
__global__ void reduce_kernel(const float* __restrict__ upart,
                              const float* __restrict__ vpart,
                              float* __restrict__ upd, float* __restrict__ vm) {
    int i = blockIdx.x * 256 + threadIdx.x;
    if (i < UPDN) {
        float s = 0.f;
#pragma unroll
        for (int c = 0; c < 8; c++) s += upart[(size_t)c * UPDN + i];
        upd[i] = s;
    } else {
        int j = i - UPDN;
        float s = 0.f;
#pragma unroll
        for (int c = 0; c < 8; c++) s += vpart[c * (BH * DK) + j];
        vm[j] = s * (1.f / (float)Ll);
    }
}

// ---------------- ctx build: mean fill + top-row scatter, fp16 -------------
__global__ void ctxbuild_kernel(const int* __restrict__ map,
                                const float* __restrict__ vm,
                                const float* __restrict__ upd,
                                __half* __restrict__ ctx) {
    size_t i4 = ((size_t)blockIdx.x * 256 + threadIdx.x) * 4;
    int col = (int)(i4 % DM);
    size_t row = i4 / DM;
    int b = (int)(row >> 11);
    int l = (int)(row & 2047);
    int h = col >> 6, d = col & 63;
    int bh = b * Hh + h;
    int u = map[bh * Ll + l];
    const float* src = (u >= 0) ? upd + ((size_t)bh * Uu + u) * DK + d
                                : vm + bh * DK + d;
    float4 v = *(const float4*)src;
    *(__half2*)&ctx[i4]     = __floats2half2_rn(v.x, v.y);
    *(__half2*)&ctx[i4 + 2] = __floats2half2_rn(v.z, v.w);
}

// ---------------- residual (+bias) + LayerNorm (optional fp16 copy) --------
__global__ void addln_kernel(const float* __restrict__ A,
                             const float* __restrict__ R,
                             const float* __restrict__ bias,
                             const float* __restrict__ gamma,
                             const float* __restrict__ beta,
                             float* __restrict__ out,
                             __half* __restrict__ outh) {
    int row = blockIdx.x;
    int t = threadIdx.x;
    __shared__ float red[256];
    size_t base = (size_t)row * DM;
    float v0 = A[base + t] + R[base + t];
    float v1 = A[base + t + 256] + R[base + t + 256];
    if (bias) { v0 += bias[t]; v1 += bias[t + 256]; }
    red[t] = v0 + v1; __syncthreads();
    for (int s = 128; s; s >>= 1) { if (t < s) red[t] += red[t + s]; __syncthreads(); }
    float mean = red[0] / (float)DM; __syncthreads();
    float d0 = v0 - mean, d1 = v1 - mean;
    red[t] = d0 * d0 + d1 * d1; __syncthreads();
    for (int s = 128; s; s >>= 1) { if (t < s) red[t] += red[t + s]; __syncthreads(); }
    float inv = rsqrtf(red[0] / (float)DM + 1e-5f);
    float o0 = d0 * inv * gamma[t] + beta[t];
    float o1 = d1 * inv * gamma[t + 256] + beta[t + 256];
    out[base + t] = o0;
    out[base + t + 256] = o1;
    if (outh) {
        outh[base + t] = __float2half_rn(o0);
        outh[base + t + 256] = __float2half_rn(o1);
    }
}

// ---------------- host orchestration ---------------------------------------
extern "C" void kernel_launch(void* const* d_in, const int* in_sizes, int n_in,
                              void* d_out, int out_size) {
    const float* x    = (const float*)d_in[0];
    const float* Wq   = (const float*)d_in[1];
    const float* Wk   = (const float*)d_in[2];
    const float* Wv   = (const float*)d_in[3];
    const float* Wo   = (const float*)d_in[4];
    const float* ln1g = (const float*)d_in[5];
    const float* ln1b = (const float*)d_in[6];
    const float* w1   = (const float*)d_in[7];
    const float* b1   = (const float*)d_in[8];
    const float* w2   = (const float*)d_in[9];
    const float* b2   = (const float*)d_in[10];
    const float* ln2g = (const float*)d_in[11];
    const float* ln2b = (const float*)d_in[12];
    const int*   sidx = (const int*)d_in[13];
    float* out = (float*)d_out;

    float *pQK, *pV, *pM, *pS, *pUpd, *pUpart, *pVm, *pVpart, *pAo, *pX1, *pY2;
    __half *pXs, *pXh, *pX1h, *pCtxh, *pFFh, *pWqks, *pWvh, *pWoh, *pW1h, *pW2h;
    int *pTop, *pMap;
    cudaGetSymbolAddress((void**)&pQK, g_QK);
    cudaGetSymbolAddress((void**)&pV, g_V);
    cudaGetSymbolAddress((void**)&pM, g_M);
    cudaGetSymbolAddress((void**)&pTop, g_top);
    cudaGetSymbolAddress((void**)&pMap, g_map);
    cudaGetSymbolAddress((void**)&pS, g_S);
    cudaGetSymbolAddress((void**)&pUpd, g_upd);
    cudaGetSymbolAddress((void**)&pUpart, g_upart);
    cudaGetSymbolAddress((void**)&pVm, g_vm);
    cudaGetSymbolAddress((void**)&pVpart, g_vpart);
    cudaGetSymbolAddress((void**)&pAo, g_ao);
    cudaGetSymbolAddress((void**)&pX1, g_x1);
    cudaGetSymbolAddress((void**)&pY2, g_y2);
    cudaGetSymbolAddress((void**)&pXs, g_xs);
    cudaGetSymbolAddress((void**)&pXh, g_xh);
    cudaGetSymbolAddress((void**)&pX1h, g_x1h);
    cudaGetSymbolAddress((void**)&pCtxh, g_ctxh);
    cudaGetSymbolAddress((void**)&pFFh, g_ffh);
    cudaGetSymbolAddress((void**)&pWqks, g_wqks);
    cudaGetSymbolAddress((void**)&pWvh, g_wvh);
    cudaGetSymbolAddress((void**)&pWoh, g_woh);
    cudaGetSymbolAddress((void**)&pW1h, g_w1h);
    cudaGetSymbolAddress((void**)&pW2h, g_w2h);

    const int smemT = 3 * 24576;   // 73728
    const int smemS = (Uu * 64 + 256 * 65) * 4;   // 76800
    cudaFuncSetAttribute(hgemm<0,0>, cudaFuncAttributeMaxDynamicSharedMemorySize, smemT);
    cudaFuncSetAttribute(hgemm<1,1>, cudaFuncAttributeMaxDynamicSharedMemorySize, smemT);
    cudaFuncSetAttribute(hgemm3,     cudaFuncAttributeMaxDynamicSharedMemorySize, smemT);
    cudaFuncSetAttribute(scores_kernel, cudaFuncAttributeMaxDynamicSharedMemorySize, smemS);

    // prep
    prep_x<<<ROWS * DM / 4 / 256, 256>>>(x, pXs, pXh);
    prep_w<<<3072, dim3(32, 8)>>>(Wq, Wk, Wv, Wo, w1, w2, pWqks, pWvh, pWoh, pW1h, pW2h);

    // merged Q|K (fp16x3, near-fp32) and V (1-pass fp16)
    hgemm3<<<dim3(16, ROWS / 128), 256, smemT>>>(pXs, pWqks, pQK, ROWS, 1024, DM);
    hgemm<0,0><<<dim3(8, ROWS / 128), 256, smemT>>>(pXh, pWvh, nullptr, pV, ROWS, DM, DM);

    // sparse measure + top-k (+ membership map)
    measure_kernel<<<BH * Ll / 4, 128>>>(pQK, sidx, pM);
    topk_kernel<<<BH, 256>>>(pM, pTop, pMap);

    // V mean partials
    vmean_kernel<<<dim3(BH, 8), 256>>>(pV, pVpart);

    // reduced attention
    scores_kernel<<<dim3(BH, Ll / 256), 256, smemS>>>(pQK, pTop, pS);
    softmax_kernel<<<BH * Uu, 256>>>(pS);
    upd_kernel<<<dim3(BH, 8), 256>>>(pS, pV, pUpart);
    reduce_kernel<<<(UPDN + BH * DK) / 256, 256>>>(pUpart, pVpart, pUpd, pVm);

    // context (fp16) + output projection
    ctxbuild_kernel<<<ROWS * DM / 4 / 256, 256>>>(pMap, pVm, pUpd, pCtxh);
    hgemm<0,0><<<dim3(8, ROWS / 128), 256, smemT>>>(pCtxh, pWoh, nullptr, pAo, ROWS, DM, DM);

    // residual + LN1
    addln_kernel<<<ROWS, 256>>>(x, pAo, nullptr, ln1g, ln1b, pX1, pX1h);

    // FFN
    hgemm<1,1><<<dim3(32, ROWS / 128), 256, smemT>>>(pX1h, pW1h, b1, pFFh, ROWS, DFF, DM);
    hgemm<0,0><<<dim3(8, ROWS / 128), 256, smemT>>>(pFFh, pW2h, nullptr, pY2, ROWS, DM, DFF);

    // residual + bias + LN2 -> output
    addln_kernel<<<ROWS, 256>>>(pX1, pY2, b2, ln2g, ln2b, out, nullptr);
}

// round 8
// speedup vs baseline: 3.8727x; 1.0001x over previous
#include <cuda_runtime.h>
#include <cuda_fp16.h>
#include <math.h>
#include <stdint.h>

#define Bb 4
#define Ll 2048
#define DM 512
#define Hh 8
#define DK 64
#define DFF 2048
#define Uu 40
#define BH (Bb*Hh)
#define ROWS (Bb*Ll)
#define UPDN (BH*Uu*DK)

// ---------------- scratch (static device globals; allocation-free) ----------
__device__ float g_QK[ROWS*1024];     // Q (cols 0-511) | K (cols 512-1023)
__device__ float g_V[ROWS*DM];
__device__ float g_M[BH*Ll];
__device__ int   g_top[BH*Uu];
__device__ int   g_map[BH*Ll];
__device__ float g_upd[UPDN];
__device__ float g_upart[8*UPDN];
__device__ float g_mpart[8*BH*Uu];
__device__ float g_spart[8*BH*Uu];
__device__ float g_vm[BH*DK];
__device__ float g_vpart[8*BH*DK];
__device__ float g_ao[ROWS*DM];
__device__ float g_x1[ROWS*DM];
__device__ float g_y2[ROWS*DM];
__device__ __half g_xs[ROWS*DM*2];    // x split: [M][K/32][hi32|lo32]
__device__ __half g_xh[ROWS*DM];      // x fp16
__device__ __half g_x1h[ROWS*DM];     // x1 fp16
__device__ __half g_ctxh[ROWS*DM];    // ctx fp16
__device__ __half g_ffh[ROWS*DFF];    // FFN mid fp16
__device__ __half g_wqks[1024*DM*2];  // [Wq^T;Wk^T] split
__device__ __half g_wvh[DM*DM];       // Wv^T fp16
__device__ __half g_woh[DM*DM];       // Wo^T fp16
__device__ __half g_w1h[DFF*DM];
__device__ __half g_w2h[DM*DFF];

#define SWZ(b) ((b) ^ (((b) >> 3) & 0x70))

__device__ __forceinline__ uint32_t smem_u32(const void* p) {
    uint32_t a;
    asm("{ .reg .u64 t; cvta.to.shared.u64 t, %1; cvt.u32.u64 %0, t; }" : "=r"(a) : "l"(p));
    return a;
}
__device__ __forceinline__ void cp_async16(uint32_t s, const void* g) {
    asm volatile("cp.async.cg.shared.global [%0], [%1], 16;" :: "r"(s), "l"(g) : "memory");
}
__device__ __forceinline__ void ldsm_x4(uint32_t* r, uint32_t a) {
    asm volatile("ldmatrix.sync.aligned.m8n8.x4.shared.b16 {%0,%1,%2,%3}, [%4];"
                 : "=r"(r[0]), "=r"(r[1]), "=r"(r[2]), "=r"(r[3]) : "r"(a));
}
__device__ __forceinline__ void mma_f16(float* c, const uint32_t* a, uint32_t b0, uint32_t b1) {
    asm volatile("mma.sync.aligned.m16n8k16.row.col.f32.f16.f16.f32 "
                 "{%0,%1,%2,%3}, {%4,%5,%6,%7}, {%8,%9}, {%0,%1,%2,%3};"
                 : "+f"(c[0]), "+f"(c[1]), "+f"(c[2]), "+f"(c[3])
                 : "r"(a[0]), "r"(a[1]), "r"(a[2]), "r"(a[3]), "r"(b0), "r"(b1));
}
__device__ __forceinline__ float gelu_f(float v) {
    return 0.5f * v * (1.f + erff(v * 0.70710678118654752f));
}

// ============ fp16 mma GEMM (1-pass): C[M,N] = A[M,K] @ B^T, B [N,K] =======
// Block 128x128, BK=64, 256 threads (8 warps, warp 64x32), 3-stage cp.async.
template<int EPI, int OUTH>
__global__ void __launch_bounds__(256, 2) hgemm(
    const __half* __restrict__ A, const __half* __restrict__ Bw,
    const float* __restrict__ bias, void* __restrict__ Cv,
    int M, int N, int K)
{
    extern __shared__ char smem[];
    const uint32_t sbase = smem_u32(smem);
    const int tid = threadIdx.x, wid = tid >> 5, lane = tid & 31;
    const int m0 = blockIdx.y * 128, n0 = blockIdx.x * 128;
    const int wm0 = (wid & 1) * 64, wn0 = (wid >> 1) * 32;
    const int STG = 32768;
    const int KC = K >> 6;

    float acc[4][4][4];
#pragma unroll
    for (int i = 0; i < 4; i++)
#pragma unroll
        for (int j = 0; j < 4; j++)
#pragma unroll
            for (int r = 0; r < 4; r++) acc[i][j][r] = 0.f;

    auto load_stage = [&](int kc, int s) {
        const __half* Ap = A + (size_t)m0 * K + kc * 64;
        const __half* Bp = Bw + (size_t)n0 * K + kc * 64;
        uint32_t sa = sbase + s * STG;
        uint32_t sb = sa + 16384;
#pragma unroll
        for (int p = 0; p < 4; p++) {
            int idx = tid + p * 256;
            int r = idx >> 3, c = idx & 7;
            uint32_t so = SWZ((uint32_t)(r * 128 + c * 16));
            cp_async16(sa + so, Ap + (size_t)r * K + c * 8);
            cp_async16(sb + so, Bp + (size_t)r * K + c * 8);
        }
    };

    load_stage(0, 0);
    asm volatile("cp.async.commit_group;");
    if (KC > 1) load_stage(1, 1);
    asm volatile("cp.async.commit_group;");

    const int frow = lane & 15;
    const int fchk = (lane >> 4) * 16;

    for (int i = 0; i < KC; i++) {
        asm volatile("cp.async.wait_group 1;" ::: "memory");
        __syncthreads();
        if (i + 2 < KC) load_stage(i + 2, (i + 2) % 3);
        asm volatile("cp.async.commit_group;");

        uint32_t sa = sbase + (i % 3) * STG;
        uint32_t sb = sa + 16384;
#pragma unroll
        for (int s = 0; s < 4; s++) {
            uint32_t Bf[2][4];
#pragma unroll
            for (int p = 0; p < 2; p++)
                ldsm_x4(Bf[p], sb + SWZ((uint32_t)((wn0 + p * 16 + frow) * 128 + s * 32 + fchk)));
#pragma unroll
            for (int mt = 0; mt < 4; mt++) {
                uint32_t Af[4];
                ldsm_x4(Af, sa + SWZ((uint32_t)((wm0 + mt * 16 + frow) * 128 + s * 32 + fchk)));
#pragma unroll
                for (int nt = 0; nt < 4; nt++)
                    mma_f16(acc[mt][nt], Af, Bf[nt >> 1][nt & 1], Bf[nt >> 1][(nt & 1) + 2]);
            }
        }
        __syncthreads();
    }
    asm volatile("cp.async.wait_group 0;" ::: "memory");

    const int rbase = m0 + wm0 + (lane >> 2);
    const int cbase = n0 + wn0 + (lane & 3) * 2;
    float* Cf = (float*)Cv;
    __half* Ch = (__half*)Cv;
#pragma unroll
    for (int mt = 0; mt < 4; mt++) {
#pragma unroll
        for (int nt = 0; nt < 4; nt++) {
            int col = cbase + nt * 8;
            float v0 = acc[mt][nt][0], v1 = acc[mt][nt][1];
            float v2 = acc[mt][nt][2], v3 = acc[mt][nt][3];
            if (EPI == 1) {
                float b0 = bias[col], b1 = bias[col + 1];
                v0 = gelu_f(v0 + b0); v1 = gelu_f(v1 + b1);
                v2 = gelu_f(v2 + b0); v3 = gelu_f(v3 + b1);
            }
            size_t r0 = (size_t)(rbase + mt * 16) * N + col;
            size_t r1 = (size_t)(rbase + mt * 16 + 8) * N + col;
            if (OUTH) {
                *(__half2*)&Ch[r0] = __floats2half2_rn(v0, v1);
                *(__half2*)&Ch[r1] = __floats2half2_rn(v2, v3);
            } else {
                float2 p0; p0.x = v0; p0.y = v1;
                float2 p1; p1.x = v2; p1.y = v3;
                *(float2*)&Cf[r0] = p0;
                *(float2*)&Cf[r1] = p1;
            }
        }
    }
}

// ============ fp16x3 split GEMM (near-fp32; for Q|K merged) ================
__global__ void __launch_bounds__(256, 2) hgemm3(
    const __half* __restrict__ As, const __half* __restrict__ Bs,
    float* __restrict__ C, int M, int N, int K)
{
    extern __shared__ char smem[];
    const uint32_t sbase = smem_u32(smem);
    const int tid = threadIdx.x, wid = tid >> 5, lane = tid & 31;
    const int m0 = blockIdx.y * 128, n0 = blockIdx.x * 128;
    const int wm0 = (wid & 1) * 64, wn0 = (wid >> 1) * 32;
    const int STG = 32768;
    const int KC = K >> 5;
    const int RS = K * 2;

    float acc[4][4][4];
#pragma unroll
    for (int i = 0; i < 4; i++)
#pragma unroll
        for (int j = 0; j < 4; j++)
#pragma unroll
            for (int r = 0; r < 4; r++) acc[i][j][r] = 0.f;

    auto load_stage = [&](int kc, int s) {
        const __half* Ap = As + (size_t)m0 * RS + kc * 64;
        const __half* Bp = Bs + (size_t)n0 * RS + kc * 64;
        uint32_t sa = sbase + s * STG;
        uint32_t sb = sa + 16384;
#pragma unroll
        for (int p = 0; p < 4; p++) {
            int idx = tid + p * 256;
            int r = idx >> 3, c = idx & 7;
            uint32_t so = SWZ((uint32_t)(r * 128 + c * 16));
            cp_async16(sa + so, Ap + (size_t)r * RS + c * 8);
            cp_async16(sb + so, Bp + (size_t)r * RS + c * 8);
        }
    };

    load_stage(0, 0);
    asm volatile("cp.async.commit_group;");
    if (KC > 1) load_stage(1, 1);
    asm volatile("cp.async.commit_group;");

    const int frow = lane & 15;
    const int fchk = (lane >> 4) * 16;

    for (int i = 0; i < KC; i++) {
        asm volatile("cp.async.wait_group 1;" ::: "memory");
        __syncthreads();
        if (i + 2 < KC) load_stage(i + 2, (i + 2) % 3);
        asm volatile("cp.async.commit_group;");

        uint32_t sa = sbase + (i % 3) * STG;
        uint32_t sb = sa + 16384;
#pragma unroll
        for (int s = 0; s < 2; s++) {
            uint32_t Bh[2][4], Bl[2][4];
#pragma unroll
            for (int p = 0; p < 2; p++) {
                uint32_t rowoff = (uint32_t)((wn0 + p * 16 + frow) * 128 + s * 32 + fchk);
                ldsm_x4(Bh[p], sb + SWZ(rowoff));
                ldsm_x4(Bl[p], sb + SWZ(rowoff + 64));
            }
#pragma unroll
            for (int mt = 0; mt < 4; mt++) {
                uint32_t Ah[4], Al[4];
                uint32_t rowoff = (uint32_t)((wm0 + mt * 16 + frow) * 128 + s * 32 + fchk);
                ldsm_x4(Ah, sa + SWZ(rowoff));
                ldsm_x4(Al, sa + SWZ(rowoff + 64));
#pragma unroll
                for (int nt = 0; nt < 4; nt++) {
                    uint32_t bh0 = Bh[nt >> 1][nt & 1], bh1 = Bh[nt >> 1][(nt & 1) + 2];
                    uint32_t bl0 = Bl[nt >> 1][nt & 1], bl1 = Bl[nt >> 1][(nt & 1) + 2];
                    mma_f16(acc[mt][nt], Al, bh0, bh1);
                    mma_f16(acc[mt][nt], Ah, bl0, bl1);
                    mma_f16(acc[mt][nt], Ah, bh0, bh1);
                }
            }
        }
        __syncthreads();
    }
    asm volatile("cp.async.wait_group 0;" ::: "memory");

    const int rbase = m0 + wm0 + (lane >> 2);
    const int cbase = n0 + wn0 + (lane & 3) * 2;
#pragma unroll
    for (int mt = 0; mt < 4; mt++) {
#pragma unroll
        for (int nt = 0; nt < 4; nt++) {
            int col = cbase + nt * 8;
            float2 p0; p0.x = acc[mt][nt][0]; p0.y = acc[mt][nt][1];
            float2 p1; p1.x = acc[mt][nt][2]; p1.y = acc[mt][nt][3];
            *(float2*)&C[(size_t)(rbase + mt * 16) * N + col] = p0;
            *(float2*)&C[(size_t)(rbase + mt * 16 + 8) * N + col] = p1;
        }
    }
}

// ---------------- prep: x -> split + plain fp16 ----------------------------
__global__ void prep_x(const float* __restrict__ x, __half* __restrict__ xs,
                       __half* __restrict__ xh) {
    size_t i = ((size_t)blockIdx.x * 256 + threadIdx.x) * 4;
    int m = (int)(i / DM), k = (int)(i % DM);
    float4 v = *(const float4*)&x[i];
    __half h0 = __float2half_rn(v.x), h1 = __float2half_rn(v.y);
    __half h2 = __float2half_rn(v.z), h3 = __float2half_rn(v.w);
    __half l0 = __float2half_rn(v.x - __half2float(h0));
    __half l1 = __float2half_rn(v.y - __half2float(h1));
    __half l2 = __float2half_rn(v.z - __half2float(h2));
    __half l3 = __float2half_rn(v.w - __half2float(h3));
    xh[i] = h0; xh[i + 1] = h1; xh[i + 2] = h2; xh[i + 3] = h3;
    size_t o = (size_t)m * (DM * 2) + (k >> 5) * 64 + (k & 31);
    xs[o] = h0; xs[o + 1] = h1; xs[o + 2] = h2; xs[o + 3] = h3;
    xs[o + 32] = l0; xs[o + 33] = l1; xs[o + 34] = l2; xs[o + 35] = l3;
}

// ---------------- mega weight prep -----------------------------------------
__global__ void prep_w(const float* __restrict__ Wq, const float* __restrict__ Wk,
                       const float* __restrict__ Wv, const float* __restrict__ Wo,
                       const float* __restrict__ w1, const float* __restrict__ w2,
                       __half* __restrict__ wqks, __half* __restrict__ wvh,
                       __half* __restrict__ woh, __half* __restrict__ w1h,
                       __half* __restrict__ w2h) {
    int blk = blockIdx.x;
    int tx = threadIdx.x, ty = threadIdx.y;
    if (blk < 1024) {
        int region = blk >> 8;
        int tile = blk & 255;
        int bx = (tile & 15) * 32, by = (tile >> 4) * 32;
        const float* W = region == 0 ? Wq : region == 1 ? Wk : region == 2 ? Wv : Wo;
        __shared__ float tbuf[32][33];
        for (int i = ty; i < 32; i += 8)
            tbuf[i][tx] = W[(size_t)(by + i) * DM + bx + tx];
        __syncthreads();
        if (region < 2) {
            int roff = region * 512;
            for (int i = ty; i < 32; i += 8) {
                int n = bx + i;
                float v = tbuf[tx][i];
                __half hh = __float2half_rn(v);
                __half lo = __float2half_rn(v - __half2float(hh));
                size_t off = (size_t)(roff + n) * (DM * 2) + (by >> 5) * 64 + tx;
                wqks[off] = hh; wqks[off + 32] = lo;
            }
        } else {
            __half* o = (region == 2) ? wvh : woh;
            for (int i = ty; i < 32; i += 8)
                o[(size_t)(bx + i) * DM + by + tx] = __float2half_rn(tbuf[tx][i]);
        }
    } else {
        int t = ty * 32 + tx;
        const float* src = (blk < 2048) ? w1 : w2;
        __half* dst = (blk < 2048) ? w1h : w2h;
        size_t i = ((size_t)((blk - 1024) & 1023)) * 1024 + t * 4;
        float4 v = *(const float4*)&src[i];
        *(__half2*)&dst[i] = __floats2half2_rn(v.x, v.y);
        *(__half2*)&dst[i + 2] = __floats2half2_rn(v.z, v.w);
    }
}

// ---------------- sampled QK measure (ILP-2, float2 loads) ------------------
__global__ void measure_kernel(const float* __restrict__ QK,
                               const int* __restrict__ sidx,
                               float* __restrict__ Mout) {
    int gw = blockIdx.x * 4 + (threadIdx.x >> 5);
    int lane = threadIdx.x & 31;
    int l = gw % Ll;
    int bh = gw / Ll;
    int b = bh >> 3, h = bh & 7;
    const float2* q2 = (const float2*)(QK + ((size_t)(b * Ll + l)) * 1024 + h * DK);
    float2 qa = q2[lane];
    const float* Kb = QK + (size_t)b * Ll * 1024 + 512 + h * DK;
    float mx = -1e30f, sum = 0.f;
#pragma unroll 4
    for (int s = 0; s < Uu; s += 2) {
        int2 jj = *(const int2*)&sidx[l * Uu + s];
        float2 ka = __ldg((const float2*)(Kb + (size_t)jj.x * 1024) + lane);
        float2 kb = __ldg((const float2*)(Kb + (size_t)jj.y * 1024) + lane);
        float p0 = qa.x * ka.x + qa.y * ka.y;
        float p1 = qa.x * kb.x + qa.y * kb.y;
#pragma unroll
        for (int o = 16; o; o >>= 1) {
            p0 += __shfl_xor_sync(0xffffffffu, p0, o);
            p1 += __shfl_xor_sync(0xffffffffu, p1, o);
        }
        mx = fmaxf(mx, fmaxf(p0, p1));
        sum += p0 + p1;
    }
    if (lane == 0) Mout[bh * Ll + l] = mx - sum / (float)Ll;
}

// ---------------- top-40 per (b,h) via radix select ------------------------
// Exact jax.lax.top_k set semantics: ties at the threshold take lowest indices.
__global__ void __launch_bounds__(256) topk_kernel(
    const float* __restrict__ Mv, int* __restrict__ top, int* __restrict__ map) {
    int bh = blockIdx.x;
    int t = threadIdx.x;
    __shared__ uint32_t keys[Ll];
    __shared__ int eqlist[Ll];
    __shared__ int hist[256];
    __shared__ uint32_t sh_prefix;
    __shared__ int sh_need, sh_eqc, sh_cnt, sh_eqn;

    for (int i = t; i < Ll; i += 256) {
        uint32_t u = __float_as_uint(Mv[bh * Ll + i]);
        u = (u & 0x80000000u) ? ~u : (u | 0x80000000u);   // order-preserving map
        keys[i] = u;
        map[bh * Ll + i] = -1;
    }
    if (t == 0) { sh_prefix = 0; sh_need = Uu; sh_cnt = 0; sh_eqn = 0; }
    __syncthreads();

    for (int pass = 0; pass < 4; pass++) {
        int shift = 24 - 8 * pass;
        hist[t] = 0;
        __syncthreads();
        uint32_t pfx = sh_prefix;
        for (int i = t; i < Ll; i += 256) {
            uint32_t u = keys[i];
            bool mt = (pass == 0) || ((u >> (shift + 8)) == pfx);
            if (mt) atomicAdd(&hist[(u >> shift) & 255], 1);
        }
        __syncthreads();
        if (t == 0) {
            int need = sh_need, c = 0, b = 255;
            for (; b > 0; b--) {
                int hb = hist[b];
                if (c + hb >= need) break;
                c += hb;
            }
            sh_need = need - c;               // >= 1 by construction
            sh_prefix = (pfx << 8) | (uint32_t)b;
            sh_eqc = hist[b];
        }
        __syncthreads();
    }
    uint32_t T = sh_prefix;
    int need_eq = sh_need;
    int eqc = sh_eqc;

    // strictly greater than threshold: always in-set
    for (int i = t; i < Ll; i += 256) {
        if (keys[i] > T) {
            int s = atomicAdd(&sh_cnt, 1);
            top[bh * Uu + s] = i;
            map[bh * Ll + i] = s;
        }
    }
    __syncthreads();
    if (eqc == need_eq) {
        // all ties taken — no index ordering needed
        for (int i = t; i < Ll; i += 256) {
            if (keys[i] == T) {
                int s = atomicAdd(&sh_cnt, 1);
                top[bh * Uu + s] = i;
                map[bh * Ll + i] = s;
            }
        }
    } else {
        // rare: choose need_eq smallest indices among ties
        for (int i = t; i < Ll; i += 256) {
            if (keys[i] == T) {
                int s = atomicAdd(&sh_eqn, 1);
                eqlist[s] = i;
            }
        }
        __syncthreads();
        if (t == 0) {
            int n = sh_eqn;
            for (int k = 0; k < need_eq; k++) {
                int mn = 0x7fffffff, mj = -1;
                for (int j = 0; j < n; j++)
                    if (eqlist[j] < mn) { mn = eqlist[j]; mj = j; }
                eqlist[mj] = 0x7fffffff;
                int s = sh_cnt++;
                top[bh * Uu + s] = mn;
                map[bh * Ll + mn] = s;
            }
        }
    }
}

// ---------------- V mean partials ------------------------------------------
__global__ void vmean_kernel(const float* __restrict__ V, float* __restrict__ vpart) {
    int bh = blockIdx.x, c8 = blockIdx.y;
    int b = bh >> 3, h = bh & 7;
    int t = threadIdx.x;
    int d = t & 63, sub = t >> 6;
    __shared__ float red[256];
    float s = 0.f;
    int l0 = c8 * 256 + sub * 64;
#pragma unroll 8
    for (int r = 0; r < 64; r++)
        s += V[((size_t)(b * Ll + l0 + r)) * DM + h * DK + d];
    red[t] = s;
    __syncthreads();
    if (t < 64)
        vpart[c8 * (BH * DK) + bh * DK + t] = red[t] + red[t + 64] + red[t + 128] + red[t + 192];
}

// ---------------- fused scores+softmax+upd (flash-style, split-softmax) ----
// Block (bh, lc): 256 L-rows. Outputs unnormalized upart plus per-chunk
// running max (mpart) and sum-of-exp (spart); reduce_kernel combines.
__global__ void __launch_bounds__(256) attn_kernel(
    const float* __restrict__ QK, const int* __restrict__ top,
    const float* __restrict__ V,
    float* __restrict__ upart, float* __restrict__ mpart,
    float* __restrict__ spart)
{
    int bh = blockIdx.x, lc = blockIdx.y;
    int b = bh >> 3, h = bh & 7;
    int t = threadIdx.x;
    extern __shared__ float sm[];
    float* Qs = sm;                       // [40][64]
    float* Ks = Qs + Uu * 64;             // [64][65]
    float* Vs = Ks + 64 * 65;             // [64][65]
    float* Ss = Vs + 64 * 65;             // [40][65]
    float* s_scale = Ss + Uu * 65;        // [40]
    float* s_mnew  = s_scale + Uu;        // [40]

    const float* Qbase = QK + (size_t)b * Ll * 1024 + h * DK;
    const float* Kbase = Qbase + 512;

    for (int idx = t; idx < Uu * 64; idx += 256) {
        int u = idx >> 6, d = idx & 63;
        Qs[idx] = Qbase[(size_t)top[bh * Uu + u] * 1024 + d];
    }

    float m_run = -1e30f, s_run = 0.f;    // meaningful for t < 40
    const int dd = t & 63, ug = t >> 6;
    float acc[10];
#pragma unroll
    for (int o = 0; o < 10; o++) acc[o] = 0.f;

    for (int lt = 0; lt < 4; lt++) {
        int l0 = lc * 256 + lt * 64;
        __syncthreads();                  // protect K/V tiles from prev iter reads
        for (int idx = t; idx < 64 * 64; idx += 256) {
            int i = idx >> 6, d = idx & 63;
            Ks[i * 65 + d] = Kbase[(size_t)(l0 + i) * 1024 + d];
            Vs[i * 65 + d] = V[((size_t)(b * Ll + l0 + i)) * DM + h * DK + d];
        }
        __syncthreads();
        // phase A: scores for this 64-row tile
        {
            int ig = t & 63;
            float sa[10];
#pragma unroll
            for (int o = 0; o < 10; o++) sa[o] = 0.f;
#pragma unroll 4
            for (int d = 0; d < 64; d++) {
                float kv = Ks[ig * 65 + d];
#pragma unroll
                for (int o = 0; o < 10; o++)
                    sa[o] += Qs[(ug + 4 * o) * 64 + d] * kv;
            }
#pragma unroll
            for (int o = 0; o < 10; o++)
                Ss[(ug + 4 * o) * 65 + ig] = sa[o] * 0.125f;
        }
        __syncthreads();
        // phase B: per-u tile max, rescale factor
        if (t < Uu) {
            float mloc = -1e30f;
            for (int i = 0; i < 64; i++) mloc = fmaxf(mloc, Ss[t * 65 + i]);
            float mn = fmaxf(m_run, mloc);
            s_scale[t] = expf(m_run - mn);
            s_mnew[t] = mn;
            m_run = mn;
        }
        __syncthreads();
        // phase B2: exponentiate in place
        for (int idx = t; idx < Uu * 64; idx += 256) {
            int u = idx >> 6, i = idx & 63;
            Ss[u * 65 + i] = expf(Ss[u * 65 + i] - s_mnew[u]);
        }
        __syncthreads();
        // phase B3 (t<40, concurrent with C): running sum-of-exp
        if (t < Uu) {
            float ssum = 0.f;
            for (int i = 0; i < 64; i++) ssum += Ss[t * 65 + i];
            s_run = s_run * s_scale[t] + ssum;
        }
        // phase C: accumulate exp(s)*V with rescale
#pragma unroll
        for (int o = 0; o < 10; o++) {
            int u = ug + 4 * o;
            float a = acc[o] * s_scale[u];
#pragma unroll 8
            for (int i = 0; i < 64; i++)
                a += Ss[u * 65 + i] * Vs[i * 65 + dd];
            acc[o] = a;
        }
    }
#pragma unroll
    for (int o = 0; o < 10; o++) {
        int u = ug + 4 * o;
        upart[(size_t)lc * UPDN + ((size_t)bh * Uu + u) * DK + dd] = acc[o];
    }
    if (t < Uu) {
        mpart[lc * BH * Uu + bh * Uu + t] = m_run;
        spart[lc * BH * Uu + bh * Uu + t] = s_run;
    }
}

// ---------------- reduce: LSE-combine upd partials + vmean -----------------
__global__ void reduce_kernel(const float* __restrict__ upart,
                              const float* __restrict__ mpart,
                              const float* __restrict__ spart,
                              const float* __restrict__ vpart,
                              float* __restrict__ upd, float* __restrict__ vm) {
    int i = blockIdx.x * 256 + threadIdx.x;
    if (i < UPDN) {
        int row = i >> 6;
        float M = -1e30f;
#pragma unroll
        for (int c = 0; c < 8; c++) M = fmaxf(M, mpart[c * BH * Uu + row]);
        float Z = 0.f, s = 0.f;
#pragma unroll
        for (int c = 0; c < 8; c++) {
            float w = expf(mpart[c * BH * Uu + row] - M);
            Z += spart[c * BH * Uu + row] * w;
            s += upart[(size_t)c * UPDN + i] * w;
        }
        upd[i] = s / Z;
    } else if (i < UPDN + BH * DK) {
        int j = i - UPDN;
        float sv = 0.f;
#pragma unroll
        for (int c = 0; c < 8; c++) sv += vpart[c * (BH * DK) + j];
        vm[j] = sv * (1.f / (float)Ll);
    }
}

// ---------------- ctx build: mean fill + top-row scatter, fp16 -------------
__global__ void ctxbuild_kernel(const int* __restrict__ map,
                                const float* __restrict__ vm,
                                const float* __restrict__ upd,
                                __half* __restrict__ ctx) {
    size_t i4 = ((size_t)blockIdx.x * 256 + threadIdx.x) * 4;
    int col = (int)(i4 % DM);
    size_t row = i4 / DM;
    int b = (int)(row >> 11);
    int l = (int)(row & 2047);
    int h = col >> 6, d = col & 63;
    int bh = b * Hh + h;
    int u = map[bh * Ll + l];
    const float* src = (u >= 0) ? upd + ((size_t)bh * Uu + u) * DK + d
                                : vm + bh * DK + d;
    float4 v = *(const float4*)src;
    *(__half2*)&ctx[i4]     = __floats2half2_rn(v.x, v.y);
    *(__half2*)&ctx[i4 + 2] = __floats2half2_rn(v.z, v.w);
}

// ---------------- residual (+bias) + LayerNorm (optional fp16 copy) --------
__global__ void addln_kernel(const float* __restrict__ A,
                             const float* __restrict__ R,
                             const float* __restrict__ bias,
                             const float* __restrict__ gamma,
                             const float* __restrict__ beta,
                             float* __restrict__ out,
                             __half* __restrict__ outh) {
    int row = blockIdx.x;
    int t = threadIdx.x;
    __shared__ float red[256];
    size_t base = (size_t)row * DM;
    float v0 = A[base + t] + R[base + t];
    float v1 = A[base + t + 256] + R[base + t + 256];
    if (bias) { v0 += bias[t]; v1 += bias[t + 256]; }
    red[t] = v0 + v1; __syncthreads();
    for (int s = 128; s; s >>= 1) { if (t < s) red[t] += red[t + s]; __syncthreads(); }
    float mean = red[0] / (float)DM; __syncthreads();
    float d0 = v0 - mean, d1 = v1 - mean;
    red[t] = d0 * d0 + d1 * d1; __syncthreads();
    for (int s = 128; s; s >>= 1) { if (t < s) red[t] += red[t + s]; __syncthreads(); }
    float inv = rsqrtf(red[0] / (float)DM + 1e-5f);
    float o0 = d0 * inv * gamma[t] + beta[t];
    float o1 = d1 * inv * gamma[t + 256] + beta[t + 256];
    out[base + t] = o0;
    out[base + t + 256] = o1;
    if (outh) {
        outh[base + t] = __float2half_rn(o0);
        outh[base + t + 256] = __float2half_rn(o1);
    }
}

// ---------------- host orchestration ---------------------------------------
extern "C" void kernel_launch(void* const* d_in, const int* in_sizes, int n_in,
                              void* d_out, int out_size) {
    const float* x    = (const float*)d_in[0];
    const float* Wq   = (const float*)d_in[1];
    const float* Wk   = (const float*)d_in[2];
    const float* Wv   = (const float*)d_in[3];
    const float* Wo   = (const float*)d_in[4];
    const float* ln1g = (const float*)d_in[5];
    const float* ln1b = (const float*)d_in[6];
    const float* w1   = (const float*)d_in[7];
    const float* b1   = (const float*)d_in[8];
    const float* w2   = (const float*)d_in[9];
    const float* b2   = (const float*)d_in[10];
    const float* ln2g = (const float*)d_in[11];
    const float* ln2b = (const float*)d_in[12];
    const int*   sidx = (const int*)d_in[13];
    float* out = (float*)d_out;

    float *pQK, *pV, *pM, *pUpd, *pUpart, *pMpart, *pSpart, *pVm, *pVpart, *pAo, *pX1, *pY2;
    __half *pXs, *pXh, *pX1h, *pCtxh, *pFFh, *pWqks, *pWvh, *pWoh, *pW1h, *pW2h;
    int *pTop, *pMap;
    cudaGetSymbolAddress((void**)&pQK, g_QK);
    cudaGetSymbolAddress((void**)&pV, g_V);
    cudaGetSymbolAddress((void**)&pM, g_M);
    cudaGetSymbolAddress((void**)&pTop, g_top);
    cudaGetSymbolAddress((void**)&pMap, g_map);
    cudaGetSymbolAddress((void**)&pUpd, g_upd);
    cudaGetSymbolAddress((void**)&pUpart, g_upart);
    cudaGetSymbolAddress((void**)&pMpart, g_mpart);
    cudaGetSymbolAddress((void**)&pSpart, g_spart);
    cudaGetSymbolAddress((void**)&pVm, g_vm);
    cudaGetSymbolAddress((void**)&pVpart, g_vpart);
    cudaGetSymbolAddress((void**)&pAo, g_ao);
    cudaGetSymbolAddress((void**)&pX1, g_x1);
    cudaGetSymbolAddress((void**)&pY2, g_y2);
    cudaGetSymbolAddress((void**)&pXs, g_xs);
    cudaGetSymbolAddress((void**)&pXh, g_xh);
    cudaGetSymbolAddress((void**)&pX1h, g_x1h);
    cudaGetSymbolAddress((void**)&pCtxh, g_ctxh);
    cudaGetSymbolAddress((void**)&pFFh, g_ffh);
    cudaGetSymbolAddress((void**)&pWqks, g_wqks);
    cudaGetSymbolAddress((void**)&pWvh, g_wvh);
    cudaGetSymbolAddress((void**)&pWoh, g_woh);
    cudaGetSymbolAddress((void**)&pW1h, g_w1h);
    cudaGetSymbolAddress((void**)&pW2h, g_w2h);

    const int smemT = 3 * 32768;                              // 98304
    const int smemA = (Uu * 64 + 64 * 65 * 2 + Uu * 65 + 2 * Uu) * 4;  // 54240
    cudaFuncSetAttribute(hgemm<0,0>, cudaFuncAttributeMaxDynamicSharedMemorySize, smemT);
    cudaFuncSetAttribute(hgemm<1,1>, cudaFuncAttributeMaxDynamicSharedMemorySize, smemT);
    cudaFuncSetAttribute(hgemm3,     cudaFuncAttributeMaxDynamicSharedMemorySize, smemT);
    cudaFuncSetAttribute(attn_kernel, cudaFuncAttributeMaxDynamicSharedMemorySize, smemA);

    // prep
    prep_x<<<ROWS * DM / 4 / 256, 256>>>(x, pXs, pXh);
    prep_w<<<3072, dim3(32, 8)>>>(Wq, Wk, Wv, Wo, w1, w2, pWqks, pWvh, pWoh, pW1h, pW2h);

    // merged Q|K (fp16x3, near-fp32) and V (1-pass fp16)
    hgemm3<<<dim3(8, ROWS / 128), 256, smemT>>>(pXs, pWqks, pQK, ROWS, 1024, DM);
    hgemm<0,0><<<dim3(4, ROWS / 128), 256, smemT>>>(pXh, pWvh, nullptr, pV, ROWS, DM, DM);

    // sparse measure + top-k (radix select) + membership map
    measure_kernel<<<BH * Ll / 4, 128>>>(pQK, sidx, pM);
    topk_kernel<<<BH, 256>>>(pM, pTop, pMap);

    // V mean partials
    vmean_kernel<<<dim3(BH, 8), 256>>>(pV, pVpart);

    // fused scores+softmax+upd (split-softmax over 8 L-chunks)
    attn_kernel<<<dim3(BH, 8), 256, smemA>>>(pQK, pTop, pV, pUpart, pMpart, pSpart);
    reduce_kernel<<<(UPDN + BH * DK + 255) / 256, 256>>>(pUpart, pMpart, pSpart, pVpart, pUpd, pVm);

    // context (fp16) + output projection
    ctxbuild_kernel<<<ROWS * DM / 4 / 256, 256>>>(pMap, pVm, pUpd, pCtxh);
    hgemm<0,0><<<dim3(4, ROWS / 128), 256, smemT>>>(pCtxh, pWoh, nullptr, pAo, ROWS, DM, DM);

    // residual + LN1
    addln_kernel<<<ROWS, 256>>>(x, pAo, nullptr, ln1g, ln1b, pX1, pX1h);

    // FFN
    hgemm<1,1><<<dim3(16, ROWS / 128), 256, smemT>>>(pX1h, pW1h, b1, pFFh, ROWS, DFF, DM);
    hgemm<0,0><<<dim3(4, ROWS / 128), 256, smemT>>>(pFFh, pW2h, nullptr, pY2, ROWS, DM, DFF);

    // residual + bias + LN2 -> output
    addln_kernel<<<ROWS, 256>>>(pX1, pY2, b2, ln2g, ln2b, out, nullptr);
}